// round 1
// baseline (speedup 1.0000x reference)
#include <cuda_runtime.h>
#include <math.h>
#include <stdint.h>

// Problem constants
#define L_ 12
#define H_ 12
#define C_ 768
#define V_ 50257
#define B_ 2
#define T_ 1024
#define D_ 64
#define M_ (B_*T_)   // 2048 rows

// ---------------------------------------------------------------------------
// Scratch (static device globals; no runtime allocation allowed)
// ---------------------------------------------------------------------------
__device__ float g_bias[T_*T_];            // FIRE bias (T,T)           4 MB
__device__ float g_x   [M_*C_];            // residual stream           6 MB
__device__ float g_h   [M_*C_];            // layernorm output          6 MB
__device__ float g_qkv [M_*3*C_];          // qkv projections          19 MB
__device__ float g_att [B_*H_*T_*T_];      // attention scores         96 MB
__device__ float g_y   [M_*C_];            // attention output          6 MB
__device__ float g_mlp [M_*4*C_];          // MLP hidden               25 MB

// ---------------------------------------------------------------------------
// Block reductions
// ---------------------------------------------------------------------------
__device__ __forceinline__ float block_reduce_sum(float v) {
    __shared__ float sh[32];
    __syncthreads();
    int lane = threadIdx.x & 31, wid = threadIdx.x >> 5;
    #pragma unroll
    for (int o = 16; o > 0; o >>= 1) v += __shfl_down_sync(0xffffffffu, v, o);
    if (lane == 0) sh[wid] = v;
    __syncthreads();
    v = (threadIdx.x < (blockDim.x >> 5)) ? sh[lane] : 0.f;
    if (wid == 0) {
        #pragma unroll
        for (int o = 16; o > 0; o >>= 1) v += __shfl_down_sync(0xffffffffu, v, o);
        if (lane == 0) sh[0] = v;
    }
    __syncthreads();
    return sh[0];
}

__device__ __forceinline__ float block_reduce_max(float v) {
    __shared__ float sh[32];
    __syncthreads();
    int lane = threadIdx.x & 31, wid = threadIdx.x >> 5;
    #pragma unroll
    for (int o = 16; o > 0; o >>= 1) v = fmaxf(v, __shfl_down_sync(0xffffffffu, v, o));
    if (lane == 0) sh[wid] = v;
    __syncthreads();
    v = (threadIdx.x < (blockDim.x >> 5)) ? sh[lane] : -INFINITY;
    if (wid == 0) {
        #pragma unroll
        for (int o = 16; o > 0; o >>= 1) v = fmaxf(v, __shfl_down_sync(0xffffffffu, v, o));
        if (lane == 0) sh[0] = v;
    }
    __syncthreads();
    return sh[0];
}

// ---------------------------------------------------------------------------
// FIRE bias: bias[i,j] = MLP(psi(i-j)/psi(i)), -1e30 above diagonal
// ---------------------------------------------------------------------------
__global__ void fire_bias_kernel(const float* __restrict__ log_c,
                                 const float* __restrict__ v1w, const float* __restrict__ v1b,
                                 const float* __restrict__ v2w, const float* __restrict__ v2b,
                                 const float* __restrict__ v3w, const float* __restrict__ v3b,
                                 float* __restrict__ bias) {
    __shared__ float s1w[32], s1b[32], s2w[1024], s2b[32], s3w[32];
    __shared__ float s3b, sc;
    int tid = threadIdx.x;
    if (tid < 32) { s1w[tid] = v1w[tid]; s1b[tid] = v1b[tid]; s2b[tid] = v2b[tid]; s3w[tid] = v3w[tid]; }
    for (int i = tid; i < 1024; i += blockDim.x) s2w[i] = v2w[i];
    if (tid == 0) { s3b = v3b[0]; sc = expf(log_c[0]); }
    __syncthreads();

    int idx = blockIdx.x * blockDim.x + tid;
    if (idx >= T_*T_) return;
    int i = idx / T_, j = idx % T_;
    if (j > i) { bias[idx] = -1e30f; return; }

    float c = sc;
    float fi = (float)(i + 1), fj = (float)(j + 1);
    float pv = logf(c * (fi - fj) + 1.0f) / logf(c * fi + 1.0f);

    float h1[32];
    #pragma unroll
    for (int k = 0; k < 32; k++) h1[k] = fmaxf(pv * s1w[k] + s1b[k], 0.f);
    float out = s3b;
    #pragma unroll
    for (int k2 = 0; k2 < 32; k2++) {
        float a = s2b[k2];
        #pragma unroll
        for (int k1 = 0; k1 < 32; k1++) a += h1[k1] * s2w[k1*32 + k2];
        out += fmaxf(a, 0.f) * s3w[k2];
    }
    bias[idx] = out;
}

// ---------------------------------------------------------------------------
// Embedding gather
// ---------------------------------------------------------------------------
__global__ void embed_kernel(const int* __restrict__ idx, const float* __restrict__ wte,
                             float* __restrict__ x) {
    int row = blockIdx.x;                       // 0..M_-1
    const float* src = wte + (size_t)idx[row] * C_;
    float* dst = x + (size_t)row * C_;
    for (int c = threadIdx.x; c < C_; c += blockDim.x) dst[c] = src[c];
}

// ---------------------------------------------------------------------------
// LayerNorm: one block per row (C_=768, 256 threads, 3 elems/thread)
// ---------------------------------------------------------------------------
__global__ void ln_kernel(const float* __restrict__ x, const float* __restrict__ g,
                          const float* __restrict__ b, float* __restrict__ out) {
    int row = blockIdx.x;
    const float* xr = x + (size_t)row * C_;
    float v0 = xr[threadIdx.x], v1 = xr[threadIdx.x + 256], v2 = xr[threadIdx.x + 512];
    float s = block_reduce_sum(v0 + v1 + v2);
    float mean = s * (1.0f / C_);
    float d0 = v0 - mean, d1 = v1 - mean, d2 = v2 - mean;
    float s2 = block_reduce_sum(d0*d0 + d1*d1 + d2*d2);
    float rs = rsqrtf(s2 * (1.0f / C_) + 1e-5f);
    float* o = out + (size_t)row * C_;
    int c = threadIdx.x;
    o[c      ] = d0 * rs * g[c      ] + b[c      ];
    o[c + 256] = d1 * rs * g[c + 256] + b[c + 256];
    o[c + 512] = d2 * rs * g[c + 512] + b[c + 512];
}

// ---------------------------------------------------------------------------
// Generic tiled SGEMM: C[M,N] = act(A[M,K] @ B + bias) + residual
//   TRANSB=false: B is K x N row-major.   TRANSB=true: B is N x K row-major.
//   ACT: 0 = none, 1 = tanh-GELU
// 64x64 tile, BK=16, 256 threads, 4x4 per-thread micro-tile.
// ---------------------------------------------------------------------------
template<bool TRANSB, int ACT>
__global__ void gemm_kernel(const float* __restrict__ A, const float* __restrict__ B,
                            const float* __restrict__ bias, const float* __restrict__ residual,
                            float* C, int Mm, int Nn, int Kk) {
    const int BM = 64, BN = 64, BK = 16;
    __shared__ float As[BK][BM + 1];
    __shared__ float Bs[BK][BN + 1];
    int bm = blockIdx.y * BM, bn = blockIdx.x * BN;
    int tid = threadIdx.x;
    int tm = (tid / 16) * 4, tn = (tid % 16) * 4;
    float acc[4][4] = {};

    for (int k0 = 0; k0 < Kk; k0 += BK) {
        for (int i = tid; i < BM * BK; i += 256) {
            int m = i / BK, k = i % BK;
            int gm = bm + m, gk = k0 + k;
            As[k][m] = (gm < Mm && gk < Kk) ? A[(size_t)gm * Kk + gk] : 0.f;
        }
        for (int i = tid; i < BK * BN; i += 256) {
            int k = i / BN, n = i % BN;
            int gk = k0 + k, gn = bn + n;
            float v = 0.f;
            if (gk < Kk && gn < Nn)
                v = TRANSB ? B[(size_t)gn * Kk + gk] : B[(size_t)gk * Nn + gn];
            Bs[k][n] = v;
        }
        __syncthreads();
        #pragma unroll
        for (int k = 0; k < BK; k++) {
            float a[4], bb[4];
            #pragma unroll
            for (int i = 0; i < 4; i++) a[i] = As[k][tm + i];
            #pragma unroll
            for (int j = 0; j < 4; j++) bb[j] = Bs[k][tn + j];
            #pragma unroll
            for (int i = 0; i < 4; i++)
                #pragma unroll
                for (int j = 0; j < 4; j++)
                    acc[i][j] += a[i] * bb[j];
        }
        __syncthreads();
    }

    #pragma unroll
    for (int i = 0; i < 4; i++) {
        int gm = bm + tm + i;
        if (gm >= Mm) continue;
        #pragma unroll
        for (int j = 0; j < 4; j++) {
            int gn = bn + tn + j;
            if (gn >= Nn) continue;
            float v = acc[i][j];
            if (bias) v += bias[gn];
            if (ACT == 1) {
                float x3 = v * v * v;
                v = 0.5f * v * (1.f + tanhf(0.7978845608028654f * (v + 0.044715f * x3)));
            }
            if (residual) v += residual[(size_t)gm * Nn + gn];
            C[(size_t)gm * Nn + gn] = v;
        }
    }
}

// ---------------------------------------------------------------------------
// Attention scores: att[b,h,i,j] = 0.125 * q.k + bias[i,j]
// grid (T/32, T/32, B*H), 256 threads, 32x32 tile, K=64 fully in smem.
// Fully-masked tiles (j0 > i0+31) are shortcut to -1e30.
// ---------------------------------------------------------------------------
__global__ void attn_score_kernel(const float* __restrict__ qkv,
                                  const float* __restrict__ bias,
                                  float* __restrict__ att) {
    int bh = blockIdx.z, b = bh / H_, h = bh % H_;
    int i0 = blockIdx.y * 32, j0 = blockIdx.x * 32;
    float* ab = att + (size_t)bh * T_ * T_;
    int tid = threadIdx.x;

    if (j0 > i0 + 31) {   // strictly above the diagonal: bias dominates (-1e30)
        for (int idx = tid; idx < 32 * 32; idx += 256) {
            int r = idx / 32, c = idx % 32;
            ab[(size_t)(i0 + r) * T_ + j0 + c] = -1e30f;
        }
        return;
    }

    __shared__ float Qs[32][65], Ks[32][65];
    const float* qb = qkv + (size_t)b * T_ * 3 * C_ + h * D_;
    const float* kb = qb + C_;
    for (int idx = tid; idx < 32 * 64; idx += 256) {
        int r = idx / 64, c = idx % 64;
        Qs[r][c] = qb[(size_t)(i0 + r) * 3 * C_ + c];
        Ks[r][c] = kb[(size_t)(j0 + r) * 3 * C_ + c];
    }
    __syncthreads();

    int r = (tid / 16) * 2, c2 = (tid % 16) * 2;
    float acc00 = 0, acc01 = 0, acc10 = 0, acc11 = 0;
    #pragma unroll
    for (int k = 0; k < 64; k++) {
        float a0 = Qs[r][k],  a1 = Qs[r + 1][k];
        float b0 = Ks[c2][k], b1 = Ks[c2 + 1][k];
        acc00 += a0 * b0; acc01 += a0 * b1;
        acc10 += a1 * b0; acc11 += a1 * b1;
    }
    const float scale = 0.125f;  // 1/sqrt(64)
    int gi0 = i0 + r, gj0 = j0 + c2;
    ab[(size_t)gi0 * T_ + gj0    ] = scale * acc00 + bias[gi0 * T_ + gj0    ];
    ab[(size_t)gi0 * T_ + gj0 + 1] = scale * acc01 + bias[gi0 * T_ + gj0 + 1];
    ab[(size_t)(gi0+1)*T_ + gj0    ] = scale * acc10 + bias[(gi0+1)*T_ + gj0    ];
    ab[(size_t)(gi0+1)*T_ + gj0 + 1] = scale * acc11 + bias[(gi0+1)*T_ + gj0 + 1];
}

// ---------------------------------------------------------------------------
// Row softmax over T_ entries; grid = B*H*T rows, 256 threads.
// ---------------------------------------------------------------------------
__global__ void softmax_kernel(float* att) {
    float* a = att + (size_t)blockIdx.x * T_;
    float m = -INFINITY;
    for (int j = threadIdx.x; j < T_; j += 256) m = fmaxf(m, a[j]);
    m = block_reduce_max(m);
    float s = 0.f;
    float e[4];
    #pragma unroll
    for (int u = 0; u < 4; u++) {
        int j = threadIdx.x + u * 256;
        e[u] = expf(a[j] - m);
        s += e[u];
    }
    s = block_reduce_sum(s);
    float inv = 1.0f / s;
    #pragma unroll
    for (int u = 0; u < 4; u++) a[threadIdx.x + u * 256] = e[u] * inv;
}

// ---------------------------------------------------------------------------
// AV: y[b,i,h*64+d] = sum_j att[b,h,i,j] * v[b,j,h,d]; causal-capped K loop.
// grid (T/32, B*H), 256 threads. Each thread: 1 row x 8 cols.
// ---------------------------------------------------------------------------
__global__ void attn_av_kernel(const float* __restrict__ qkv,
                               const float* __restrict__ att,
                               float* __restrict__ y) {
    int bh = blockIdx.y, b = bh / H_, h = bh % H_;
    int i0 = blockIdx.x * 32;
    const float* vb = qkv + (size_t)b * T_ * 3 * C_ + 2 * C_ + h * D_;
    const float* ab = att + (size_t)bh * T_ * T_;
    __shared__ float As[32][33], Vs[32][65];
    int tid = threadIdx.x;
    int r = tid / 8, d0 = (tid % 8) * 8;
    float acc[8] = {};
    int jmax = i0 + 32;   // att is exactly 0 for j > i after softmax
    for (int j0 = 0; j0 < jmax; j0 += 32) {
        for (int idx = tid; idx < 32 * 32; idx += 256) {
            int rr = idx / 32, cc = idx % 32;
            As[rr][cc] = ab[(size_t)(i0 + rr) * T_ + j0 + cc];
        }
        for (int idx = tid; idx < 32 * 64; idx += 256) {
            int rr = idx / 64, cc = idx % 64;
            Vs[rr][cc] = vb[(size_t)(j0 + rr) * 3 * C_ + cc];
        }
        __syncthreads();
        #pragma unroll
        for (int k = 0; k < 32; k++) {
            float a = As[r][k];
            #pragma unroll
            for (int d = 0; d < 8; d++) acc[d] += a * Vs[k][d0 + d];
        }
        __syncthreads();
    }
    float* yb = y + (size_t)b * T_ * C_ + (size_t)(i0 + r) * C_ + h * D_ + d0;
    #pragma unroll
    for (int d = 0; d < 8; d++) yb[d] = acc[d];
}

// ---------------------------------------------------------------------------
// Launch
// ---------------------------------------------------------------------------
extern "C" void kernel_launch(void* const* d_in, const int* in_sizes, int n_in,
                              void* d_out, int out_size) {
    // Input order (metadata): idx, [n_head], wte, log_c, v1_w, v1_b, v2_w, v2_b,
    // v3_w, v3_b, ln1_g, ln1_b, attn_w, attn_b, proj_w, proj_b, ln2_g, ln2_b,
    // fc_w, fc_b, fc2_w, fc2_b, lnf_g, lnf_b.
    // Detect whether the scalar n_head is materialized as an input.
    int o = (n_in >= 2 && in_sizes[1] == 1) ? 1 : 0;

    const int*   idx   = (const int*)  d_in[0];
    const float* wte   = (const float*)d_in[1 + o];
    const float* log_c = (const float*)d_in[2 + o];
    const float* v1w   = (const float*)d_in[3 + o];
    const float* v1b   = (const float*)d_in[4 + o];
    const float* v2w   = (const float*)d_in[5 + o];
    const float* v2b   = (const float*)d_in[6 + o];
    const float* v3w   = (const float*)d_in[7 + o];
    const float* v3b   = (const float*)d_in[8 + o];
    const float* ln1g  = (const float*)d_in[9 + o];
    const float* ln1b  = (const float*)d_in[10 + o];
    const float* attnw = (const float*)d_in[11 + o];
    const float* attnb = (const float*)d_in[12 + o];
    const float* projw = (const float*)d_in[13 + o];
    const float* projb = (const float*)d_in[14 + o];
    const float* ln2g  = (const float*)d_in[15 + o];
    const float* ln2b  = (const float*)d_in[16 + o];
    const float* fcw   = (const float*)d_in[17 + o];
    const float* fcb   = (const float*)d_in[18 + o];
    const float* fc2w  = (const float*)d_in[19 + o];
    const float* fc2b  = (const float*)d_in[20 + o];
    const float* lnfg  = (const float*)d_in[21 + o];
    const float* lnfb  = (const float*)d_in[22 + o];

    float *bias, *x, *h, *qkv, *att, *y, *mlp;
    cudaGetSymbolAddress((void**)&bias, g_bias);
    cudaGetSymbolAddress((void**)&x,    g_x);
    cudaGetSymbolAddress((void**)&h,    g_h);
    cudaGetSymbolAddress((void**)&qkv,  g_qkv);
    cudaGetSymbolAddress((void**)&att,  g_att);
    cudaGetSymbolAddress((void**)&y,    g_y);
    cudaGetSymbolAddress((void**)&mlp,  g_mlp);

    // 1. FIRE bias (T,T)
    fire_bias_kernel<<<(T_*T_ + 255) / 256, 256>>>(log_c, v1w, v1b, v2w, v2b, v3w, v3b, bias);

    // 2. Embedding
    embed_kernel<<<M_, 256>>>(idx, wte, x);

    // 3. Transformer layers
    const dim3 g_qkvd((3*C_ + 63) / 64, M_ / 64);
    const dim3 g_cc  ((C_   + 63) / 64, M_ / 64);
    const dim3 g_fc  ((4*C_ + 63) / 64, M_ / 64);
    const dim3 g_sc  (T_ / 32, T_ / 32, B_ * H_);
    const dim3 g_av  (T_ / 32, B_ * H_);

    for (int l = 0; l < L_; l++) {
        ln_kernel<<<M_, 256>>>(x, ln1g + (size_t)l*C_, ln1b + (size_t)l*C_, h);
        gemm_kernel<false,0><<<g_qkvd, 256>>>(h, attnw + (size_t)l*C_*3*C_,
                                              attnb + (size_t)l*3*C_, nullptr,
                                              qkv, M_, 3*C_, C_);
        attn_score_kernel<<<g_sc, 256>>>(qkv, bias, att);
        softmax_kernel<<<B_*H_*T_, 256>>>(att);
        attn_av_kernel<<<g_av, 256>>>(qkv, att, y);
        gemm_kernel<false,0><<<g_cc, 256>>>(y, projw + (size_t)l*C_*C_,
                                            projb + (size_t)l*C_, x,
                                            x, M_, C_, C_);
        ln_kernel<<<M_, 256>>>(x, ln2g + (size_t)l*C_, ln2b + (size_t)l*C_, h);
        gemm_kernel<false,1><<<g_fc, 256>>>(h, fcw + (size_t)l*C_*4*C_,
                                            fcb + (size_t)l*4*C_, nullptr,
                                            mlp, M_, 4*C_, C_);
        gemm_kernel<false,0><<<g_cc, 256>>>(mlp, fc2w + (size_t)l*4*C_*C_,
                                            fc2b + (size_t)l*C_, x,
                                            x, M_, C_, 4*C_);
    }

    // 4. Final LN + tied LM head (B^T = wte, N x K row-major)
    ln_kernel<<<M_, 256>>>(x, lnfg, lnfb, h);
    const dim3 g_lm((V_ + 63) / 64, M_ / 64);
    gemm_kernel<true,0><<<g_lm, 256>>>(h, wte, nullptr, nullptr,
                                       (float*)d_out, M_, V_, C_);
}

// round 4
// speedup vs baseline: 1.6487x; 1.6487x over previous
#include <cuda_runtime.h>
#include <math.h>
#include <stdint.h>

// Problem constants
#define L_ 12
#define H_ 12
#define C_ 768
#define V_ 50257
#define B_ 2
#define T_ 1024
#define D_ 64
#define M_ (B_*T_)   // 2048 rows

// ---------------------------------------------------------------------------
// Scratch (static device globals; no runtime allocation allowed)
// ---------------------------------------------------------------------------
__device__ float g_bias[T_*T_];
__device__ float g_x   [M_*C_];
__device__ float g_h   [M_*C_];
__device__ float g_qkv [M_*3*C_];
__device__ float g_att [B_*H_*T_*T_];
__device__ float g_y   [M_*C_];
__device__ float g_mlp [M_*4*C_];

// ---------------------------------------------------------------------------
// Helpers
// ---------------------------------------------------------------------------
__device__ __forceinline__ uint32_t smem_u32(const void* p){
    uint32_t a;
    asm("{ .reg .u64 t; cvta.to.shared.u64 t, %1; cvt.u32.u64 %0, t; }":"=r"(a):"l"(p));
    return a;
}
__device__ __forceinline__ float tf32_hi(float x){
    uint32_t r; asm("cvt.rna.tf32.f32 %0, %1;":"=r"(r):"f"(x));
    return __uint_as_float(r);
}
__device__ __forceinline__ void sts128(uint32_t a, float x, float y, float z, float w){
    asm volatile("st.shared.v4.b32 [%0], {%1,%2,%3,%4};"::"r"(a),"f"(x),"f"(y),"f"(z),"f"(w));
}
__device__ __forceinline__ void sts32(uint32_t a, float x){
    asm volatile("st.shared.b32 [%0], %1;"::"r"(a),"f"(x));
}
__device__ __forceinline__ void ldsm4(uint32_t* r, uint32_t addr){
    asm volatile("ldmatrix.sync.aligned.m8n8.x4.shared.b16 {%0,%1,%2,%3}, [%4];"
      : "=r"(r[0]),"=r"(r[1]),"=r"(r[2]),"=r"(r[3]) : "r"(addr));
}
__device__ __forceinline__ void mma8(float* d, const uint32_t* a, uint32_t b0, uint32_t b1){
    asm volatile("mma.sync.aligned.m16n8k8.row.col.f32.tf32.tf32.f32 "
      "{%0,%1,%2,%3}, {%4,%5,%6,%7}, {%8,%9}, {%0,%1,%2,%3};"
      : "+f"(d[0]),"+f"(d[1]),"+f"(d[2]),"+f"(d[3])
      : "r"(a[0]),"r"(a[1]),"r"(a[2]),"r"(a[3]),"r"(b0),"r"(b1));
}
#define SWZ(o) ((o) ^ (((o)>>3)&0x70))

// ---------------------------------------------------------------------------
// mma.sync TF32 GEMM (3xTF32 split for ~fp32 accuracy)
//   C[M,N] = act(A[M,K] @ B + bias) + residual
//   BNK=false: B global is [K,N].   BNK=true: B global is [N,K] (wte).
//   ACT: 0 = none, 1 = tanh-GELU
// Tile 128x128x32, 256 threads (8 warps, 4x2), reg-prefetch pipelined.
// smem: Ah 16K | Al 16K | Bh 16K | Bl 16K = 64KB
// ---------------------------------------------------------------------------
#define BM 128
#define BN 128
#define BKT 32
#define GEMM_SMEM 65536

template<int ACT, bool BNK>
__global__ void __launch_bounds__(256) mma_gemm(
    const float* __restrict__ A, const float* __restrict__ Bw,
    const float* __restrict__ bias, const float* __restrict__ resid,
    float* __restrict__ Cc, int Mm, int Nn, int Kk)
{
    extern __shared__ char ds[];
    const uint32_t sAh = smem_u32(ds);
    const uint32_t sAl = sAh + 16384;
    const uint32_t sBh = sAh + 32768;
    const uint32_t sBl = sAh + 49152;

    const int tid = threadIdx.x, lane = tid & 31, wid = tid >> 5;
    const int bm = blockIdx.y * BM, bn = blockIdx.x * BN;
    const int NT = Kk / BKT;

    float ra[16], rb[16];

    // ---- gmem tile load into registers -----------------------------------
    auto gload = [&](int t){
        const int k0 = t * BKT;
        #pragma unroll
        for (int i = 0; i < 4; i++){
            int idx = tid + i*256;
            int r = idx >> 3, c4 = (idx & 7) * 4;
            const float4 v = *reinterpret_cast<const float4*>(
                A + (size_t)(bm + r) * Kk + k0 + c4);
            ra[i*4+0]=v.x; ra[i*4+1]=v.y; ra[i*4+2]=v.z; ra[i*4+3]=v.w;
        }
        if (BNK){
            #pragma unroll
            for (int i = 0; i < 4; i++){
                int idx = tid + i*256;
                int r = idx >> 3, c4 = (idx & 7) * 4;
                int gn = bn + r;
                if (gn < Nn){
                    const float4 v = *reinterpret_cast<const float4*>(
                        Bw + (size_t)gn * Kk + k0 + c4);
                    rb[i*4+0]=v.x; rb[i*4+1]=v.y; rb[i*4+2]=v.z; rb[i*4+3]=v.w;
                } else {
                    rb[i*4+0]=0.f; rb[i*4+1]=0.f; rb[i*4+2]=0.f; rb[i*4+3]=0.f;
                }
            }
        } else {
            #pragma unroll
            for (int i = 0; i < 4; i++){
                int idx = tid + i*256;
                int kk = idx >> 5, nq = idx & 31;
                const float4 v = *reinterpret_cast<const float4*>(
                    Bw + (size_t)(k0 + kk) * Nn + bn + nq*4);
                rb[i*4+0]=v.x; rb[i*4+1]=v.y; rb[i*4+2]=v.z; rb[i*4+3]=v.w;
            }
        }
    };

    // ---- regs -> smem (with tf32 hi/lo split) ----------------------------
    auto sstore = [&](){
        #pragma unroll
        for (int i = 0; i < 4; i++){
            int idx = tid + i*256;
            int r = idx >> 3, c4 = (idx & 7) * 4;
            uint32_t off = SWZ((uint32_t)(r*128 + c4*4));
            float x=ra[i*4+0], y=ra[i*4+1], z=ra[i*4+2], w=ra[i*4+3];
            float hx=tf32_hi(x), hy=tf32_hi(y), hz=tf32_hi(z), hw=tf32_hi(w);
            sts128(sAh+off, hx, hy, hz, hw);
            sts128(sAl+off, x-hx, y-hy, z-hz, w-hw);
        }
        if (BNK){
            #pragma unroll
            for (int i = 0; i < 4; i++){
                int idx = tid + i*256;
                int r = idx >> 3, c4 = (idx & 7) * 4;
                uint32_t off = SWZ((uint32_t)(r*128 + c4*4));
                float x=rb[i*4+0], y=rb[i*4+1], z=rb[i*4+2], w=rb[i*4+3];
                float hx=tf32_hi(x), hy=tf32_hi(y), hz=tf32_hi(z), hw=tf32_hi(w);
                sts128(sBh+off, hx, hy, hz, hw);
                sts128(sBl+off, x-hx, y-hy, z-hz, w-hw);
            }
        } else {
            #pragma unroll
            for (int i = 0; i < 4; i++){
                int idx = tid + i*256;
                int kk = idx >> 5, nq = idx & 31;
                #pragma unroll
                for (int j = 0; j < 4; j++){
                    int n = nq*4 + j;
                    uint32_t off = SWZ((uint32_t)(n*128 + kk*4));
                    float x = rb[i*4+j];
                    float hx = tf32_hi(x);
                    sts32(sBh+off, hx);
                    sts32(sBl+off, x-hx);
                }
            }
        }
    };

    // ---- per-warp compute -------------------------------------------------
    float acc[2][8][4];
    #pragma unroll
    for (int a=0;a<2;a++) for (int b=0;b<8;b++) for (int c=0;c<4;c++) acc[a][b][c]=0.f;

    const int mw = wid >> 1, nw = wid & 1;
    const int m0 = mw * 32, n0 = nw * 64;
    const int q = lane >> 3, r8 = lane & 7;

    auto compute = [&](){
        #pragma unroll
        for (int ks = 0; ks < 4; ks++){
            const int kb = ks * 8;
            uint32_t ah[2][4], al[2][4];
            #pragma unroll
            for (int mt = 0; mt < 2; mt++){
                uint32_t off = SWZ((uint32_t)((m0 + mt*16 + (q&1)*8 + r8)*128 + (kb + (q>>1)*4)*4));
                ldsm4(ah[mt], sAh + off);
                ldsm4(al[mt], sAl + off);
            }
            #pragma unroll
            for (int ng = 0; ng < 4; ng++){
                uint32_t bh[4], bl[4];
                uint32_t off = SWZ((uint32_t)((n0 + ng*16 + (q>>1)*8 + r8)*128 + (kb + (q&1)*4)*4));
                ldsm4(bh, sBh + off);
                ldsm4(bl, sBl + off);
                #pragma unroll
                for (int mt = 0; mt < 2; mt++){
                    #pragma unroll
                    for (int sub = 0; sub < 2; sub++){
                        float* d = acc[mt][ng*2 + sub];
                        mma8(d, ah[mt], bh[sub*2], bh[sub*2+1]);   // hi*hi
                        mma8(d, ah[mt], bl[sub*2], bl[sub*2+1]);   // hi*lo
                        mma8(d, al[mt], bh[sub*2], bh[sub*2+1]);   // lo*hi
                    }
                }
            }
        }
    };

    // ---- pipelined main loop ---------------------------------------------
    gload(0);
    for (int t = 0; t < NT; t++){
        __syncthreads();
        sstore();
        __syncthreads();
        if (t + 1 < NT) gload(t + 1);
        compute();
    }

    // ---- epilogue ---------------------------------------------------------
    #pragma unroll
    for (int mt = 0; mt < 2; mt++){
        #pragma unroll
        for (int h2 = 0; h2 < 2; h2++){
            int row = bm + m0 + mt*16 + (lane>>2) + h2*8;
            float* crow = Cc + (size_t)row * Nn;
            const float* rrow = resid ? resid + (size_t)row * Nn : nullptr;
            #pragma unroll
            for (int nt = 0; nt < 8; nt++){
                int col = bn + n0 + nt*8 + (lane&3)*2;
                if (col >= Nn) continue;
                float v0 = acc[mt][nt][h2*2+0];
                float v1 = acc[mt][nt][h2*2+1];
                bool has1 = (col + 1 < Nn);
                if (bias){ v0 += bias[col]; if (has1) v1 += bias[col+1]; }
                if (ACT == 1){
                    float x3 = v0*v0*v0;
                    v0 = 0.5f*v0*(1.f + tanhf(0.7978845608028654f*(v0 + 0.044715f*x3)));
                    x3 = v1*v1*v1;
                    v1 = 0.5f*v1*(1.f + tanhf(0.7978845608028654f*(v1 + 0.044715f*x3)));
                }
                if (rrow){ v0 += rrow[col]; if (has1) v1 += rrow[col+1]; }
                if (((Nn & 1) == 0) && has1){
                    // row stride even => crow+col is 8B aligned (col is even)
                    float2 st; st.x = v0; st.y = v1;
                    *reinterpret_cast<float2*>(crow + col) = st;
                } else {
                    crow[col] = v0;
                    if (has1) crow[col + 1] = v1;
                }
            }
        }
    }
}

// ---------------------------------------------------------------------------
// Block reductions
// ---------------------------------------------------------------------------
__device__ __forceinline__ float block_reduce_sum(float v) {
    __shared__ float sh[32];
    __syncthreads();
    int lane = threadIdx.x & 31, wid = threadIdx.x >> 5;
    #pragma unroll
    for (int o = 16; o > 0; o >>= 1) v += __shfl_down_sync(0xffffffffu, v, o);
    if (lane == 0) sh[wid] = v;
    __syncthreads();
    v = (threadIdx.x < (blockDim.x >> 5)) ? sh[lane] : 0.f;
    if (wid == 0) {
        #pragma unroll
        for (int o = 16; o > 0; o >>= 1) v += __shfl_down_sync(0xffffffffu, v, o);
        if (lane == 0) sh[0] = v;
    }
    __syncthreads();
    return sh[0];
}

__device__ __forceinline__ float block_reduce_max(float v) {
    __shared__ float sh[32];
    __syncthreads();
    int lane = threadIdx.x & 31, wid = threadIdx.x >> 5;
    #pragma unroll
    for (int o = 16; o > 0; o >>= 1) v = fmaxf(v, __shfl_down_sync(0xffffffffu, v, o));
    if (lane == 0) sh[wid] = v;
    __syncthreads();
    v = (threadIdx.x < (blockDim.x >> 5)) ? sh[lane] : -INFINITY;
    if (wid == 0) {
        #pragma unroll
        for (int o = 16; o > 0; o >>= 1) v = fmaxf(v, __shfl_down_sync(0xffffffffu, v, o));
        if (lane == 0) sh[0] = v;
    }
    __syncthreads();
    return sh[0];
}

// ---------------------------------------------------------------------------
// FIRE bias
// ---------------------------------------------------------------------------
__global__ void fire_bias_kernel(const float* __restrict__ log_c,
                                 const float* __restrict__ v1w, const float* __restrict__ v1b,
                                 const float* __restrict__ v2w, const float* __restrict__ v2b,
                                 const float* __restrict__ v3w, const float* __restrict__ v3b,
                                 float* __restrict__ bias) {
    __shared__ float s1w[32], s1b[32], s2w[1024], s2b[32], s3w[32];
    __shared__ float s3b, sc;
    int tid = threadIdx.x;
    if (tid < 32) { s1w[tid] = v1w[tid]; s1b[tid] = v1b[tid]; s2b[tid] = v2b[tid]; s3w[tid] = v3w[tid]; }
    for (int i = tid; i < 1024; i += blockDim.x) s2w[i] = v2w[i];
    if (tid == 0) { s3b = v3b[0]; sc = expf(log_c[0]); }
    __syncthreads();

    int idx = blockIdx.x * blockDim.x + tid;
    if (idx >= T_*T_) return;
    int i = idx / T_, j = idx % T_;
    if (j > i) { bias[idx] = -1e30f; return; }

    float c = sc;
    float fi = (float)(i + 1), fj = (float)(j + 1);
    float pv = logf(c * (fi - fj) + 1.0f) / logf(c * fi + 1.0f);

    float h1[32];
    #pragma unroll
    for (int k = 0; k < 32; k++) h1[k] = fmaxf(pv * s1w[k] + s1b[k], 0.f);
    float out = s3b;
    #pragma unroll
    for (int k2 = 0; k2 < 32; k2++) {
        float a = s2b[k2];
        #pragma unroll
        for (int k1 = 0; k1 < 32; k1++) a += h1[k1] * s2w[k1*32 + k2];
        out += fmaxf(a, 0.f) * s3w[k2];
    }
    bias[idx] = out;
}

// ---------------------------------------------------------------------------
// Embedding gather
// ---------------------------------------------------------------------------
__global__ void embed_kernel(const int* __restrict__ idx, const float* __restrict__ wte,
                             float* __restrict__ x) {
    int row = blockIdx.x;
    const float* src = wte + (size_t)idx[row] * C_;
    float* dst = x + (size_t)row * C_;
    for (int c = threadIdx.x; c < C_; c += blockDim.x) dst[c] = src[c];
}

// ---------------------------------------------------------------------------
// LayerNorm
// ---------------------------------------------------------------------------
__global__ void ln_kernel(const float* __restrict__ x, const float* __restrict__ g,
                          const float* __restrict__ b, float* __restrict__ out) {
    int row = blockIdx.x;
    const float* xr = x + (size_t)row * C_;
    float v0 = xr[threadIdx.x], v1 = xr[threadIdx.x + 256], v2 = xr[threadIdx.x + 512];
    float s = block_reduce_sum(v0 + v1 + v2);
    float mean = s * (1.0f / C_);
    float d0 = v0 - mean, d1 = v1 - mean, d2 = v2 - mean;
    float s2 = block_reduce_sum(d0*d0 + d1*d1 + d2*d2);
    float rs = rsqrtf(s2 * (1.0f / C_) + 1e-5f);
    float* o = out + (size_t)row * C_;
    int c = threadIdx.x;
    o[c      ] = d0 * rs * g[c      ] + b[c      ];
    o[c + 256] = d1 * rs * g[c + 256] + b[c + 256];
    o[c + 512] = d2 * rs * g[c + 512] + b[c + 512];
}

// ---------------------------------------------------------------------------
// Attention scores (masked tiles skipped — never read downstream)
// ---------------------------------------------------------------------------
__global__ void attn_score_kernel(const float* __restrict__ qkv,
                                  const float* __restrict__ bias,
                                  float* __restrict__ att) {
    int bh = blockIdx.z, b = bh / H_, h = bh % H_;
    int i0 = blockIdx.y * 32, j0 = blockIdx.x * 32;
    if (j0 > i0 + 31) return;
    float* ab = att + (size_t)bh * T_ * T_;
    int tid = threadIdx.x;

    __shared__ float Qs[32][65], Ks[32][65];
    const float* qb = qkv + (size_t)b * T_ * 3 * C_ + h * D_;
    const float* kb = qb + C_;
    for (int idx = tid; idx < 32 * 64; idx += 256) {
        int r = idx / 64, c = idx % 64;
        Qs[r][c] = qb[(size_t)(i0 + r) * 3 * C_ + c];
        Ks[r][c] = kb[(size_t)(j0 + r) * 3 * C_ + c];
    }
    __syncthreads();

    int r = (tid / 16) * 2, c2 = (tid % 16) * 2;
    float acc00 = 0, acc01 = 0, acc10 = 0, acc11 = 0;
    #pragma unroll
    for (int k = 0; k < 64; k++) {
        float a0 = Qs[r][k],  a1 = Qs[r + 1][k];
        float b0 = Ks[c2][k], b1 = Ks[c2 + 1][k];
        acc00 += a0 * b0; acc01 += a0 * b1;
        acc10 += a1 * b0; acc11 += a1 * b1;
    }
    const float scale = 0.125f;
    int gi0 = i0 + r, gj0 = j0 + c2;
    ab[(size_t)gi0 * T_ + gj0    ] = scale * acc00 + bias[gi0 * T_ + gj0    ];
    ab[(size_t)gi0 * T_ + gj0 + 1] = scale * acc01 + bias[gi0 * T_ + gj0 + 1];
    ab[(size_t)(gi0+1)*T_ + gj0    ] = scale * acc10 + bias[(gi0+1)*T_ + gj0    ];
    ab[(size_t)(gi0+1)*T_ + gj0 + 1] = scale * acc11 + bias[(gi0+1)*T_ + gj0 + 1];
}

// ---------------------------------------------------------------------------
// Row softmax, capped at causal limit
// ---------------------------------------------------------------------------
__global__ void softmax_kernel(float* att) {
    int row = blockIdx.x;
    int i = row & (T_ - 1);
    float* a = att + (size_t)row * T_;
    int jlim = ((i >> 5) + 1) << 5;
    float m = -INFINITY;
    for (int j = threadIdx.x; j < jlim; j += 256) m = fmaxf(m, a[j]);
    m = block_reduce_max(m);
    float s = 0.f;
    for (int j = threadIdx.x; j < jlim; j += 256) {
        float e = expf(a[j] - m);
        a[j] = e;
        s += e;
    }
    s = block_reduce_sum(s);
    float inv = 1.0f / s;
    for (int j = threadIdx.x; j < jlim; j += 256) a[j] *= inv;
}

// ---------------------------------------------------------------------------
// AV
// ---------------------------------------------------------------------------
__global__ void attn_av_kernel(const float* __restrict__ qkv,
                               const float* __restrict__ att,
                               float* __restrict__ y) {
    int bh = blockIdx.y, b = bh / H_, h = bh % H_;
    int i0 = blockIdx.x * 32;
    const float* vb = qkv + (size_t)b * T_ * 3 * C_ + 2 * C_ + h * D_;
    const float* ab = att + (size_t)bh * T_ * T_;
    __shared__ float As[32][33], Vs[32][65];
    int tid = threadIdx.x;
    int r = tid / 8, d0 = (tid % 8) * 8;
    float acc[8] = {};
    int jmax = i0 + 32;
    for (int j0 = 0; j0 < jmax; j0 += 32) {
        for (int idx = tid; idx < 32 * 32; idx += 256) {
            int rr = idx / 32, cc = idx % 32;
            As[rr][cc] = ab[(size_t)(i0 + rr) * T_ + j0 + cc];
        }
        for (int idx = tid; idx < 32 * 64; idx += 256) {
            int rr = idx / 64, cc = idx % 64;
            Vs[rr][cc] = vb[(size_t)(j0 + rr) * 3 * C_ + cc];
        }
        __syncthreads();
        #pragma unroll
        for (int k = 0; k < 32; k++) {
            float a = As[r][k];
            #pragma unroll
            for (int d = 0; d < 8; d++) acc[d] += a * Vs[k][d0 + d];
        }
        __syncthreads();
    }
    float* yb = y + (size_t)b * T_ * C_ + (size_t)(i0 + r) * C_ + h * D_ + d0;
    #pragma unroll
    for (int d = 0; d < 8; d++) yb[d] = acc[d];
}

// ---------------------------------------------------------------------------
// Launch
// ---------------------------------------------------------------------------
extern "C" void kernel_launch(void* const* d_in, const int* in_sizes, int n_in,
                              void* d_out, int out_size) {
    int o = (n_in >= 2 && in_sizes[1] == 1) ? 1 : 0;

    const int*   idx   = (const int*)  d_in[0];
    const float* wte   = (const float*)d_in[1 + o];
    const float* log_c = (const float*)d_in[2 + o];
    const float* v1w   = (const float*)d_in[3 + o];
    const float* v1b   = (const float*)d_in[4 + o];
    const float* v2w   = (const float*)d_in[5 + o];
    const float* v2b   = (const float*)d_in[6 + o];
    const float* v3w   = (const float*)d_in[7 + o];
    const float* v3b   = (const float*)d_in[8 + o];
    const float* ln1g  = (const float*)d_in[9 + o];
    const float* ln1b  = (const float*)d_in[10 + o];
    const float* attnw = (const float*)d_in[11 + o];
    const float* attnb = (const float*)d_in[12 + o];
    const float* projw = (const float*)d_in[13 + o];
    const float* projb = (const float*)d_in[14 + o];
    const float* ln2g  = (const float*)d_in[15 + o];
    const float* ln2b  = (const float*)d_in[16 + o];
    const float* fcw   = (const float*)d_in[17 + o];
    const float* fcb   = (const float*)d_in[18 + o];
    const float* fc2w  = (const float*)d_in[19 + o];
    const float* fc2b  = (const float*)d_in[20 + o];
    const float* lnfg  = (const float*)d_in[21 + o];
    const float* lnfb  = (const float*)d_in[22 + o];

    float *bias, *x, *h, *qkv, *att, *y, *mlp;
    cudaGetSymbolAddress((void**)&bias, g_bias);
    cudaGetSymbolAddress((void**)&x,    g_x);
    cudaGetSymbolAddress((void**)&h,    g_h);
    cudaGetSymbolAddress((void**)&qkv,  g_qkv);
    cudaGetSymbolAddress((void**)&att,  g_att);
    cudaGetSymbolAddress((void**)&y,    g_y);
    cudaGetSymbolAddress((void**)&mlp,  g_mlp);

    cudaFuncSetAttribute(mma_gemm<0,false>, cudaFuncAttributeMaxDynamicSharedMemorySize, GEMM_SMEM);
    cudaFuncSetAttribute(mma_gemm<1,false>, cudaFuncAttributeMaxDynamicSharedMemorySize, GEMM_SMEM);
    cudaFuncSetAttribute(mma_gemm<0,true>,  cudaFuncAttributeMaxDynamicSharedMemorySize, GEMM_SMEM);

    // 1. FIRE bias
    fire_bias_kernel<<<(T_*T_ + 255) / 256, 256>>>(log_c, v1w, v1b, v2w, v2b, v3w, v3b, bias);

    // 2. Embedding
    embed_kernel<<<M_, 256>>>(idx, wte, x);

    // 3. Transformer layers
    const dim3 g_qkvd(3*C_/BN, M_/BM);
    const dim3 g_cc  (C_/BN,   M_/BM);
    const dim3 g_fc  (4*C_/BN, M_/BM);
    const dim3 g_sc  (T_/32, T_/32, B_*H_);
    const dim3 g_av  (T_/32, B_*H_);

    for (int l = 0; l < L_; l++) {
        ln_kernel<<<M_, 256>>>(x, ln1g + (size_t)l*C_, ln1b + (size_t)l*C_, h);
        mma_gemm<0,false><<<g_qkvd, 256, GEMM_SMEM>>>(h, attnw + (size_t)l*C_*3*C_,
                                                      attnb + (size_t)l*3*C_, nullptr,
                                                      qkv, M_, 3*C_, C_);
        attn_score_kernel<<<g_sc, 256>>>(qkv, bias, att);
        softmax_kernel<<<B_*H_*T_, 256>>>(att);
        attn_av_kernel<<<g_av, 256>>>(qkv, att, y);
        mma_gemm<0,false><<<g_cc, 256, GEMM_SMEM>>>(y, projw + (size_t)l*C_*C_,
                                                    projb + (size_t)l*C_, x,
                                                    x, M_, C_, C_);
        ln_kernel<<<M_, 256>>>(x, ln2g + (size_t)l*C_, ln2b + (size_t)l*C_, h);
        mma_gemm<1,false><<<g_fc, 256, GEMM_SMEM>>>(h, fcw + (size_t)l*C_*4*C_,
                                                    fcb + (size_t)l*4*C_, nullptr,
                                                    mlp, M_, 4*C_, C_);
        mma_gemm<0,false><<<g_cc, 256, GEMM_SMEM>>>(mlp, fc2w + (size_t)l*4*C_*C_,
                                                    fc2b + (size_t)l*C_, x,
                                                    x, M_, C_, 4*C_);
    }

    // 4. Final LN + tied LM head
    ln_kernel<<<M_, 256>>>(x, lnfg, lnfb, h);
    const dim3 g_lm((V_ + BN - 1)/BN, M_/BM);
    mma_gemm<0,true><<<g_lm, 256, GEMM_SMEM>>>(h, wte, nullptr, nullptr,
                                               (float*)d_out, M_, V_, C_);
}

// round 5
// speedup vs baseline: 3.1271x; 1.8967x over previous
#include <cuda_runtime.h>
#include <cuda_bf16.h>
#include <math.h>
#include <stdint.h>

// Problem constants
#define L_ 12
#define H_ 12
#define C_ 768
#define V_ 50257
#define B_ 2
#define T_ 1024
#define D_ 64
#define M_ (B_*T_)   // 2048 rows

typedef __nv_bfloat16 bf16;

// ---------------------------------------------------------------------------
// Scratch (static device globals)
// ---------------------------------------------------------------------------
__device__ float g_bias[T_*T_];
__device__ float g_x   [M_*C_];
__device__ float g_qkv [M_*3*C_];
__device__ float g_att [B_*H_*T_*T_];

__device__ bf16 g_h_hi [M_*C_],   g_h_lo [M_*C_];
__device__ bf16 g_y_hi [M_*C_],   g_y_lo [M_*C_];
__device__ bf16 g_mlp_hi[M_*4*C_], g_mlp_lo[M_*4*C_];

__device__ bf16 g_wa_hi [L_*3*C_*C_], g_wa_lo [L_*3*C_*C_];
__device__ bf16 g_wp_hi [L_*C_*C_],   g_wp_lo [L_*C_*C_];
__device__ bf16 g_wf_hi [L_*4*C_*C_], g_wf_lo [L_*4*C_*C_];
__device__ bf16 g_wf2_hi[L_*C_*4*C_], g_wf2_lo[L_*C_*4*C_];
__device__ bf16 g_wte_hi[(size_t)V_*C_], g_wte_lo[(size_t)V_*C_];

// ---------------------------------------------------------------------------
// Helpers
// ---------------------------------------------------------------------------
__device__ __forceinline__ uint32_t smem_u32(const void* p){
    uint32_t a;
    asm("{ .reg .u64 t; cvta.to.shared.u64 t, %1; cvt.u32.u64 %0, t; }":"=r"(a):"l"(p));
    return a;
}
__device__ __forceinline__ void bsplit(float v, bf16& h, bf16& l){
    h = __float2bfloat16(v);
    l = __float2bfloat16(v - __bfloat162float(h));
}
__device__ __forceinline__ void cpa16(uint32_t saddr, const void* gptr){
    asm volatile("cp.async.cg.shared.global [%0], [%1], 16;"::"r"(saddr),"l"(gptr));
}
__device__ __forceinline__ void cpa16z(uint32_t saddr, const void* gptr, int ssz){
    asm volatile("cp.async.cg.shared.global [%0], [%1], 16, %2;"::"r"(saddr),"l"(gptr),"r"(ssz));
}
__device__ __forceinline__ void ldsm4(uint32_t* r, uint32_t addr){
    asm volatile("ldmatrix.sync.aligned.m8n8.x4.shared.b16 {%0,%1,%2,%3}, [%4];"
      : "=r"(r[0]),"=r"(r[1]),"=r"(r[2]),"=r"(r[3]) : "r"(addr));
}
__device__ __forceinline__ void mma16(float* d, const uint32_t* a, uint32_t b0, uint32_t b1){
    asm volatile("mma.sync.aligned.m16n8k16.row.col.f32.bf16.bf16.f32 "
      "{%0,%1,%2,%3}, {%4,%5,%6,%7}, {%8,%9}, {%0,%1,%2,%3};"
      : "+f"(d[0]),"+f"(d[1]),"+f"(d[2]),"+f"(d[3])
      : "r"(a[0]),"r"(a[1]),"r"(a[2]),"r"(a[3]),"r"(b0),"r"(b1));
}
#define SWZ(o) ((o) ^ (((o)>>3)&0x70))

// ---------------------------------------------------------------------------
// BF16 3x-split GEMM via mma.m16n8k16, cp.async double-buffered.
//   Inputs: A planes [2048,K] bf16 hi/lo; B planes [N,K] bf16 hi/lo.
//   C[M,N] = act(A@B^T + bias) (+ residual)  -> fp32 Cf  OR bf16 hi/lo planes
// Tile 128x128x64(k), 256 threads (8 warps, 4x2 warp grid, 32x64 warp tiles).
// smem per stage: Ah 16K | Al 16K | Bh 16K | Bl 16K = 64KB, 2 stages.
// ---------------------------------------------------------------------------
#define GEMM_SMEM (131072 + 1024)

template<int ACT, bool OUTBF>
__global__ void __launch_bounds__(256) mma_gemm(
    const bf16* __restrict__ Ahi, const bf16* __restrict__ Alo,
    const bf16* __restrict__ Bhi, const bf16* __restrict__ Blo,
    const float* __restrict__ bias, const float* __restrict__ resid,
    float* __restrict__ Cf, bf16* __restrict__ Chi, bf16* __restrict__ Clo,
    int Nn, int Kk)
{
    extern __shared__ char ds[];
    const uint32_t sb = (smem_u32(ds) + 1023) & ~1023u;

    const int tid = threadIdx.x, lane = tid & 31, wid = tid >> 5;
    const int bm = blockIdx.y * 128, bn = blockIdx.x * 128;
    const int NT = Kk >> 6;     // k-tiles of 64

    // ---- async stage load -------------------------------------------------
    auto cp_stage = [&](int t){
        const uint32_t base = sb + (uint32_t)(t & 1) * 65536;
        const int k0 = t << 6;
        #pragma unroll
        for (int i = 0; i < 4; i++){
            int idx = tid + i*256;
            int r = idx >> 3, c = idx & 7;          // row 0..127, 16B chunk 0..7
            uint32_t off = SWZ((uint32_t)(r*128 + c*16));
            size_t ka = (size_t)(bm + r) * Kk + k0 + c*8;
            cpa16(base + off,         Ahi + ka);
            cpa16(base + 16384 + off, Alo + ka);
            int gn = bn + r;
            size_t kb = (size_t)gn * Kk + k0 + c*8;
            int ssz = (gn < Nn) ? 16 : 0;
            cpa16z(base + 32768 + off, Bhi + kb, ssz);
            cpa16z(base + 49152 + off, Blo + kb, ssz);
        }
        asm volatile("cp.async.commit_group;":::"memory");
    };

    // ---- warp compute -----------------------------------------------------
    float acc[2][8][4];
    #pragma unroll
    for (int a=0;a<2;a++) for (int b=0;b<8;b++) for (int c=0;c<4;c++) acc[a][b][c]=0.f;

    const int m0 = (wid >> 1) * 32, n0 = (wid & 1) * 64;
    const uint32_t arow = (uint32_t)(m0 + (lane & 15));
    const uint32_t acol = (uint32_t)((lane >> 4) * 16);
    const uint32_t brow = (uint32_t)(n0 + (lane & 7) + ((lane >> 4) & 1) * 8);
    const uint32_t bcol = (uint32_t)(((lane >> 3) & 1) * 16);

    auto compute = [&](int t){
        const uint32_t base = sb + (uint32_t)(t & 1) * 65536;
        #pragma unroll
        for (int ks = 0; ks < 4; ks++){
            const uint32_t kb2 = (uint32_t)(ks * 32);   // byte offset of k16 group
            uint32_t ah[2][4], al[2][4];
            #pragma unroll
            for (int mt = 0; mt < 2; mt++){
                uint32_t off = SWZ((arow + mt*16)*128 + kb2 + acol);
                ldsm4(ah[mt], base + off);
                ldsm4(al[mt], base + 16384 + off);
            }
            #pragma unroll
            for (int g = 0; g < 4; g++){
                uint32_t off = SWZ((brow + g*16)*128 + kb2 + bcol);
                uint32_t bh[4], bl[4];
                ldsm4(bh, base + 32768 + off);
                ldsm4(bl, base + 49152 + off);
                #pragma unroll
                for (int mt = 0; mt < 2; mt++){
                    #pragma unroll
                    for (int sub = 0; sub < 2; sub++){
                        float* d = acc[mt][g*2 + sub];
                        mma16(d, ah[mt], bh[sub*2], bh[sub*2+1]);  // hi*hi
                        mma16(d, ah[mt], bl[sub*2], bl[sub*2+1]);  // hi*lo
                        mma16(d, al[mt], bh[sub*2], bh[sub*2+1]);  // lo*hi
                    }
                }
            }
        }
    };

    // ---- pipelined mainloop ----------------------------------------------
    cp_stage(0);
    if (NT > 1) cp_stage(1);
    for (int t = 0; t < NT; t++){
        if (t + 1 < NT) asm volatile("cp.async.wait_group 1;":::"memory");
        else            asm volatile("cp.async.wait_group 0;":::"memory");
        __syncthreads();
        compute(t);
        __syncthreads();
        if (t + 2 < NT) cp_stage(t + 2);
    }

    // ---- epilogue ---------------------------------------------------------
    #pragma unroll
    for (int mt = 0; mt < 2; mt++){
        #pragma unroll
        for (int h2 = 0; h2 < 2; h2++){
            int row = bm + m0 + mt*16 + (lane>>2) + h2*8;
            float* crow = OUTBF ? nullptr : (Cf + (size_t)row * Nn);
            const float* rrow = resid ? resid + (size_t)row * Nn : nullptr;
            #pragma unroll
            for (int nt = 0; nt < 8; nt++){
                int col = bn + n0 + nt*8 + (lane&3)*2;
                if (col >= Nn) continue;
                float v0 = acc[mt][nt][h2*2+0];
                float v1 = acc[mt][nt][h2*2+1];
                bool has1 = (col + 1 < Nn);
                if (bias){ v0 += bias[col]; if (has1) v1 += bias[col+1]; }
                if (ACT == 1){
                    float x3 = v0*v0*v0;
                    v0 = 0.5f*v0*(1.f + tanhf(0.7978845608028654f*(v0 + 0.044715f*x3)));
                    x3 = v1*v1*v1;
                    v1 = 0.5f*v1*(1.f + tanhf(0.7978845608028654f*(v1 + 0.044715f*x3)));
                }
                if (rrow){ v0 += rrow[col]; if (has1) v1 += rrow[col+1]; }
                if (OUTBF){
                    size_t o = (size_t)row * Nn + col;
                    bf16 bh, bl;
                    bsplit(v0, bh, bl); Chi[o] = bh; Clo[o] = bl;
                    if (has1){ bsplit(v1, bh, bl); Chi[o+1] = bh; Clo[o+1] = bl; }
                } else if (((Nn & 1) == 0) && has1){
                    float2 st; st.x = v0; st.y = v1;
                    *reinterpret_cast<float2*>(crow + col) = st;
                } else {
                    crow[col] = v0;
                    if (has1) crow[col + 1] = v1;
                }
            }
        }
    }
}

// ---------------------------------------------------------------------------
// Weight prep: transpose [K,N] -> [N,K] + bf16 hi/lo split (per layer in z)
// ---------------------------------------------------------------------------
__global__ void wsplit_t_kernel(const float* __restrict__ in,
                                bf16* __restrict__ ohi, bf16* __restrict__ olo,
                                int K, int N){
    __shared__ float t[32][33];
    size_t lb = (size_t)blockIdx.z * K * N;
    const float* inp = in + lb;
    int kb = blockIdx.y*32, nb = blockIdx.x*32;
    int tx = threadIdx.x, ty = threadIdx.y;   // (32,8)
    #pragma unroll
    for (int j = 0; j < 4; j++)
        t[ty + 8*j][tx] = inp[(size_t)(kb + ty + 8*j) * N + nb + tx];
    __syncthreads();
    #pragma unroll
    for (int j = 0; j < 4; j++){
        int n = nb + ty + 8*j, k = kb + tx;
        float v = t[tx][ty + 8*j];
        bf16 h, l; bsplit(v, h, l);
        size_t o = lb + (size_t)n * K + k;
        ohi[o] = h; olo[o] = l;
    }
}

// Elementwise split (wte: already [N,K])
__global__ void split_kernel(const float* __restrict__ in,
                             bf16* __restrict__ ohi, bf16* __restrict__ olo, int n){
    int i = blockIdx.x * 256 + threadIdx.x;
    if (i < n){
        bf16 h, l; bsplit(in[i], h, l);
        ohi[i] = h; olo[i] = l;
    }
}

// ---------------------------------------------------------------------------
// Block reductions
// ---------------------------------------------------------------------------
__device__ __forceinline__ float block_reduce_sum(float v) {
    __shared__ float sh[32];
    __syncthreads();
    int lane = threadIdx.x & 31, wid = threadIdx.x >> 5;
    #pragma unroll
    for (int o = 16; o > 0; o >>= 1) v += __shfl_down_sync(0xffffffffu, v, o);
    if (lane == 0) sh[wid] = v;
    __syncthreads();
    v = (threadIdx.x < (blockDim.x >> 5)) ? sh[lane] : 0.f;
    if (wid == 0) {
        #pragma unroll
        for (int o = 16; o > 0; o >>= 1) v += __shfl_down_sync(0xffffffffu, v, o);
        if (lane == 0) sh[0] = v;
    }
    __syncthreads();
    return sh[0];
}
__device__ __forceinline__ float block_reduce_max(float v) {
    __shared__ float sh[32];
    __syncthreads();
    int lane = threadIdx.x & 31, wid = threadIdx.x >> 5;
    #pragma unroll
    for (int o = 16; o > 0; o >>= 1) v = fmaxf(v, __shfl_down_sync(0xffffffffu, v, o));
    if (lane == 0) sh[wid] = v;
    __syncthreads();
    v = (threadIdx.x < (blockDim.x >> 5)) ? sh[lane] : -INFINITY;
    if (wid == 0) {
        #pragma unroll
        for (int o = 16; o > 0; o >>= 1) v = fmaxf(v, __shfl_down_sync(0xffffffffu, v, o));
        if (lane == 0) sh[0] = v;
    }
    __syncthreads();
    return sh[0];
}

// ---------------------------------------------------------------------------
// FIRE bias
// ---------------------------------------------------------------------------
__global__ void fire_bias_kernel(const float* __restrict__ log_c,
                                 const float* __restrict__ v1w, const float* __restrict__ v1b,
                                 const float* __restrict__ v2w, const float* __restrict__ v2b,
                                 const float* __restrict__ v3w, const float* __restrict__ v3b,
                                 float* __restrict__ bias) {
    __shared__ float s1w[32], s1b[32], s2w[1024], s2b[32], s3w[32];
    __shared__ float s3b, sc;
    int tid = threadIdx.x;
    if (tid < 32) { s1w[tid] = v1w[tid]; s1b[tid] = v1b[tid]; s2b[tid] = v2b[tid]; s3w[tid] = v3w[tid]; }
    for (int i = tid; i < 1024; i += blockDim.x) s2w[i] = v2w[i];
    if (tid == 0) { s3b = v3b[0]; sc = expf(log_c[0]); }
    __syncthreads();

    int idx = blockIdx.x * blockDim.x + tid;
    if (idx >= T_*T_) return;
    int i = idx / T_, j = idx % T_;
    if (j > i) { bias[idx] = -1e30f; return; }

    float c = sc;
    float fi = (float)(i + 1), fj = (float)(j + 1);
    float pv = logf(c * (fi - fj) + 1.0f) / logf(c * fi + 1.0f);

    float h1[32];
    #pragma unroll
    for (int k = 0; k < 32; k++) h1[k] = fmaxf(pv * s1w[k] + s1b[k], 0.f);
    float out = s3b;
    #pragma unroll
    for (int k2 = 0; k2 < 32; k2++) {
        float a = s2b[k2];
        #pragma unroll
        for (int k1 = 0; k1 < 32; k1++) a += h1[k1] * s2w[k1*32 + k2];
        out += fmaxf(a, 0.f) * s3w[k2];
    }
    bias[idx] = out;
}

// ---------------------------------------------------------------------------
// Embedding gather
// ---------------------------------------------------------------------------
__global__ void embed_kernel(const int* __restrict__ idx, const float* __restrict__ wte,
                             float* __restrict__ x) {
    int row = blockIdx.x;
    const float* src = wte + (size_t)idx[row] * C_;
    float* dst = x + (size_t)row * C_;
    for (int c = threadIdx.x; c < C_; c += blockDim.x) dst[c] = src[c];
}

// ---------------------------------------------------------------------------
// LayerNorm -> bf16 hi/lo planes
// ---------------------------------------------------------------------------
__global__ void ln_kernel(const float* __restrict__ x, const float* __restrict__ g,
                          const float* __restrict__ b,
                          bf16* __restrict__ ohi, bf16* __restrict__ olo) {
    int row = blockIdx.x;
    const float* xr = x + (size_t)row * C_;
    float v0 = xr[threadIdx.x], v1 = xr[threadIdx.x + 256], v2 = xr[threadIdx.x + 512];
    float s = block_reduce_sum(v0 + v1 + v2);
    float mean = s * (1.0f / C_);
    float d0 = v0 - mean, d1 = v1 - mean, d2 = v2 - mean;
    float s2 = block_reduce_sum(d0*d0 + d1*d1 + d2*d2);
    float rs = rsqrtf(s2 * (1.0f / C_) + 1e-5f);
    size_t base = (size_t)row * C_;
    int c = threadIdx.x;
    bf16 h, l;
    bsplit(d0 * rs * g[c      ] + b[c      ], h, l); ohi[base + c      ] = h; olo[base + c      ] = l;
    bsplit(d1 * rs * g[c + 256] + b[c + 256], h, l); ohi[base + c + 256] = h; olo[base + c + 256] = l;
    bsplit(d2 * rs * g[c + 512] + b[c + 512], h, l); ohi[base + c + 512] = h; olo[base + c + 512] = l;
}

// ---------------------------------------------------------------------------
// Attention scores (masked tiles skipped — never read downstream)
// ---------------------------------------------------------------------------
__global__ void attn_score_kernel(const float* __restrict__ qkv,
                                  const float* __restrict__ bias,
                                  float* __restrict__ att) {
    int bh = blockIdx.z, b = bh / H_, h = bh % H_;
    int i0 = blockIdx.y * 32, j0 = blockIdx.x * 32;
    if (j0 > i0 + 31) return;
    float* ab = att + (size_t)bh * T_ * T_;
    int tid = threadIdx.x;

    __shared__ float Qs[32][65], Ks[32][65];
    const float* qb = qkv + (size_t)b * T_ * 3 * C_ + h * D_;
    const float* kb = qb + C_;
    for (int idx = tid; idx < 32 * 64; idx += 256) {
        int r = idx / 64, c = idx % 64;
        Qs[r][c] = qb[(size_t)(i0 + r) * 3 * C_ + c];
        Ks[r][c] = kb[(size_t)(j0 + r) * 3 * C_ + c];
    }
    __syncthreads();

    int r = (tid / 16) * 2, c2 = (tid % 16) * 2;
    float acc00 = 0, acc01 = 0, acc10 = 0, acc11 = 0;
    #pragma unroll
    for (int k = 0; k < 64; k++) {
        float a0 = Qs[r][k],  a1 = Qs[r + 1][k];
        float b0 = Ks[c2][k], b1 = Ks[c2 + 1][k];
        acc00 += a0 * b0; acc01 += a0 * b1;
        acc10 += a1 * b0; acc11 += a1 * b1;
    }
    const float scale = 0.125f;
    int gi0 = i0 + r, gj0 = j0 + c2;
    ab[(size_t)gi0 * T_ + gj0    ] = scale * acc00 + bias[gi0 * T_ + gj0    ];
    ab[(size_t)gi0 * T_ + gj0 + 1] = scale * acc01 + bias[gi0 * T_ + gj0 + 1];
    ab[(size_t)(gi0+1)*T_ + gj0    ] = scale * acc10 + bias[(gi0+1)*T_ + gj0    ];
    ab[(size_t)(gi0+1)*T_ + gj0 + 1] = scale * acc11 + bias[(gi0+1)*T_ + gj0 + 1];
}

// ---------------------------------------------------------------------------
// Row softmax, capped at causal limit
// ---------------------------------------------------------------------------
__global__ void softmax_kernel(float* att) {
    int row = blockIdx.x;
    int i = row & (T_ - 1);
    float* a = att + (size_t)row * T_;
    int jlim = ((i >> 5) + 1) << 5;
    float m = -INFINITY;
    for (int j = threadIdx.x; j < jlim; j += 256) m = fmaxf(m, a[j]);
    m = block_reduce_max(m);
    float s = 0.f;
    for (int j = threadIdx.x; j < jlim; j += 256) {
        float e = expf(a[j] - m);
        a[j] = e;
        s += e;
    }
    s = block_reduce_sum(s);
    float inv = 1.0f / s;
    for (int j = threadIdx.x; j < jlim; j += 256) a[j] *= inv;
}

// ---------------------------------------------------------------------------
// AV -> bf16 hi/lo planes
// ---------------------------------------------------------------------------
__global__ void attn_av_kernel(const float* __restrict__ qkv,
                               const float* __restrict__ att,
                               bf16* __restrict__ yhi, bf16* __restrict__ ylo) {
    int bh = blockIdx.y, b = bh / H_, h = bh % H_;
    int i0 = blockIdx.x * 32;
    const float* vb = qkv + (size_t)b * T_ * 3 * C_ + 2 * C_ + h * D_;
    const float* ab = att + (size_t)bh * T_ * T_;
    __shared__ float As[32][33], Vs[32][65];
    int tid = threadIdx.x;
    int r = tid / 8, d0 = (tid % 8) * 8;
    float acc[8] = {};
    int jmax = i0 + 32;
    for (int j0 = 0; j0 < jmax; j0 += 32) {
        for (int idx = tid; idx < 32 * 32; idx += 256) {
            int rr = idx / 32, cc = idx % 32;
            As[rr][cc] = ab[(size_t)(i0 + rr) * T_ + j0 + cc];
        }
        for (int idx = tid; idx < 32 * 64; idx += 256) {
            int rr = idx / 64, cc = idx % 64;
            Vs[rr][cc] = vb[(size_t)(j0 + rr) * 3 * C_ + cc];
        }
        __syncthreads();
        #pragma unroll
        for (int k = 0; k < 32; k++) {
            float a = As[r][k];
            #pragma unroll
            for (int d = 0; d < 8; d++) acc[d] += a * Vs[k][d0 + d];
        }
        __syncthreads();
    }
    size_t off = (size_t)b * T_ * C_ + (size_t)(i0 + r) * C_ + h * D_ + d0;
    #pragma unroll
    for (int d = 0; d < 8; d++){
        bf16 hh, ll; bsplit(acc[d], hh, ll);
        yhi[off + d] = hh; ylo[off + d] = ll;
    }
}

// ---------------------------------------------------------------------------
// Launch
// ---------------------------------------------------------------------------
extern "C" void kernel_launch(void* const* d_in, const int* in_sizes, int n_in,
                              void* d_out, int out_size) {
    int o = (n_in >= 2 && in_sizes[1] == 1) ? 1 : 0;

    const int*   idx   = (const int*)  d_in[0];
    const float* wte   = (const float*)d_in[1 + o];
    const float* log_c = (const float*)d_in[2 + o];
    const float* v1w   = (const float*)d_in[3 + o];
    const float* v1b   = (const float*)d_in[4 + o];
    const float* v2w   = (const float*)d_in[5 + o];
    const float* v2b   = (const float*)d_in[6 + o];
    const float* v3w   = (const float*)d_in[7 + o];
    const float* v3b   = (const float*)d_in[8 + o];
    const float* ln1g  = (const float*)d_in[9 + o];
    const float* ln1b  = (const float*)d_in[10 + o];
    const float* attnw = (const float*)d_in[11 + o];
    const float* attnb = (const float*)d_in[12 + o];
    const float* projw = (const float*)d_in[13 + o];
    const float* projb = (const float*)d_in[14 + o];
    const float* ln2g  = (const float*)d_in[15 + o];
    const float* ln2b  = (const float*)d_in[16 + o];
    const float* fcw   = (const float*)d_in[17 + o];
    const float* fcb   = (const float*)d_in[18 + o];
    const float* fc2w  = (const float*)d_in[19 + o];
    const float* fc2b  = (const float*)d_in[20 + o];
    const float* lnfg  = (const float*)d_in[21 + o];
    const float* lnfb  = (const float*)d_in[22 + o];

    float *bias, *x, *qkv, *att;
    bf16 *h_hi, *h_lo, *y_hi, *y_lo, *mlp_hi, *mlp_lo;
    bf16 *wa_hi, *wa_lo, *wp_hi, *wp_lo, *wf_hi, *wf_lo, *wf2_hi, *wf2_lo, *wte_hi, *wte_lo;
    cudaGetSymbolAddress((void**)&bias,   g_bias);
    cudaGetSymbolAddress((void**)&x,      g_x);
    cudaGetSymbolAddress((void**)&qkv,    g_qkv);
    cudaGetSymbolAddress((void**)&att,    g_att);
    cudaGetSymbolAddress((void**)&h_hi,   g_h_hi);   cudaGetSymbolAddress((void**)&h_lo,   g_h_lo);
    cudaGetSymbolAddress((void**)&y_hi,   g_y_hi);   cudaGetSymbolAddress((void**)&y_lo,   g_y_lo);
    cudaGetSymbolAddress((void**)&mlp_hi, g_mlp_hi); cudaGetSymbolAddress((void**)&mlp_lo, g_mlp_lo);
    cudaGetSymbolAddress((void**)&wa_hi,  g_wa_hi);  cudaGetSymbolAddress((void**)&wa_lo,  g_wa_lo);
    cudaGetSymbolAddress((void**)&wp_hi,  g_wp_hi);  cudaGetSymbolAddress((void**)&wp_lo,  g_wp_lo);
    cudaGetSymbolAddress((void**)&wf_hi,  g_wf_hi);  cudaGetSymbolAddress((void**)&wf_lo,  g_wf_lo);
    cudaGetSymbolAddress((void**)&wf2_hi, g_wf2_hi); cudaGetSymbolAddress((void**)&wf2_lo, g_wf2_lo);
    cudaGetSymbolAddress((void**)&wte_hi, g_wte_hi); cudaGetSymbolAddress((void**)&wte_lo, g_wte_lo);

    cudaFuncSetAttribute(mma_gemm<0,false>, cudaFuncAttributeMaxDynamicSharedMemorySize, GEMM_SMEM);
    cudaFuncSetAttribute(mma_gemm<1,true>,  cudaFuncAttributeMaxDynamicSharedMemorySize, GEMM_SMEM);

    // 1. FIRE bias + embedding
    fire_bias_kernel<<<(T_*T_ + 255) / 256, 256>>>(log_c, v1w, v1b, v2w, v2b, v3w, v3b, bias);
    embed_kernel<<<M_, 256>>>(idx, wte, x);

    // 2. Weight prep (transpose + bf16 hi/lo split)
    {
        dim3 tb(32, 8);
        wsplit_t_kernel<<<dim3(3*C_/32,  C_/32,  L_), tb>>>(attnw, wa_hi,  wa_lo,  C_,   3*C_);
        wsplit_t_kernel<<<dim3(C_/32,    C_/32,  L_), tb>>>(projw, wp_hi,  wp_lo,  C_,   C_);
        wsplit_t_kernel<<<dim3(4*C_/32,  C_/32,  L_), tb>>>(fcw,   wf_hi,  wf_lo,  C_,   4*C_);
        wsplit_t_kernel<<<dim3(C_/32,  4*C_/32,  L_), tb>>>(fc2w,  wf2_hi, wf2_lo, 4*C_, C_);
        split_kernel<<<(V_*C_ + 255)/256, 256>>>(wte, wte_hi, wte_lo, V_*C_);
    }

    // 3. Transformer layers
    const dim3 g_qkvd(3*C_/128, M_/128);
    const dim3 g_cc  (C_/128,   M_/128);
    const dim3 g_fc  (4*C_/128, M_/128);
    const dim3 g_sc  (T_/32, T_/32, B_*H_);
    const dim3 g_av  (T_/32, B_*H_);

    for (int l = 0; l < L_; l++) {
        size_t wa = (size_t)l*3*C_*C_, wp = (size_t)l*C_*C_, wf = (size_t)l*4*C_*C_;
        ln_kernel<<<M_, 256>>>(x, ln1g + (size_t)l*C_, ln1b + (size_t)l*C_, h_hi, h_lo);
        mma_gemm<0,false><<<g_qkvd, 256, GEMM_SMEM>>>(h_hi, h_lo, wa_hi + wa, wa_lo + wa,
                                                      attnb + (size_t)l*3*C_, nullptr,
                                                      qkv, nullptr, nullptr, 3*C_, C_);
        attn_score_kernel<<<g_sc, 256>>>(qkv, bias, att);
        softmax_kernel<<<B_*H_*T_, 256>>>(att);
        attn_av_kernel<<<g_av, 256>>>(qkv, att, y_hi, y_lo);
        mma_gemm<0,false><<<g_cc, 256, GEMM_SMEM>>>(y_hi, y_lo, wp_hi + wp, wp_lo + wp,
                                                    projb + (size_t)l*C_, x,
                                                    x, nullptr, nullptr, C_, C_);
        ln_kernel<<<M_, 256>>>(x, ln2g + (size_t)l*C_, ln2b + (size_t)l*C_, h_hi, h_lo);
        mma_gemm<1,true><<<g_fc, 256, GEMM_SMEM>>>(h_hi, h_lo, wf_hi + wf, wf_lo + wf,
                                                   fcb + (size_t)l*4*C_, nullptr,
                                                   nullptr, mlp_hi, mlp_lo, 4*C_, C_);
        mma_gemm<0,false><<<g_cc, 256, GEMM_SMEM>>>(mlp_hi, mlp_lo, wf2_hi + wf, wf2_lo + wf,
                                                    fc2b + (size_t)l*C_, x,
                                                    x, nullptr, nullptr, C_, 4*C_);
    }

    // 4. Final LN + tied LM head
    ln_kernel<<<M_, 256>>>(x, lnfg, lnfb, h_hi, h_lo);
    const dim3 g_lm((V_ + 127)/128, M_/128);
    mma_gemm<0,false><<<g_lm, 256, GEMM_SMEM>>>(h_hi, h_lo, wte_hi, wte_lo,
                                                nullptr, nullptr,
                                                (float*)d_out, nullptr, nullptr, V_, C_);
}

// round 7
// speedup vs baseline: 5.1397x; 1.6436x over previous
#include <cuda_runtime.h>
#include <cuda_bf16.h>
#include <math.h>
#include <stdint.h>

// Problem constants
#define L_ 12
#define H_ 12
#define C_ 768
#define V_ 50257
#define B_ 2
#define T_ 1024
#define D_ 64
#define M_ (B_*T_)   // 2048 rows

typedef __nv_bfloat16 bf16;

// ---------------------------------------------------------------------------
// Scratch (static device globals)
// ---------------------------------------------------------------------------
__device__ float g_bias[T_*T_];
__device__ float g_x   [M_*C_];

__device__ bf16 g_h_hi [M_*C_],    g_h_lo [M_*C_];
__device__ bf16 g_qkvh [M_*3*C_],  g_qkvl [M_*3*C_];
__device__ bf16 g_y_hi [M_*C_],    g_y_lo [M_*C_];
__device__ bf16 g_mlp_hi[M_*4*C_], g_mlp_lo[M_*4*C_];

__device__ bf16 g_wa_hi [L_*3*C_*C_], g_wa_lo [L_*3*C_*C_];
__device__ bf16 g_wp_hi [L_*C_*C_],   g_wp_lo [L_*C_*C_];
__device__ bf16 g_wf_hi [L_*4*C_*C_], g_wf_lo [L_*4*C_*C_];
__device__ bf16 g_wf2_hi[L_*C_*4*C_], g_wf2_lo[L_*C_*4*C_];
__device__ bf16 g_wte_hi[(size_t)V_*C_], g_wte_lo[(size_t)V_*C_];

// ---------------------------------------------------------------------------
// Helpers
// ---------------------------------------------------------------------------
__device__ __forceinline__ uint32_t smem_u32(const void* p){
    uint32_t a;
    asm("{ .reg .u64 t; cvta.to.shared.u64 t, %1; cvt.u32.u64 %0, t; }":"=r"(a):"l"(p));
    return a;
}
__device__ __forceinline__ void bsplit(float v, bf16& h, bf16& l){
    h = __float2bfloat16(v);
    l = __float2bfloat16(v - __bfloat162float(h));
}
__device__ __forceinline__ void cpa16(uint32_t saddr, const void* gptr){
    asm volatile("cp.async.cg.shared.global [%0], [%1], 16;"::"r"(saddr),"l"(gptr));
}
__device__ __forceinline__ void cpa16z(uint32_t saddr, const void* gptr, int ssz){
    asm volatile("cp.async.cg.shared.global [%0], [%1], 16, %2;"::"r"(saddr),"l"(gptr),"r"(ssz));
}
__device__ __forceinline__ void ldsm4(uint32_t* r, uint32_t addr){
    asm volatile("ldmatrix.sync.aligned.m8n8.x4.shared.b16 {%0,%1,%2,%3}, [%4];"
      : "=r"(r[0]),"=r"(r[1]),"=r"(r[2]),"=r"(r[3]) : "r"(addr));
}
__device__ __forceinline__ void ldsm4t(uint32_t* r, uint32_t addr){
    asm volatile("ldmatrix.sync.aligned.m8n8.x4.trans.shared.b16 {%0,%1,%2,%3}, [%4];"
      : "=r"(r[0]),"=r"(r[1]),"=r"(r[2]),"=r"(r[3]) : "r"(addr));
}
__device__ __forceinline__ void mma16(float* d, const uint32_t* a, uint32_t b0, uint32_t b1){
    asm volatile("mma.sync.aligned.m16n8k16.row.col.f32.bf16.bf16.f32 "
      "{%0,%1,%2,%3}, {%4,%5,%6,%7}, {%8,%9}, {%0,%1,%2,%3};"
      : "+f"(d[0]),"+f"(d[1]),"+f"(d[2]),"+f"(d[3])
      : "r"(a[0]),"r"(a[1]),"r"(a[2]),"r"(a[3]),"r"(b0),"r"(b1));
}
__device__ __forceinline__ float exp2a(float x){
    float y; asm("ex2.approx.ftz.f32 %0, %1;":"=f"(y):"f"(x)); return y;
}
// pack two f32 -> bf16x2 (lower = c0), and residual pack
__device__ __forceinline__ uint32_t packsplit(float c0, float c1, uint32_t& lo){
    uint32_t hi;
    asm("cvt.rn.bf16x2.f32 %0, %1, %2;" : "=r"(hi) : "f"(c1), "f"(c0));
    float h0 = __uint_as_float(hi << 16);
    float h1 = __uint_as_float(hi & 0xffff0000u);
    asm("cvt.rn.bf16x2.f32 %0, %1, %2;" : "=r"(lo) : "f"(c1 - h1), "f"(c0 - h0));
    return hi;
}
#define SWZ(o) ((o) ^ (((o)>>3)&0x70))

// ---------------------------------------------------------------------------
// BF16 3x-split GEMM via mma.m16n8k16, cp.async double-buffered.
// ---------------------------------------------------------------------------
#define GEMM_SMEM (131072 + 1024)

template<int ACT, bool OUTBF>
__global__ void __launch_bounds__(256) mma_gemm(
    const bf16* __restrict__ Ahi, const bf16* __restrict__ Alo,
    const bf16* __restrict__ Bhi, const bf16* __restrict__ Blo,
    const float* __restrict__ bias, const float* __restrict__ resid,
    float* __restrict__ Cf, bf16* __restrict__ Chi, bf16* __restrict__ Clo,
    int Nn, int Kk)
{
    extern __shared__ char ds[];
    const uint32_t sb = (smem_u32(ds) + 1023) & ~1023u;

    const int tid = threadIdx.x, lane = tid & 31, wid = tid >> 5;
    const int bm = blockIdx.y * 128, bn = blockIdx.x * 128;
    const int NT = Kk >> 6;

    auto cp_stage = [&](int t){
        const uint32_t base = sb + (uint32_t)(t & 1) * 65536;
        const int k0 = t << 6;
        #pragma unroll
        for (int i = 0; i < 4; i++){
            int idx = tid + i*256;
            int r = idx >> 3, c = idx & 7;
            uint32_t off = SWZ((uint32_t)(r*128 + c*16));
            size_t ka = (size_t)(bm + r) * Kk + k0 + c*8;
            cpa16(base + off,         Ahi + ka);
            cpa16(base + 16384 + off, Alo + ka);
            int gn = bn + r;
            size_t kb = (size_t)gn * Kk + k0 + c*8;
            int ssz = (gn < Nn) ? 16 : 0;
            cpa16z(base + 32768 + off, Bhi + kb, ssz);
            cpa16z(base + 49152 + off, Blo + kb, ssz);
        }
        asm volatile("cp.async.commit_group;":::"memory");
    };

    float acc[2][8][4];
    #pragma unroll
    for (int a=0;a<2;a++) for (int b=0;b<8;b++) for (int c=0;c<4;c++) acc[a][b][c]=0.f;

    const int m0 = (wid >> 1) * 32, n0 = (wid & 1) * 64;
    const uint32_t arow = (uint32_t)(m0 + (lane & 15));
    const uint32_t acol = (uint32_t)((lane >> 4) * 16);
    const uint32_t brow = (uint32_t)(n0 + (lane & 7) + ((lane >> 4) & 1) * 8);
    const uint32_t bcol = (uint32_t)(((lane >> 3) & 1) * 16);

    auto compute = [&](int t){
        const uint32_t base = sb + (uint32_t)(t & 1) * 65536;
        #pragma unroll
        for (int ks = 0; ks < 4; ks++){
            const uint32_t kb2 = (uint32_t)(ks * 32);
            uint32_t ah[2][4], al[2][4];
            #pragma unroll
            for (int mt = 0; mt < 2; mt++){
                uint32_t off = SWZ((arow + mt*16)*128 + kb2 + acol);
                ldsm4(ah[mt], base + off);
                ldsm4(al[mt], base + 16384 + off);
            }
            #pragma unroll
            for (int g = 0; g < 4; g++){
                uint32_t off = SWZ((brow + g*16)*128 + kb2 + bcol);
                uint32_t bh[4], bl[4];
                ldsm4(bh, base + 32768 + off);
                ldsm4(bl, base + 49152 + off);
                #pragma unroll
                for (int mt = 0; mt < 2; mt++){
                    #pragma unroll
                    for (int sub = 0; sub < 2; sub++){
                        float* d = acc[mt][g*2 + sub];
                        mma16(d, ah[mt], bh[sub*2], bh[sub*2+1]);
                        mma16(d, ah[mt], bl[sub*2], bl[sub*2+1]);
                        mma16(d, al[mt], bh[sub*2], bh[sub*2+1]);
                    }
                }
            }
        }
    };

    cp_stage(0);
    if (NT > 1) cp_stage(1);
    for (int t = 0; t < NT; t++){
        if (t + 1 < NT) asm volatile("cp.async.wait_group 1;":::"memory");
        else            asm volatile("cp.async.wait_group 0;":::"memory");
        __syncthreads();
        compute(t);
        __syncthreads();
        if (t + 2 < NT) cp_stage(t + 2);
    }

    #pragma unroll
    for (int mt = 0; mt < 2; mt++){
        #pragma unroll
        for (int h2 = 0; h2 < 2; h2++){
            int row = bm + m0 + mt*16 + (lane>>2) + h2*8;
            float* crow = OUTBF ? nullptr : (Cf + (size_t)row * Nn);
            const float* rrow = resid ? resid + (size_t)row * Nn : nullptr;
            #pragma unroll
            for (int nt = 0; nt < 8; nt++){
                int col = bn + n0 + nt*8 + (lane&3)*2;
                if (col >= Nn) continue;
                float v0 = acc[mt][nt][h2*2+0];
                float v1 = acc[mt][nt][h2*2+1];
                bool has1 = (col + 1 < Nn);
                if (bias){ v0 += bias[col]; if (has1) v1 += bias[col+1]; }
                if (ACT == 1){
                    float x3 = v0*v0*v0;
                    v0 = 0.5f*v0*(1.f + tanhf(0.7978845608028654f*(v0 + 0.044715f*x3)));
                    x3 = v1*v1*v1;
                    v1 = 0.5f*v1*(1.f + tanhf(0.7978845608028654f*(v1 + 0.044715f*x3)));
                }
                if (rrow){ v0 += rrow[col]; if (has1) v1 += rrow[col+1]; }
                if (OUTBF){
                    size_t o = (size_t)row * Nn + col;
                    bf16 bh, bl;
                    bsplit(v0, bh, bl); Chi[o] = bh; Clo[o] = bl;
                    if (has1){ bsplit(v1, bh, bl); Chi[o+1] = bh; Clo[o+1] = bl; }
                } else if (((Nn & 1) == 0) && has1){
                    float2 st; st.x = v0; st.y = v1;
                    *reinterpret_cast<float2*>(crow + col) = st;
                } else {
                    crow[col] = v0;
                    if (has1) crow[col + 1] = v1;
                }
            }
        }
    }
}

// ---------------------------------------------------------------------------
// FlashAttention: one block = 128 q-rows x one (b,h).
// smem: Qh,Ql 32K | K 2stages hi/lo 64K | V 2stages hi/lo 64K = 160K
// ---------------------------------------------------------------------------
#define FLASH_SMEM (163840 + 1024)

__global__ void __launch_bounds__(256) flash_kernel(
    const bf16* __restrict__ qkvh, const bf16* __restrict__ qkvl,
    const float* __restrict__ bias2,
    bf16* __restrict__ yhi, bf16* __restrict__ ylo)
{
    extern __shared__ char ds[];
    const uint32_t sb = (smem_u32(ds) + 1023) & ~1023u;
    const uint32_t sQh = sb, sQl = sb + 16384;

    const int tid = threadIdx.x, lane = tid & 31, w = tid >> 5;
    const int bh = blockIdx.y, b = bh / H_, h = bh % H_;
    const int i0 = (int)(gridDim.x - 1 - blockIdx.x) * 128;
    const int nj = (i0 >> 7) + 1;

    const bf16* qh = qkvh + (size_t)b * T_ * 3 * C_ + h * D_;
    const bf16* ql = qkvl + (size_t)b * T_ * 3 * C_ + h * D_;
    const bf16* kh = qh + C_,   * kl = ql + C_;
    const bf16* vh = qh + 2*C_, * vl = ql + 2*C_;

    auto cp_q = [&](){
        #pragma unroll
        for (int i = 0; i < 4; i++){
            int idx = tid + i*256;
            int r = idx >> 3, c = idx & 7;
            uint32_t off = SWZ((uint32_t)(r*128 + c*16));
            size_t g = (size_t)(i0 + r) * 3 * C_ + c*8;
            cpa16(sQh + off, qh + g);
            cpa16(sQl + off, ql + g);
        }
    };
    auto cp_kv = [&](int jt){
        int st = jt & 1, j0 = jt << 7;
        uint32_t kb = sb + 32768 + (uint32_t)st * 32768;
        uint32_t vb = sb + 98304 + (uint32_t)st * 32768;
        #pragma unroll
        for (int i = 0; i < 4; i++){
            int idx = tid + i*256;
            int r = idx >> 3, c = idx & 7;
            uint32_t off = SWZ((uint32_t)(r*128 + c*16));
            size_t g = (size_t)(j0 + r) * 3 * C_ + c*8;
            cpa16(kb + off,         kh + g);
            cpa16(kb + 16384 + off, kl + g);
            cpa16(vb + off,         vh + g);
            cpa16(vb + 16384 + off, vl + g);
        }
        asm volatile("cp.async.commit_group;":::"memory");
    };

    cp_q(); cp_kv(0);
    if (nj > 1) cp_kv(1);
    if (nj > 1) asm volatile("cp.async.wait_group 1;":::"memory");
    else        asm volatile("cp.async.wait_group 0;":::"memory");
    __syncthreads();

    // cache Q fragments
    uint32_t qfh[4][4], qfl[4][4];
    {
        uint32_t arow = (uint32_t)(w*16 + (lane & 15));
        uint32_t acol = (uint32_t)((lane >> 4) * 16);
        #pragma unroll
        for (int kt = 0; kt < 4; kt++){
            uint32_t off = SWZ(arow*128 + (uint32_t)kt*32 + acol);
            ldsm4(qfh[kt], sQh + off);
            ldsm4(qfl[kt], sQl + off);
        }
    }

    float O[8][4];
    #pragma unroll
    for (int i=0;i<8;i++) for (int j=0;j<4;j++) O[i][j]=0.f;
    float mr0 = -INFINITY, mr1 = -INFINITY, l0 = 0.f, l1 = 0.f;

    const float SC = 0.125f * 1.4426950408889634f;
    const uint32_t brow = (uint32_t)((lane & 7) + ((lane >> 4) & 1) * 8);
    const uint32_t bcol = (uint32_t)(((lane >> 3) & 1) * 16);
    const uint32_t vrow = (uint32_t)((lane & 7) + ((lane >> 3) & 1) * 8);
    const uint32_t vcol = (uint32_t)((lane >> 4) * 16);

    for (int jt = 0; jt < nj; jt++){
        const int st = jt & 1, j0 = jt << 7;
        const uint32_t kb = sb + 32768 + (uint32_t)st * 32768;
        const uint32_t vb = sb + 98304 + (uint32_t)st * 32768;

        // --- S = Q K^T (3x split) ---
        float S[16][4];
        #pragma unroll
        for (int i=0;i<16;i++) for (int j=0;j<4;j++) S[i][j]=0.f;
        #pragma unroll
        for (int kt = 0; kt < 4; kt++){
            const uint32_t kb2 = (uint32_t)kt * 32;
            #pragma unroll
            for (int g = 0; g < 8; g++){
                uint32_t off = SWZ((brow + g*16)*128 + kb2 + bcol);
                uint32_t kh4[4], kl4[4];
                ldsm4(kh4, kb + off);
                ldsm4(kl4, kb + 16384 + off);
                #pragma unroll
                for (int sub = 0; sub < 2; sub++){
                    float* d = S[g*2 + sub];
                    mma16(d, qfh[kt], kh4[sub*2], kh4[sub*2+1]);
                    mma16(d, qfh[kt], kl4[sub*2], kl4[sub*2+1]);
                    mma16(d, qfl[kt], kh4[sub*2], kh4[sub*2+1]);
                }
            }
        }

        // --- scale + bias (log2 domain; bias2 includes -1e30 mask) ---
        {
            int gi = i0 + w*16 + (lane >> 2);
            int gjb = j0 + (lane & 3) * 2;
            const float* b0 = bias2 + (size_t)gi * T_ + gjb;
            const float* b1 = bias2 + (size_t)(gi + 8) * T_ + gjb;
            #pragma unroll
            for (int nt = 0; nt < 16; nt++){
                float2 ba = *reinterpret_cast<const float2*>(b0 + nt*8);
                float2 bb = *reinterpret_cast<const float2*>(b1 + nt*8);
                S[nt][0] = S[nt][0]*SC + ba.x;
                S[nt][1] = S[nt][1]*SC + ba.y;
                S[nt][2] = S[nt][2]*SC + bb.x;
                S[nt][3] = S[nt][3]*SC + bb.y;
            }
        }

        // --- online softmax ---
        float mn0 = mr0, mn1 = mr1;
        #pragma unroll
        for (int nt = 0; nt < 16; nt++){
            mn0 = fmaxf(mn0, fmaxf(S[nt][0], S[nt][1]));
            mn1 = fmaxf(mn1, fmaxf(S[nt][2], S[nt][3]));
        }
        mn0 = fmaxf(mn0, __shfl_xor_sync(0xffffffffu, mn0, 1));
        mn0 = fmaxf(mn0, __shfl_xor_sync(0xffffffffu, mn0, 2));
        mn1 = fmaxf(mn1, __shfl_xor_sync(0xffffffffu, mn1, 1));
        mn1 = fmaxf(mn1, __shfl_xor_sync(0xffffffffu, mn1, 2));
        float sc0 = exp2a(mr0 - mn0), sc1 = exp2a(mr1 - mn1);
        mr0 = mn0; mr1 = mn1;
        float rs0 = 0.f, rs1 = 0.f;
        #pragma unroll
        for (int nt = 0; nt < 16; nt++){
            S[nt][0] = exp2a(S[nt][0] - mn0);
            S[nt][1] = exp2a(S[nt][1] - mn0);
            S[nt][2] = exp2a(S[nt][2] - mn1);
            S[nt][3] = exp2a(S[nt][3] - mn1);
            rs0 += S[nt][0] + S[nt][1];
            rs1 += S[nt][2] + S[nt][3];
        }
        rs0 += __shfl_xor_sync(0xffffffffu, rs0, 1);
        rs0 += __shfl_xor_sync(0xffffffffu, rs0, 2);
        rs1 += __shfl_xor_sync(0xffffffffu, rs1, 1);
        rs1 += __shfl_xor_sync(0xffffffffu, rs1, 2);
        l0 = l0 * sc0 + rs0;
        l1 = l1 * sc1 + rs1;
        #pragma unroll
        for (int nt = 0; nt < 8; nt++){
            O[nt][0] *= sc0; O[nt][1] *= sc0;
            O[nt][2] *= sc1; O[nt][3] *= sc1;
        }

        // --- O += P V (3x split); dv covers ALL 64 head dims (4 x 16) ---
        #pragma unroll
        for (int g = 0; g < 8; g++){
            uint32_t pah[4], pal[4];
            pah[0] = packsplit(S[2*g  ][0], S[2*g  ][1], pal[0]);
            pah[1] = packsplit(S[2*g  ][2], S[2*g  ][3], pal[1]);
            pah[2] = packsplit(S[2*g+1][0], S[2*g+1][1], pal[2]);
            pah[3] = packsplit(S[2*g+1][2], S[2*g+1][3], pal[3]);
            #pragma unroll
            for (int dv = 0; dv < 4; dv++){
                uint32_t off = SWZ((vrow + g*16)*128 + (uint32_t)dv*32 + vcol);
                uint32_t vh4[4], vl4[4];
                ldsm4t(vh4, vb + off);
                ldsm4t(vl4, vb + 16384 + off);
                #pragma unroll
                for (int sub = 0; sub < 2; sub++){
                    float* d = O[dv*2 + sub];
                    mma16(d, pah, vh4[sub*2], vh4[sub*2+1]);
                    mma16(d, pah, vl4[sub*2], vl4[sub*2+1]);
                    mma16(d, pal, vh4[sub*2], vh4[sub*2+1]);
                }
            }
        }

        __syncthreads();
        if (jt + 2 < nj) cp_kv(jt + 2);
        if (jt + 1 < nj){
            if (jt + 2 < nj) asm volatile("cp.async.wait_group 1;":::"memory");
            else             asm volatile("cp.async.wait_group 0;":::"memory");
            __syncthreads();
        }
    }

    // --- epilogue: normalize, write y planes ---
    float li0 = 1.f / l0, li1 = 1.f / l1;
    int r0 = i0 + w*16 + (lane >> 2);
    size_t base0 = (size_t)b * T_ * C_ + (size_t)r0 * C_ + h * D_;
    size_t base1 = base0 + (size_t)8 * C_;
    #pragma unroll
    for (int nt = 0; nt < 8; nt++){
        int col = nt*8 + (lane & 3)*2;
        bf16 hh, ll;
        bsplit(O[nt][0]*li0, hh, ll); yhi[base0+col  ] = hh; ylo[base0+col  ] = ll;
        bsplit(O[nt][1]*li0, hh, ll); yhi[base0+col+1] = hh; ylo[base0+col+1] = ll;
        bsplit(O[nt][2]*li1, hh, ll); yhi[base1+col  ] = hh; ylo[base1+col  ] = ll;
        bsplit(O[nt][3]*li1, hh, ll); yhi[base1+col+1] = hh; ylo[base1+col+1] = ll;
    }
}

// ---------------------------------------------------------------------------
// Weight prep
// ---------------------------------------------------------------------------
__global__ void wsplit_t_kernel(const float* __restrict__ in,
                                bf16* __restrict__ ohi, bf16* __restrict__ olo,
                                int K, int N){
    __shared__ float t[32][33];
    size_t lb = (size_t)blockIdx.z * K * N;
    const float* inp = in + lb;
    int kb = blockIdx.y*32, nb = blockIdx.x*32;
    int tx = threadIdx.x, ty = threadIdx.y;
    #pragma unroll
    for (int j = 0; j < 4; j++)
        t[ty + 8*j][tx] = inp[(size_t)(kb + ty + 8*j) * N + nb + tx];
    __syncthreads();
    #pragma unroll
    for (int j = 0; j < 4; j++){
        int n = nb + ty + 8*j, k = kb + tx;
        float v = t[tx][ty + 8*j];
        bf16 h, l; bsplit(v, h, l);
        size_t o = lb + (size_t)n * K + k;
        ohi[o] = h; olo[o] = l;
    }
}

__global__ void split_kernel(const float* __restrict__ in,
                             bf16* __restrict__ ohi, bf16* __restrict__ olo, int n){
    int i = blockIdx.x * 256 + threadIdx.x;
    if (i < n){
        bf16 h, l; bsplit(in[i], h, l);
        ohi[i] = h; olo[i] = l;
    }
}

// ---------------------------------------------------------------------------
// Block reductions
// ---------------------------------------------------------------------------
__device__ __forceinline__ float block_reduce_sum(float v) {
    __shared__ float sh[32];
    __syncthreads();
    int lane = threadIdx.x & 31, wid = threadIdx.x >> 5;
    #pragma unroll
    for (int o = 16; o > 0; o >>= 1) v += __shfl_down_sync(0xffffffffu, v, o);
    if (lane == 0) sh[wid] = v;
    __syncthreads();
    v = (threadIdx.x < (blockDim.x >> 5)) ? sh[lane] : 0.f;
    if (wid == 0) {
        #pragma unroll
        for (int o = 16; o > 0; o >>= 1) v += __shfl_down_sync(0xffffffffu, v, o);
        if (lane == 0) sh[0] = v;
    }
    __syncthreads();
    return sh[0];
}

// ---------------------------------------------------------------------------
// FIRE bias (pre-scaled by log2e for the flash kernel's exp2 softmax)
// ---------------------------------------------------------------------------
__global__ void fire_bias_kernel(const float* __restrict__ log_c,
                                 const float* __restrict__ v1w, const float* __restrict__ v1b,
                                 const float* __restrict__ v2w, const float* __restrict__ v2b,
                                 const float* __restrict__ v3w, const float* __restrict__ v3b,
                                 float* __restrict__ bias) {
    __shared__ float s1w[32], s1b[32], s2w[1024], s2b[32], s3w[32];
    __shared__ float s3b, sc;
    int tid = threadIdx.x;
    if (tid < 32) { s1w[tid] = v1w[tid]; s1b[tid] = v1b[tid]; s2b[tid] = v2b[tid]; s3w[tid] = v3w[tid]; }
    for (int i = tid; i < 1024; i += blockDim.x) s2w[i] = v2w[i];
    if (tid == 0) { s3b = v3b[0]; sc = expf(log_c[0]); }
    __syncthreads();

    int idx = blockIdx.x * blockDim.x + tid;
    if (idx >= T_*T_) return;
    int i = idx / T_, j = idx % T_;
    if (j > i) { bias[idx] = -1e30f; return; }

    float c = sc;
    float fi = (float)(i + 1), fj = (float)(j + 1);
    float pv = logf(c * (fi - fj) + 1.0f) / logf(c * fi + 1.0f);

    float h1[32];
    #pragma unroll
    for (int k = 0; k < 32; k++) h1[k] = fmaxf(pv * s1w[k] + s1b[k], 0.f);
    float out = s3b;
    #pragma unroll
    for (int k2 = 0; k2 < 32; k2++) {
        float a = s2b[k2];
        #pragma unroll
        for (int k1 = 0; k1 < 32; k1++) a += h1[k1] * s2w[k1*32 + k2];
        out += fmaxf(a, 0.f) * s3w[k2];
    }
    bias[idx] = out * 1.4426950408889634f;
}

// ---------------------------------------------------------------------------
// Embedding gather
// ---------------------------------------------------------------------------
__global__ void embed_kernel(const int* __restrict__ idx, const float* __restrict__ wte,
                             float* __restrict__ x) {
    int row = blockIdx.x;
    const float* src = wte + (size_t)idx[row] * C_;
    float* dst = x + (size_t)row * C_;
    for (int c = threadIdx.x; c < C_; c += blockDim.x) dst[c] = src[c];
}

// ---------------------------------------------------------------------------
// LayerNorm -> bf16 hi/lo planes
// ---------------------------------------------------------------------------
__global__ void ln_kernel(const float* __restrict__ x, const float* __restrict__ g,
                          const float* __restrict__ b,
                          bf16* __restrict__ ohi, bf16* __restrict__ olo) {
    int row = blockIdx.x;
    const float* xr = x + (size_t)row * C_;
    float v0 = xr[threadIdx.x], v1 = xr[threadIdx.x + 256], v2 = xr[threadIdx.x + 512];
    float s = block_reduce_sum(v0 + v1 + v2);
    float mean = s * (1.0f / C_);
    float d0 = v0 - mean, d1 = v1 - mean, d2 = v2 - mean;
    float s2 = block_reduce_sum(d0*d0 + d1*d1 + d2*d2);
    float rs = rsqrtf(s2 * (1.0f / C_) + 1e-5f);
    size_t base = (size_t)row * C_;
    int c = threadIdx.x;
    bf16 h, l;
    bsplit(d0 * rs * g[c      ] + b[c      ], h, l); ohi[base + c      ] = h; olo[base + c      ] = l;
    bsplit(d1 * rs * g[c + 256] + b[c + 256], h, l); ohi[base + c + 256] = h; olo[base + c + 256] = l;
    bsplit(d2 * rs * g[c + 512] + b[c + 512], h, l); ohi[base + c + 512] = h; olo[base + c + 512] = l;
}

// ---------------------------------------------------------------------------
// Launch
// ---------------------------------------------------------------------------
extern "C" void kernel_launch(void* const* d_in, const int* in_sizes, int n_in,
                              void* d_out, int out_size) {
    int o = (n_in >= 2 && in_sizes[1] == 1) ? 1 : 0;

    const int*   idx   = (const int*)  d_in[0];
    const float* wte   = (const float*)d_in[1 + o];
    const float* log_c = (const float*)d_in[2 + o];
    const float* v1w   = (const float*)d_in[3 + o];
    const float* v1b   = (const float*)d_in[4 + o];
    const float* v2w   = (const float*)d_in[5 + o];
    const float* v2b   = (const float*)d_in[6 + o];
    const float* v3w   = (const float*)d_in[7 + o];
    const float* v3b   = (const float*)d_in[8 + o];
    const float* ln1g  = (const float*)d_in[9 + o];
    const float* ln1b  = (const float*)d_in[10 + o];
    const float* attnw = (const float*)d_in[11 + o];
    const float* attnb = (const float*)d_in[12 + o];
    const float* projw = (const float*)d_in[13 + o];
    const float* projb = (const float*)d_in[14 + o];
    const float* ln2g  = (const float*)d_in[15 + o];
    const float* ln2b  = (const float*)d_in[16 + o];
    const float* fcw   = (const float*)d_in[17 + o];
    const float* fcb   = (const float*)d_in[18 + o];
    const float* fc2w  = (const float*)d_in[19 + o];
    const float* fc2b  = (const float*)d_in[20 + o];
    const float* lnfg  = (const float*)d_in[21 + o];
    const float* lnfb  = (const float*)d_in[22 + o];

    float *bias, *x;
    bf16 *h_hi, *h_lo, *qkvh, *qkvl, *y_hi, *y_lo, *mlp_hi, *mlp_lo;
    bf16 *wa_hi, *wa_lo, *wp_hi, *wp_lo, *wf_hi, *wf_lo, *wf2_hi, *wf2_lo, *wte_hi, *wte_lo;
    cudaGetSymbolAddress((void**)&bias,   g_bias);
    cudaGetSymbolAddress((void**)&x,      g_x);
    cudaGetSymbolAddress((void**)&h_hi,   g_h_hi);   cudaGetSymbolAddress((void**)&h_lo,   g_h_lo);
    cudaGetSymbolAddress((void**)&qkvh,   g_qkvh);   cudaGetSymbolAddress((void**)&qkvl,   g_qkvl);
    cudaGetSymbolAddress((void**)&y_hi,   g_y_hi);   cudaGetSymbolAddress((void**)&y_lo,   g_y_lo);
    cudaGetSymbolAddress((void**)&mlp_hi, g_mlp_hi); cudaGetSymbolAddress((void**)&mlp_lo, g_mlp_lo);
    cudaGetSymbolAddress((void**)&wa_hi,  g_wa_hi);  cudaGetSymbolAddress((void**)&wa_lo,  g_wa_lo);
    cudaGetSymbolAddress((void**)&wp_hi,  g_wp_hi);  cudaGetSymbolAddress((void**)&wp_lo,  g_wp_lo);
    cudaGetSymbolAddress((void**)&wf_hi,  g_wf_hi);  cudaGetSymbolAddress((void**)&wf_lo,  g_wf_lo);
    cudaGetSymbolAddress((void**)&wf2_hi, g_wf2_hi); cudaGetSymbolAddress((void**)&wf2_lo, g_wf2_lo);
    cudaGetSymbolAddress((void**)&wte_hi, g_wte_hi); cudaGetSymbolAddress((void**)&wte_lo, g_wte_lo);

    cudaFuncSetAttribute(mma_gemm<0,false>, cudaFuncAttributeMaxDynamicSharedMemorySize, GEMM_SMEM);
    cudaFuncSetAttribute(mma_gemm<1,true>,  cudaFuncAttributeMaxDynamicSharedMemorySize, GEMM_SMEM);
    cudaFuncSetAttribute(mma_gemm<0,true>,  cudaFuncAttributeMaxDynamicSharedMemorySize, GEMM_SMEM);
    cudaFuncSetAttribute(flash_kernel,      cudaFuncAttributeMaxDynamicSharedMemorySize, FLASH_SMEM);

    // 1. FIRE bias + embedding + weight prep
    fire_bias_kernel<<<(T_*T_ + 255) / 256, 256>>>(log_c, v1w, v1b, v2w, v2b, v3w, v3b, bias);
    embed_kernel<<<M_, 256>>>(idx, wte, x);
    {
        dim3 tb(32, 8);
        wsplit_t_kernel<<<dim3(3*C_/32,  C_/32,  L_), tb>>>(attnw, wa_hi,  wa_lo,  C_,   3*C_);
        wsplit_t_kernel<<<dim3(C_/32,    C_/32,  L_), tb>>>(projw, wp_hi,  wp_lo,  C_,   C_);
        wsplit_t_kernel<<<dim3(4*C_/32,  C_/32,  L_), tb>>>(fcw,   wf_hi,  wf_lo,  C_,   4*C_);
        wsplit_t_kernel<<<dim3(C_/32,  4*C_/32,  L_), tb>>>(fc2w,  wf2_hi, wf2_lo, 4*C_, C_);
        split_kernel<<<(V_*C_ + 255)/256, 256>>>(wte, wte_hi, wte_lo, V_*C_);
    }

    // 2. Transformer layers
    const dim3 g_qkvd(3*C_/128, M_/128);
    const dim3 g_cc  (C_/128,   M_/128);
    const dim3 g_fc  (4*C_/128, M_/128);
    const dim3 g_fl  (T_/128, B_*H_);

    for (int l = 0; l < L_; l++) {
        size_t wa = (size_t)l*3*C_*C_, wp = (size_t)l*C_*C_, wf = (size_t)l*4*C_*C_;
        ln_kernel<<<M_, 256>>>(x, ln1g + (size_t)l*C_, ln1b + (size_t)l*C_, h_hi, h_lo);
        mma_gemm<0,true><<<g_qkvd, 256, GEMM_SMEM>>>(h_hi, h_lo, wa_hi + wa, wa_lo + wa,
                                                     attnb + (size_t)l*3*C_, nullptr,
                                                     nullptr, qkvh, qkvl, 3*C_, C_);
        flash_kernel<<<g_fl, 256, FLASH_SMEM>>>(qkvh, qkvl, bias, y_hi, y_lo);
        mma_gemm<0,false><<<g_cc, 256, GEMM_SMEM>>>(y_hi, y_lo, wp_hi + wp, wp_lo + wp,
                                                    projb + (size_t)l*C_, x,
                                                    x, nullptr, nullptr, C_, C_);
        ln_kernel<<<M_, 256>>>(x, ln2g + (size_t)l*C_, ln2b + (size_t)l*C_, h_hi, h_lo);
        mma_gemm<1,true><<<g_fc, 256, GEMM_SMEM>>>(h_hi, h_lo, wf_hi + wf, wf_lo + wf,
                                                   fcb + (size_t)l*4*C_, nullptr,
                                                   nullptr, mlp_hi, mlp_lo, 4*C_, C_);
        mma_gemm<0,false><<<g_cc, 256, GEMM_SMEM>>>(mlp_hi, mlp_lo, wf2_hi + wf, wf2_lo + wf,
                                                    fc2b + (size_t)l*C_, x,
                                                    x, nullptr, nullptr, C_, 4*C_);
    }

    // 3. Final LN + tied LM head
    ln_kernel<<<M_, 256>>>(x, lnfg, lnfb, h_hi, h_lo);
    const dim3 g_lm((V_ + 127)/128, M_/128);
    mma_gemm<0,false><<<g_lm, 256, GEMM_SMEM>>>(h_hi, h_lo, wte_hi, wte_lo,
                                                nullptr, nullptr,
                                                (float*)d_out, nullptr, nullptr, V_, C_);
}

// round 8
// speedup vs baseline: 5.7253x; 1.1139x over previous
#include <cuda_runtime.h>
#include <cuda_bf16.h>
#include <math.h>
#include <stdint.h>

// Problem constants
#define L_ 12
#define H_ 12
#define C_ 768
#define V_ 50257
#define B_ 2
#define T_ 1024
#define D_ 64
#define M_ (B_*T_)   // 2048 rows

typedef __nv_bfloat16 bf16;

// ---------------------------------------------------------------------------
// Scratch (static device globals)
// ---------------------------------------------------------------------------
__device__ float g_bias[T_*T_];
__device__ float g_x   [M_*C_];

__device__ bf16 g_h_hi [M_*C_],    g_h_lo [M_*C_];
__device__ bf16 g_qkvh [M_*3*C_],  g_qkvl [M_*3*C_];
__device__ bf16 g_y_hi [M_*C_],    g_y_lo [M_*C_];
__device__ bf16 g_mlp_hi[M_*4*C_], g_mlp_lo[M_*4*C_];

__device__ bf16 g_wa_hi [L_*3*C_*C_], g_wa_lo [L_*3*C_*C_];
__device__ bf16 g_wp_hi [L_*C_*C_],   g_wp_lo [L_*C_*C_];
__device__ bf16 g_wf_hi [L_*4*C_*C_], g_wf_lo [L_*4*C_*C_];
__device__ bf16 g_wf2_hi[L_*C_*4*C_], g_wf2_lo[L_*C_*4*C_];
__device__ bf16 g_wte_hi[(size_t)V_*C_], g_wte_lo[(size_t)V_*C_];

// ---------------------------------------------------------------------------
// Helpers
// ---------------------------------------------------------------------------
__device__ __forceinline__ uint32_t smem_u32(const void* p){
    uint32_t a;
    asm("{ .reg .u64 t; cvta.to.shared.u64 t, %1; cvt.u32.u64 %0, t; }":"=r"(a):"l"(p));
    return a;
}
__device__ __forceinline__ void bsplit(float v, bf16& h, bf16& l){
    h = __float2bfloat16(v);
    l = __float2bfloat16(v - __bfloat162float(h));
}
__device__ __forceinline__ void cpa16(uint32_t saddr, const void* gptr){
    asm volatile("cp.async.cg.shared.global [%0], [%1], 16;"::"r"(saddr),"l"(gptr));
}
__device__ __forceinline__ void cpa16z(uint32_t saddr, const void* gptr, int ssz){
    asm volatile("cp.async.cg.shared.global [%0], [%1], 16, %2;"::"r"(saddr),"l"(gptr),"r"(ssz));
}
__device__ __forceinline__ void ldsm4(uint32_t* r, uint32_t addr){
    asm volatile("ldmatrix.sync.aligned.m8n8.x4.shared.b16 {%0,%1,%2,%3}, [%4];"
      : "=r"(r[0]),"=r"(r[1]),"=r"(r[2]),"=r"(r[3]) : "r"(addr));
}
__device__ __forceinline__ void ldsm4t(uint32_t* r, uint32_t addr){
    asm volatile("ldmatrix.sync.aligned.m8n8.x4.trans.shared.b16 {%0,%1,%2,%3}, [%4];"
      : "=r"(r[0]),"=r"(r[1]),"=r"(r[2]),"=r"(r[3]) : "r"(addr));
}
__device__ __forceinline__ void mma16(float* d, const uint32_t* a, uint32_t b0, uint32_t b1){
    asm volatile("mma.sync.aligned.m16n8k16.row.col.f32.bf16.bf16.f32 "
      "{%0,%1,%2,%3}, {%4,%5,%6,%7}, {%8,%9}, {%0,%1,%2,%3};"
      : "+f"(d[0]),"+f"(d[1]),"+f"(d[2]),"+f"(d[3])
      : "r"(a[0]),"r"(a[1]),"r"(a[2]),"r"(a[3]),"r"(b0),"r"(b1));
}
__device__ __forceinline__ float exp2a(float x){
    float y; asm("ex2.approx.ftz.f32 %0, %1;":"=f"(y):"f"(x)); return y;
}
// pack two f32 -> bf16x2 (lower = c0), and residual pack
__device__ __forceinline__ uint32_t packsplit(float c0, float c1, uint32_t& lo){
    uint32_t hi;
    asm("cvt.rn.bf16x2.f32 %0, %1, %2;" : "=r"(hi) : "f"(c1), "f"(c0));
    float h0 = __uint_as_float(hi << 16);
    float h1 = __uint_as_float(hi & 0xffff0000u);
    asm("cvt.rn.bf16x2.f32 %0, %1, %2;" : "=r"(lo) : "f"(c1 - h1), "f"(c0 - h0));
    return hi;
}
#define SWZ(o) ((o) ^ (((o)>>3)&0x70))

// ---------------------------------------------------------------------------
// BF16 3x-split GEMM via mma.m16n8k16, cp.async multi-stage pipeline.
//   BM_ in {128, 64}; threads = BM_*2; NSTAGE in {2, 3}.
//   3-stage: single __syncthreads per k-tile (cp(t+2) writes a stage not
//   touched by compute(t); all warps passed sync(t) after compute(t-1)).
// ---------------------------------------------------------------------------
template<int ACT, bool OUTBF, int BM_, int NSTAGE>
__global__ void __launch_bounds__(BM_*2) mma_gemm(
    const bf16* __restrict__ Ahi, const bf16* __restrict__ Alo,
    const bf16* __restrict__ Bhi, const bf16* __restrict__ Blo,
    const float* __restrict__ bias, const float* __restrict__ resid,
    float* __restrict__ Cf, bf16* __restrict__ Chi, bf16* __restrict__ Clo,
    int Nn, int Kk)
{
    constexpr int T = BM_ * 2;
    constexpr uint32_t ABYTES = BM_ * 128;            // per A plane
    constexpr uint32_t STAGE  = 2*ABYTES + 32768;     // Ah|Al|Bh|Bl
    constexpr int NBIT = 1024 / T;                    // B cp iterations

    extern __shared__ char ds[];
    const uint32_t sb = (smem_u32(ds) + 1023) & ~1023u;

    const int tid = threadIdx.x, lane = tid & 31, wid = tid >> 5;
    const int bm = blockIdx.y * BM_, bn = blockIdx.x * 128;
    const int NT = Kk >> 6;

    auto cp_stage = [&](int t){
        const uint32_t base = sb + (uint32_t)(t % NSTAGE) * STAGE;
        const int k0 = t << 6;
        #pragma unroll
        for (int i = 0; i < 4; i++){
            int idx = tid + i*T;
            int r = idx >> 3, c = idx & 7;
            uint32_t off = SWZ((uint32_t)(r*128 + c*16));
            size_t ka = (size_t)(bm + r) * Kk + k0 + c*8;
            cpa16(base + off,          Ahi + ka);
            cpa16(base + ABYTES + off, Alo + ka);
        }
        #pragma unroll
        for (int i = 0; i < NBIT; i++){
            int idx = tid + i*T;
            int r = idx >> 3, c = idx & 7;
            uint32_t off = SWZ((uint32_t)(r*128 + c*16));
            int gn = bn + r;
            size_t kb = (size_t)gn * Kk + k0 + c*8;
            int ssz = (gn < Nn) ? 16 : 0;
            cpa16z(base + 2*ABYTES + off,         Bhi + kb, ssz);
            cpa16z(base + 2*ABYTES + 16384 + off, Blo + kb, ssz);
        }
        asm volatile("cp.async.commit_group;":::"memory");
    };

    float acc[2][8][4];
    #pragma unroll
    for (int a=0;a<2;a++) for (int b=0;b<8;b++) for (int c=0;c<4;c++) acc[a][b][c]=0.f;

    const int m0 = (wid >> 1) * 32, n0 = (wid & 1) * 64;
    const uint32_t arow = (uint32_t)(m0 + (lane & 15));
    const uint32_t acol = (uint32_t)((lane >> 4) * 16);
    const uint32_t brow = (uint32_t)(n0 + (lane & 7) + ((lane >> 4) & 1) * 8);
    const uint32_t bcol = (uint32_t)(((lane >> 3) & 1) * 16);

    auto compute = [&](int t){
        const uint32_t base = sb + (uint32_t)(t % NSTAGE) * STAGE;
        #pragma unroll
        for (int ks = 0; ks < 4; ks++){
            const uint32_t kb2 = (uint32_t)(ks * 32);
            uint32_t ah[2][4], al[2][4];
            #pragma unroll
            for (int mt = 0; mt < 2; mt++){
                uint32_t off = SWZ((arow + mt*16)*128 + kb2 + acol);
                ldsm4(ah[mt], base + off);
                ldsm4(al[mt], base + ABYTES + off);
            }
            #pragma unroll
            for (int g = 0; g < 4; g++){
                uint32_t off = SWZ((brow + g*16)*128 + kb2 + bcol);
                uint32_t bh[4], bl[4];
                ldsm4(bh, base + 2*ABYTES + off);
                ldsm4(bl, base + 2*ABYTES + 16384 + off);
                #pragma unroll
                for (int mt = 0; mt < 2; mt++){
                    #pragma unroll
                    for (int sub = 0; sub < 2; sub++){
                        float* d = acc[mt][g*2 + sub];
                        mma16(d, ah[mt], bh[sub*2], bh[sub*2+1]);
                        mma16(d, ah[mt], bl[sub*2], bl[sub*2+1]);
                        mma16(d, al[mt], bh[sub*2], bh[sub*2+1]);
                    }
                }
            }
        }
    };

    cp_stage(0);
    if (NT > 1) cp_stage(1);
    for (int t = 0; t < NT; t++){
        if (t + 1 < NT) asm volatile("cp.async.wait_group 1;":::"memory");
        else            asm volatile("cp.async.wait_group 0;":::"memory");
        __syncthreads();
        compute(t);
        if (NSTAGE == 2) __syncthreads();
        if (t + 2 < NT) cp_stage(t + 2);
    }

    #pragma unroll
    for (int mt = 0; mt < 2; mt++){
        #pragma unroll
        for (int h2 = 0; h2 < 2; h2++){
            int row = bm + m0 + mt*16 + (lane>>2) + h2*8;
            float* crow = OUTBF ? nullptr : (Cf + (size_t)row * Nn);
            const float* rrow = resid ? resid + (size_t)row * Nn : nullptr;
            #pragma unroll
            for (int nt = 0; nt < 8; nt++){
                int col = bn + n0 + nt*8 + (lane&3)*2;
                if (col >= Nn) continue;
                float v0 = acc[mt][nt][h2*2+0];
                float v1 = acc[mt][nt][h2*2+1];
                bool has1 = (col + 1 < Nn);
                if (bias){ v0 += bias[col]; if (has1) v1 += bias[col+1]; }
                if (ACT == 1){
                    float x3 = v0*v0*v0;
                    v0 = 0.5f*v0*(1.f + tanhf(0.7978845608028654f*(v0 + 0.044715f*x3)));
                    x3 = v1*v1*v1;
                    v1 = 0.5f*v1*(1.f + tanhf(0.7978845608028654f*(v1 + 0.044715f*x3)));
                }
                if (rrow){ v0 += rrow[col]; if (has1) v1 += rrow[col+1]; }
                if (OUTBF){
                    // OUTBF targets all have even Nn; col is even -> packed store
                    size_t o = (size_t)row * Nn + col;
                    uint32_t lo2, hi2 = packsplit(v0, v1, lo2);
                    *reinterpret_cast<uint32_t*>(Chi + o) = hi2;
                    *reinterpret_cast<uint32_t*>(Clo + o) = lo2;
                } else if (((Nn & 1) == 0) && has1){
                    float2 st; st.x = v0; st.y = v1;
                    *reinterpret_cast<float2*>(crow + col) = st;
                } else {
                    crow[col] = v0;
                    if (has1) crow[col + 1] = v1;
                }
            }
        }
    }
}

// ---------------------------------------------------------------------------
// FlashAttention: one block = 128 q-rows x one (b,h).
// smem: Qh,Ql 32K | K 2stages hi/lo 64K | V 2stages hi/lo 64K = 160K
// ---------------------------------------------------------------------------
#define FLASH_SMEM (163840 + 1024)

__global__ void __launch_bounds__(256) flash_kernel(
    const bf16* __restrict__ qkvh, const bf16* __restrict__ qkvl,
    const float* __restrict__ bias2,
    bf16* __restrict__ yhi, bf16* __restrict__ ylo)
{
    extern __shared__ char ds[];
    const uint32_t sb = (smem_u32(ds) + 1023) & ~1023u;
    const uint32_t sQh = sb, sQl = sb + 16384;

    const int tid = threadIdx.x, lane = tid & 31, w = tid >> 5;
    const int bh = blockIdx.y, b = bh / H_, h = bh % H_;
    const int i0 = (int)(gridDim.x - 1 - blockIdx.x) * 128;
    const int nj = (i0 >> 7) + 1;

    const bf16* qh = qkvh + (size_t)b * T_ * 3 * C_ + h * D_;
    const bf16* ql = qkvl + (size_t)b * T_ * 3 * C_ + h * D_;
    const bf16* kh = qh + C_,   * kl = ql + C_;
    const bf16* vh = qh + 2*C_, * vl = ql + 2*C_;

    auto cp_q = [&](){
        #pragma unroll
        for (int i = 0; i < 4; i++){
            int idx = tid + i*256;
            int r = idx >> 3, c = idx & 7;
            uint32_t off = SWZ((uint32_t)(r*128 + c*16));
            size_t g = (size_t)(i0 + r) * 3 * C_ + c*8;
            cpa16(sQh + off, qh + g);
            cpa16(sQl + off, ql + g);
        }
    };
    auto cp_kv = [&](int jt){
        int st = jt & 1, j0 = jt << 7;
        uint32_t kb = sb + 32768 + (uint32_t)st * 32768;
        uint32_t vb = sb + 98304 + (uint32_t)st * 32768;
        #pragma unroll
        for (int i = 0; i < 4; i++){
            int idx = tid + i*256;
            int r = idx >> 3, c = idx & 7;
            uint32_t off = SWZ((uint32_t)(r*128 + c*16));
            size_t g = (size_t)(j0 + r) * 3 * C_ + c*8;
            cpa16(kb + off,         kh + g);
            cpa16(kb + 16384 + off, kl + g);
            cpa16(vb + off,         vh + g);
            cpa16(vb + 16384 + off, vl + g);
        }
        asm volatile("cp.async.commit_group;":::"memory");
    };

    cp_q(); cp_kv(0);
    if (nj > 1) cp_kv(1);
    if (nj > 1) asm volatile("cp.async.wait_group 1;":::"memory");
    else        asm volatile("cp.async.wait_group 0;":::"memory");
    __syncthreads();

    // cache Q fragments
    uint32_t qfh[4][4], qfl[4][4];
    {
        uint32_t arow = (uint32_t)(w*16 + (lane & 15));
        uint32_t acol = (uint32_t)((lane >> 4) * 16);
        #pragma unroll
        for (int kt = 0; kt < 4; kt++){
            uint32_t off = SWZ(arow*128 + (uint32_t)kt*32 + acol);
            ldsm4(qfh[kt], sQh + off);
            ldsm4(qfl[kt], sQl + off);
        }
    }

    float O[8][4];
    #pragma unroll
    for (int i=0;i<8;i++) for (int j=0;j<4;j++) O[i][j]=0.f;
    float mr0 = -INFINITY, mr1 = -INFINITY, l0 = 0.f, l1 = 0.f;

    const float SC = 0.125f * 1.4426950408889634f;
    const uint32_t brow = (uint32_t)((lane & 7) + ((lane >> 4) & 1) * 8);
    const uint32_t bcol = (uint32_t)(((lane >> 3) & 1) * 16);
    const uint32_t vrow = (uint32_t)((lane & 7) + ((lane >> 3) & 1) * 8);
    const uint32_t vcol = (uint32_t)((lane >> 4) * 16);

    for (int jt = 0; jt < nj; jt++){
        const int st = jt & 1, j0 = jt << 7;
        const uint32_t kb = sb + 32768 + (uint32_t)st * 32768;
        const uint32_t vb = sb + 98304 + (uint32_t)st * 32768;

        // --- S = Q K^T (3x split) ---
        float S[16][4];
        #pragma unroll
        for (int i=0;i<16;i++) for (int j=0;j<4;j++) S[i][j]=0.f;
        #pragma unroll
        for (int kt = 0; kt < 4; kt++){
            const uint32_t kb2 = (uint32_t)kt * 32;
            #pragma unroll
            for (int g = 0; g < 8; g++){
                uint32_t off = SWZ((brow + g*16)*128 + kb2 + bcol);
                uint32_t kh4[4], kl4[4];
                ldsm4(kh4, kb + off);
                ldsm4(kl4, kb + 16384 + off);
                #pragma unroll
                for (int sub = 0; sub < 2; sub++){
                    float* d = S[g*2 + sub];
                    mma16(d, qfh[kt], kh4[sub*2], kh4[sub*2+1]);
                    mma16(d, qfh[kt], kl4[sub*2], kl4[sub*2+1]);
                    mma16(d, qfl[kt], kh4[sub*2], kh4[sub*2+1]);
                }
            }
        }

        // --- scale + bias (log2 domain; bias2 includes -1e30 mask) ---
        {
            int gi = i0 + w*16 + (lane >> 2);
            int gjb = j0 + (lane & 3) * 2;
            const float* b0 = bias2 + (size_t)gi * T_ + gjb;
            const float* b1 = bias2 + (size_t)(gi + 8) * T_ + gjb;
            #pragma unroll
            for (int nt = 0; nt < 16; nt++){
                float2 ba = *reinterpret_cast<const float2*>(b0 + nt*8);
                float2 bb = *reinterpret_cast<const float2*>(b1 + nt*8);
                S[nt][0] = S[nt][0]*SC + ba.x;
                S[nt][1] = S[nt][1]*SC + ba.y;
                S[nt][2] = S[nt][2]*SC + bb.x;
                S[nt][3] = S[nt][3]*SC + bb.y;
            }
        }

        // --- online softmax ---
        float mn0 = mr0, mn1 = mr1;
        #pragma unroll
        for (int nt = 0; nt < 16; nt++){
            mn0 = fmaxf(mn0, fmaxf(S[nt][0], S[nt][1]));
            mn1 = fmaxf(mn1, fmaxf(S[nt][2], S[nt][3]));
        }
        mn0 = fmaxf(mn0, __shfl_xor_sync(0xffffffffu, mn0, 1));
        mn0 = fmaxf(mn0, __shfl_xor_sync(0xffffffffu, mn0, 2));
        mn1 = fmaxf(mn1, __shfl_xor_sync(0xffffffffu, mn1, 1));
        mn1 = fmaxf(mn1, __shfl_xor_sync(0xffffffffu, mn1, 2));
        float sc0 = exp2a(mr0 - mn0), sc1 = exp2a(mr1 - mn1);
        mr0 = mn0; mr1 = mn1;
        float rs0 = 0.f, rs1 = 0.f;
        #pragma unroll
        for (int nt = 0; nt < 16; nt++){
            S[nt][0] = exp2a(S[nt][0] - mn0);
            S[nt][1] = exp2a(S[nt][1] - mn0);
            S[nt][2] = exp2a(S[nt][2] - mn1);
            S[nt][3] = exp2a(S[nt][3] - mn1);
            rs0 += S[nt][0] + S[nt][1];
            rs1 += S[nt][2] + S[nt][3];
        }
        rs0 += __shfl_xor_sync(0xffffffffu, rs0, 1);
        rs0 += __shfl_xor_sync(0xffffffffu, rs0, 2);
        rs1 += __shfl_xor_sync(0xffffffffu, rs1, 1);
        rs1 += __shfl_xor_sync(0xffffffffu, rs1, 2);
        l0 = l0 * sc0 + rs0;
        l1 = l1 * sc1 + rs1;
        #pragma unroll
        for (int nt = 0; nt < 8; nt++){
            O[nt][0] *= sc0; O[nt][1] *= sc0;
            O[nt][2] *= sc1; O[nt][3] *= sc1;
        }

        // --- O += P V (3x split); dv covers all 64 head dims ---
        #pragma unroll
        for (int g = 0; g < 8; g++){
            uint32_t pah[4], pal[4];
            pah[0] = packsplit(S[2*g  ][0], S[2*g  ][1], pal[0]);
            pah[1] = packsplit(S[2*g  ][2], S[2*g  ][3], pal[1]);
            pah[2] = packsplit(S[2*g+1][0], S[2*g+1][1], pal[2]);
            pah[3] = packsplit(S[2*g+1][2], S[2*g+1][3], pal[3]);
            #pragma unroll
            for (int dv = 0; dv < 4; dv++){
                uint32_t off = SWZ((vrow + g*16)*128 + (uint32_t)dv*32 + vcol);
                uint32_t vh4[4], vl4[4];
                ldsm4t(vh4, vb + off);
                ldsm4t(vl4, vb + 16384 + off);
                #pragma unroll
                for (int sub = 0; sub < 2; sub++){
                    float* d = O[dv*2 + sub];
                    mma16(d, pah, vh4[sub*2], vh4[sub*2+1]);
                    mma16(d, pah, vl4[sub*2], vl4[sub*2+1]);
                    mma16(d, pal, vh4[sub*2], vh4[sub*2+1]);
                }
            }
        }

        __syncthreads();
        if (jt + 2 < nj) cp_kv(jt + 2);
        if (jt + 1 < nj){
            if (jt + 2 < nj) asm volatile("cp.async.wait_group 1;":::"memory");
            else             asm volatile("cp.async.wait_group 0;":::"memory");
            __syncthreads();
        }
    }

    // --- epilogue: normalize, write y planes (packed bf16x2) ---
    float li0 = 1.f / l0, li1 = 1.f / l1;
    int r0 = i0 + w*16 + (lane >> 2);
    size_t base0 = (size_t)b * T_ * C_ + (size_t)r0 * C_ + h * D_;
    size_t base1 = base0 + (size_t)8 * C_;
    #pragma unroll
    for (int nt = 0; nt < 8; nt++){
        int col = nt*8 + (lane & 3)*2;
        uint32_t lo2, hi2;
        hi2 = packsplit(O[nt][0]*li0, O[nt][1]*li0, lo2);
        *reinterpret_cast<uint32_t*>(yhi + base0 + col) = hi2;
        *reinterpret_cast<uint32_t*>(ylo + base0 + col) = lo2;
        hi2 = packsplit(O[nt][2]*li1, O[nt][3]*li1, lo2);
        *reinterpret_cast<uint32_t*>(yhi + base1 + col) = hi2;
        *reinterpret_cast<uint32_t*>(ylo + base1 + col) = lo2;
    }
}

// ---------------------------------------------------------------------------
// Weight prep
// ---------------------------------------------------------------------------
__global__ void wsplit_t_kernel(const float* __restrict__ in,
                                bf16* __restrict__ ohi, bf16* __restrict__ olo,
                                int K, int N){
    __shared__ float t[32][33];
    size_t lb = (size_t)blockIdx.z * K * N;
    const float* inp = in + lb;
    int kb = blockIdx.y*32, nb = blockIdx.x*32;
    int tx = threadIdx.x, ty = threadIdx.y;
    #pragma unroll
    for (int j = 0; j < 4; j++)
        t[ty + 8*j][tx] = inp[(size_t)(kb + ty + 8*j) * N + nb + tx];
    __syncthreads();
    #pragma unroll
    for (int j = 0; j < 4; j++){
        int n = nb + ty + 8*j, k = kb + tx;
        float v = t[tx][ty + 8*j];
        bf16 h, l; bsplit(v, h, l);
        size_t o = lb + (size_t)n * K + k;
        ohi[o] = h; olo[o] = l;
    }
}

__global__ void split_kernel(const float* __restrict__ in,
                             bf16* __restrict__ ohi, bf16* __restrict__ olo, int n){
    int i = blockIdx.x * 256 + threadIdx.x;
    if (i < n){
        bf16 h, l; bsplit(in[i], h, l);
        ohi[i] = h; olo[i] = l;
    }
}

// ---------------------------------------------------------------------------
// FIRE bias (pre-scaled by log2e for the flash kernel's exp2 softmax)
// ---------------------------------------------------------------------------
__global__ void fire_bias_kernel(const float* __restrict__ log_c,
                                 const float* __restrict__ v1w, const float* __restrict__ v1b,
                                 const float* __restrict__ v2w, const float* __restrict__ v2b,
                                 const float* __restrict__ v3w, const float* __restrict__ v3b,
                                 float* __restrict__ bias) {
    __shared__ float s1w[32], s1b[32], s2w[1024], s2b[32], s3w[32];
    __shared__ float s3b, sc;
    int tid = threadIdx.x;
    if (tid < 32) { s1w[tid] = v1w[tid]; s1b[tid] = v1b[tid]; s2b[tid] = v2b[tid]; s3w[tid] = v3w[tid]; }
    for (int i = tid; i < 1024; i += blockDim.x) s2w[i] = v2w[i];
    if (tid == 0) { s3b = v3b[0]; sc = expf(log_c[0]); }
    __syncthreads();

    int idx = blockIdx.x * blockDim.x + tid;
    if (idx >= T_*T_) return;
    int i = idx / T_, j = idx % T_;
    if (j > i) { bias[idx] = -1e30f; return; }

    float c = sc;
    float fi = (float)(i + 1), fj = (float)(j + 1);
    float pv = logf(c * (fi - fj) + 1.0f) / logf(c * fi + 1.0f);

    float h1[32];
    #pragma unroll
    for (int k = 0; k < 32; k++) h1[k] = fmaxf(pv * s1w[k] + s1b[k], 0.f);
    float out = s3b;
    #pragma unroll
    for (int k2 = 0; k2 < 32; k2++) {
        float a = s2b[k2];
        #pragma unroll
        for (int k1 = 0; k1 < 32; k1++) a += h1[k1] * s2w[k1*32 + k2];
        out += fmaxf(a, 0.f) * s3w[k2];
    }
    bias[idx] = out * 1.4426950408889634f;
}

// ---------------------------------------------------------------------------
// Embedding gather
// ---------------------------------------------------------------------------
__global__ void embed_kernel(const int* __restrict__ idx, const float* __restrict__ wte,
                             float* __restrict__ x) {
    int row = blockIdx.x;
    const float* src = wte + (size_t)idx[row] * C_;
    float* dst = x + (size_t)row * C_;
    for (int c = threadIdx.x; c < C_; c += blockDim.x) dst[c] = src[c];
}

// ---------------------------------------------------------------------------
// LayerNorm: warp-per-row (8 rows/block), shuffle-only reductions.
// ---------------------------------------------------------------------------
__global__ void __launch_bounds__(256) ln_kernel(
    const float* __restrict__ x, const float* __restrict__ g,
    const float* __restrict__ b,
    bf16* __restrict__ ohi, bf16* __restrict__ olo) {
    const int wid = threadIdx.x >> 5, lane = threadIdx.x & 31;
    const int row = blockIdx.x * 8 + wid;
    const float4* xr = reinterpret_cast<const float4*>(x + (size_t)row * C_);
    const float4* g4 = reinterpret_cast<const float4*>(g);
    const float4* b4 = reinterpret_cast<const float4*>(b);

    float4 v[6];
    float s = 0.f;
    #pragma unroll
    for (int c = 0; c < 6; c++){
        v[c] = xr[lane + c*32];
        s += v[c].x + v[c].y + v[c].z + v[c].w;
    }
    #pragma unroll
    for (int o = 16; o > 0; o >>= 1) s += __shfl_xor_sync(0xffffffffu, s, o);
    const float mean = s * (1.0f / C_);

    float q = 0.f;
    #pragma unroll
    for (int c = 0; c < 6; c++){
        v[c].x -= mean; v[c].y -= mean; v[c].z -= mean; v[c].w -= mean;
        q += v[c].x*v[c].x + v[c].y*v[c].y + v[c].z*v[c].z + v[c].w*v[c].w;
    }
    #pragma unroll
    for (int o = 16; o > 0; o >>= 1) q += __shfl_xor_sync(0xffffffffu, q, o);
    const float rs = rsqrtf(q * (1.0f / C_) + 1e-5f);

    const size_t base = (size_t)row * C_;
    #pragma unroll
    for (int c = 0; c < 6; c++){
        int c4 = lane + c*32;
        float4 gg = g4[c4], bb = b4[c4];
        float o0 = v[c].x*rs*gg.x + bb.x;
        float o1 = v[c].y*rs*gg.y + bb.y;
        float o2 = v[c].z*rs*gg.z + bb.z;
        float o3 = v[c].w*rs*gg.w + bb.w;
        uint32_t lo01, lo23;
        uint32_t hi01 = packsplit(o0, o1, lo01);
        uint32_t hi23 = packsplit(o2, o3, lo23);
        uint2 hh; hh.x = hi01; hh.y = hi23;
        uint2 ll; ll.x = lo01; ll.y = lo23;
        *reinterpret_cast<uint2*>(ohi + base + c4*4) = hh;
        *reinterpret_cast<uint2*>(olo + base + c4*4) = ll;
    }
}

// ---------------------------------------------------------------------------
// Launch
// ---------------------------------------------------------------------------
extern "C" void kernel_launch(void* const* d_in, const int* in_sizes, int n_in,
                              void* d_out, int out_size) {
    int o = (n_in >= 2 && in_sizes[1] == 1) ? 1 : 0;

    const int*   idx   = (const int*)  d_in[0];
    const float* wte   = (const float*)d_in[1 + o];
    const float* log_c = (const float*)d_in[2 + o];
    const float* v1w   = (const float*)d_in[3 + o];
    const float* v1b   = (const float*)d_in[4 + o];
    const float* v2w   = (const float*)d_in[5 + o];
    const float* v2b   = (const float*)d_in[6 + o];
    const float* v3w   = (const float*)d_in[7 + o];
    const float* v3b   = (const float*)d_in[8 + o];
    const float* ln1g  = (const float*)d_in[9 + o];
    const float* ln1b  = (const float*)d_in[10 + o];
    const float* attnw = (const float*)d_in[11 + o];
    const float* attnb = (const float*)d_in[12 + o];
    const float* projw = (const float*)d_in[13 + o];
    const float* projb = (const float*)d_in[14 + o];
    const float* ln2g  = (const float*)d_in[15 + o];
    const float* ln2b  = (const float*)d_in[16 + o];
    const float* fcw   = (const float*)d_in[17 + o];
    const float* fcb   = (const float*)d_in[18 + o];
    const float* fc2w  = (const float*)d_in[19 + o];
    const float* fc2b  = (const float*)d_in[20 + o];
    const float* lnfg  = (const float*)d_in[21 + o];
    const float* lnfb  = (const float*)d_in[22 + o];

    float *bias, *x;
    bf16 *h_hi, *h_lo, *qkvh, *qkvl, *y_hi, *y_lo, *mlp_hi, *mlp_lo;
    bf16 *wa_hi, *wa_lo, *wp_hi, *wp_lo, *wf_hi, *wf_lo, *wf2_hi, *wf2_lo, *wte_hi, *wte_lo;
    cudaGetSymbolAddress((void**)&bias,   g_bias);
    cudaGetSymbolAddress((void**)&x,      g_x);
    cudaGetSymbolAddress((void**)&h_hi,   g_h_hi);   cudaGetSymbolAddress((void**)&h_lo,   g_h_lo);
    cudaGetSymbolAddress((void**)&qkvh,   g_qkvh);   cudaGetSymbolAddress((void**)&qkvl,   g_qkvl);
    cudaGetSymbolAddress((void**)&y_hi,   g_y_hi);   cudaGetSymbolAddress((void**)&y_lo,   g_y_lo);
    cudaGetSymbolAddress((void**)&mlp_hi, g_mlp_hi); cudaGetSymbolAddress((void**)&mlp_lo, g_mlp_lo);
    cudaGetSymbolAddress((void**)&wa_hi,  g_wa_hi);  cudaGetSymbolAddress((void**)&wa_lo,  g_wa_lo);
    cudaGetSymbolAddress((void**)&wp_hi,  g_wp_hi);  cudaGetSymbolAddress((void**)&wp_lo,  g_wp_lo);
    cudaGetSymbolAddress((void**)&wf_hi,  g_wf_hi);  cudaGetSymbolAddress((void**)&wf_lo,  g_wf_lo);
    cudaGetSymbolAddress((void**)&wf2_hi, g_wf2_hi); cudaGetSymbolAddress((void**)&wf2_lo, g_wf2_lo);
    cudaGetSymbolAddress((void**)&wte_hi, g_wte_hi); cudaGetSymbolAddress((void**)&wte_lo, g_wte_lo);

    // smem sizes per GEMM variant
    const int SM128 = 3*65536 + 1024;   // BM=128, 3 stages
    const int SM64  = 2*49152 + 1024;   // BM=64, 2 stages (2 CTAs/SM)

    cudaFuncSetAttribute(mma_gemm<0,true ,128,3>, cudaFuncAttributeMaxDynamicSharedMemorySize, SM128);
    cudaFuncSetAttribute(mma_gemm<1,true ,128,3>, cudaFuncAttributeMaxDynamicSharedMemorySize, SM128);
    cudaFuncSetAttribute(mma_gemm<0,false,128,3>, cudaFuncAttributeMaxDynamicSharedMemorySize, SM128);
    cudaFuncSetAttribute(mma_gemm<0,false, 64,2>, cudaFuncAttributeMaxDynamicSharedMemorySize, SM64);
    cudaFuncSetAttribute(flash_kernel,            cudaFuncAttributeMaxDynamicSharedMemorySize, FLASH_SMEM);

    // 1. FIRE bias + embedding + weight prep
    fire_bias_kernel<<<(T_*T_ + 255) / 256, 256>>>(log_c, v1w, v1b, v2w, v2b, v3w, v3b, bias);
    embed_kernel<<<M_, 256>>>(idx, wte, x);
    {
        dim3 tb(32, 8);
        wsplit_t_kernel<<<dim3(3*C_/32,  C_/32,  L_), tb>>>(attnw, wa_hi,  wa_lo,  C_,   3*C_);
        wsplit_t_kernel<<<dim3(C_/32,    C_/32,  L_), tb>>>(projw, wp_hi,  wp_lo,  C_,   C_);
        wsplit_t_kernel<<<dim3(4*C_/32,  C_/32,  L_), tb>>>(fcw,   wf_hi,  wf_lo,  C_,   4*C_);
        wsplit_t_kernel<<<dim3(C_/32,  4*C_/32,  L_), tb>>>(fc2w,  wf2_hi, wf2_lo, 4*C_, C_);
        split_kernel<<<(V_*C_ + 255)/256, 256>>>(wte, wte_hi, wte_lo, V_*C_);
    }

    // 2. Transformer layers
    const dim3 g_qkvd(3*C_/128, M_/128);
    const dim3 g_cc64(C_/128,   M_/64);
    const dim3 g_fc  (4*C_/128, M_/128);
    const dim3 g_fl  (T_/128, B_*H_);

    for (int l = 0; l < L_; l++) {
        size_t wa = (size_t)l*3*C_*C_, wp = (size_t)l*C_*C_, wf = (size_t)l*4*C_*C_;
        ln_kernel<<<M_/8, 256>>>(x, ln1g + (size_t)l*C_, ln1b + (size_t)l*C_, h_hi, h_lo);
        mma_gemm<0,true,128,3><<<g_qkvd, 256, SM128>>>(h_hi, h_lo, wa_hi + wa, wa_lo + wa,
                                                       attnb + (size_t)l*3*C_, nullptr,
                                                       nullptr, qkvh, qkvl, 3*C_, C_);
        flash_kernel<<<g_fl, 256, FLASH_SMEM>>>(qkvh, qkvl, bias, y_hi, y_lo);
        mma_gemm<0,false,64,2><<<g_cc64, 128, SM64>>>(y_hi, y_lo, wp_hi + wp, wp_lo + wp,
                                                      projb + (size_t)l*C_, x,
                                                      x, nullptr, nullptr, C_, C_);
        ln_kernel<<<M_/8, 256>>>(x, ln2g + (size_t)l*C_, ln2b + (size_t)l*C_, h_hi, h_lo);
        mma_gemm<1,true,128,3><<<g_fc, 256, SM128>>>(h_hi, h_lo, wf_hi + wf, wf_lo + wf,
                                                     fcb + (size_t)l*4*C_, nullptr,
                                                     nullptr, mlp_hi, mlp_lo, 4*C_, C_);
        mma_gemm<0,false,64,2><<<g_cc64, 128, SM64>>>(mlp_hi, mlp_lo, wf2_hi + wf, wf2_lo + wf,
                                                      fc2b + (size_t)l*C_, x,
                                                      x, nullptr, nullptr, C_, 4*C_);
    }

    // 3. Final LN + tied LM head
    ln_kernel<<<M_/8, 256>>>(x, lnfg, lnfb, h_hi, h_lo);
    const dim3 g_lm((V_ + 127)/128, M_/128);
    mma_gemm<0,false,128,3><<<g_lm, 256, SM128>>>(h_hi, h_lo, wte_hi, wte_lo,
                                                  nullptr, nullptr,
                                                  (float*)d_out, nullptr, nullptr, V_, C_);
}

// round 9
// speedup vs baseline: 6.0059x; 1.0490x over previous
#include <cuda_runtime.h>
#include <cuda_bf16.h>
#include <cuda_fp16.h>
#include <math.h>
#include <stdint.h>

// Problem constants
#define L_ 12
#define H_ 12
#define C_ 768
#define V_ 50257
#define B_ 2
#define T_ 1024
#define D_ 64
#define M_ (B_*T_)   // 2048 rows

typedef __nv_bfloat16 bf16;

// ---------------------------------------------------------------------------
// Scratch (static device globals)
// ---------------------------------------------------------------------------
__device__ float g_bias[T_*T_];
__device__ float g_x   [M_*C_];

__device__ bf16 g_h_hi [M_*C_],    g_h_lo [M_*C_];
__device__ bf16 g_qkvh [M_*3*C_],  g_qkvl [M_*3*C_];
__device__ bf16 g_y_hi [M_*C_],    g_y_lo [M_*C_];
__device__ bf16 g_mlp_hi[M_*4*C_], g_mlp_lo[M_*4*C_];

__device__ bf16 g_wa_hi [L_*3*C_*C_], g_wa_lo [L_*3*C_*C_];
__device__ bf16 g_wp_hi [L_*C_*C_],   g_wp_lo [L_*C_*C_];
__device__ bf16 g_wf_hi [L_*4*C_*C_], g_wf_lo [L_*4*C_*C_];
__device__ bf16 g_wf2_hi[L_*C_*4*C_], g_wf2_lo[L_*C_*4*C_];

// LM head: fp16 planes (2-product path)
__device__ __half g_wteh[(size_t)V_*C_], g_wtel[(size_t)V_*C_];
__device__ __half g_hf16[M_*C_];

// ---------------------------------------------------------------------------
// Helpers
// ---------------------------------------------------------------------------
__device__ __forceinline__ uint32_t smem_u32(const void* p){
    uint32_t a;
    asm("{ .reg .u64 t; cvta.to.shared.u64 t, %1; cvt.u32.u64 %0, t; }":"=r"(a):"l"(p));
    return a;
}
__device__ __forceinline__ void cpa16(uint32_t saddr, const void* gptr){
    asm volatile("cp.async.cg.shared.global [%0], [%1], 16;"::"r"(saddr),"l"(gptr));
}
__device__ __forceinline__ void cpa16z(uint32_t saddr, const void* gptr, int ssz){
    asm volatile("cp.async.cg.shared.global [%0], [%1], 16, %2;"::"r"(saddr),"l"(gptr),"r"(ssz));
}
__device__ __forceinline__ void ldsm4(uint32_t* r, uint32_t addr){
    asm volatile("ldmatrix.sync.aligned.m8n8.x4.shared.b16 {%0,%1,%2,%3}, [%4];"
      : "=r"(r[0]),"=r"(r[1]),"=r"(r[2]),"=r"(r[3]) : "r"(addr));
}
__device__ __forceinline__ void ldsm4t(uint32_t* r, uint32_t addr){
    asm volatile("ldmatrix.sync.aligned.m8n8.x4.trans.shared.b16 {%0,%1,%2,%3}, [%4];"
      : "=r"(r[0]),"=r"(r[1]),"=r"(r[2]),"=r"(r[3]) : "r"(addr));
}
__device__ __forceinline__ void mma16(float* d, const uint32_t* a, uint32_t b0, uint32_t b1){
    asm volatile("mma.sync.aligned.m16n8k16.row.col.f32.bf16.bf16.f32 "
      "{%0,%1,%2,%3}, {%4,%5,%6,%7}, {%8,%9}, {%0,%1,%2,%3};"
      : "+f"(d[0]),"+f"(d[1]),"+f"(d[2]),"+f"(d[3])
      : "r"(a[0]),"r"(a[1]),"r"(a[2]),"r"(a[3]),"r"(b0),"r"(b1));
}
__device__ __forceinline__ void mma16h(float* d, const uint32_t* a, uint32_t b0, uint32_t b1){
    asm volatile("mma.sync.aligned.m16n8k16.row.col.f32.f16.f16.f32 "
      "{%0,%1,%2,%3}, {%4,%5,%6,%7}, {%8,%9}, {%0,%1,%2,%3};"
      : "+f"(d[0]),"+f"(d[1]),"+f"(d[2]),"+f"(d[3])
      : "r"(a[0]),"r"(a[1]),"r"(a[2]),"r"(a[3]),"r"(b0),"r"(b1));
}
__device__ __forceinline__ float exp2a(float x){
    float y; asm("ex2.approx.ftz.f32 %0, %1;":"=f"(y):"f"(x)); return y;
}
__device__ __forceinline__ float rcpa(float x){
    float y; asm("rcp.approx.ftz.f32 %0, %1;":"=f"(y):"f"(x)); return y;
}
// fast exact-ish tanh-GELU: 0.5x(1+tanh(u)) = x - x/(e^{2u}+1)
__device__ __forceinline__ float gelu_f(float v){
    float u = 0.7978845608028654f*(v + 0.044715f*v*v*v);
    float t = exp2a(u * 2.8853900817779268f);     // e^{2u}
    return v - v * rcpa(t + 1.0f);
}
// pack two f32 -> bf16x2 (lower = c0), and residual pack
__device__ __forceinline__ uint32_t packsplit(float c0, float c1, uint32_t& lo){
    uint32_t hi;
    asm("cvt.rn.bf16x2.f32 %0, %1, %2;" : "=r"(hi) : "f"(c1), "f"(c0));
    float h0 = __uint_as_float(hi << 16);
    float h1 = __uint_as_float(hi & 0xffff0000u);
    asm("cvt.rn.bf16x2.f32 %0, %1, %2;" : "=r"(lo) : "f"(c1 - h1), "f"(c0 - h0));
    return hi;
}
#define SWZ(o) ((o) ^ (((o)>>3)&0x70))

// ---------------------------------------------------------------------------
// Split GEMM via mma.m16n8k16, cp.async multi-stage pipeline.
//   DT=0: bf16 planes, 3 products (Ahi,Alo,Bhi,Blo).
//   DT=1: fp16, 2 products, SINGLE A plane (Ahi) x (Bhi,Blo). For LM head.
//   Grid: bm = blockIdx.x*BM_ (M fastest -> B-tile L2 reuse), bn = blockIdx.y*128.
// ---------------------------------------------------------------------------
template<int ACT, bool OUTBF, int BM_, int NSTAGE, int DT>
__global__ void __launch_bounds__(BM_*2) mma_gemm(
    const bf16* __restrict__ Ahi, const bf16* __restrict__ Alo,
    const bf16* __restrict__ Bhi, const bf16* __restrict__ Blo,
    const float* __restrict__ bias, const float* __restrict__ resid,
    float* __restrict__ Cf, bf16* __restrict__ Chi, bf16* __restrict__ Clo,
    int Nn, int Kk)
{
    constexpr int T = BM_ * 2;
    constexpr uint32_t ABYTES = BM_ * 128;                        // per A plane
    constexpr uint32_t BOFF   = (DT==0) ? 2*ABYTES : ABYTES;      // B planes base
    constexpr uint32_t STAGE  = BOFF + 32768;
    constexpr int NBIT = 1024 / T;

    extern __shared__ char ds[];
    const uint32_t sb = (smem_u32(ds) + 1023) & ~1023u;

    const int tid = threadIdx.x, lane = tid & 31, wid = tid >> 5;
    const int bm = blockIdx.x * BM_, bn = blockIdx.y * 128;
    const int NT = Kk >> 6;

    auto cp_stage = [&](int t){
        const uint32_t base = sb + (uint32_t)(t % NSTAGE) * STAGE;
        const int k0 = t << 6;
        #pragma unroll
        for (int i = 0; i < 4; i++){
            int idx = tid + i*T;
            int r = idx >> 3, c = idx & 7;
            uint32_t off = SWZ((uint32_t)(r*128 + c*16));
            size_t ka = (size_t)(bm + r) * Kk + k0 + c*8;
            cpa16(base + off, Ahi + ka);
            if (DT == 0) cpa16(base + ABYTES + off, Alo + ka);
        }
        #pragma unroll
        for (int i = 0; i < NBIT; i++){
            int idx = tid + i*T;
            int r = idx >> 3, c = idx & 7;
            uint32_t off = SWZ((uint32_t)(r*128 + c*16));
            int gn = bn + r;
            size_t kb = (size_t)gn * Kk + k0 + c*8;
            int ssz = (gn < Nn) ? 16 : 0;
            cpa16z(base + BOFF + off,         Bhi + kb, ssz);
            cpa16z(base + BOFF + 16384 + off, Blo + kb, ssz);
        }
        asm volatile("cp.async.commit_group;":::"memory");
    };

    float acc[2][8][4];
    #pragma unroll
    for (int a=0;a<2;a++) for (int b=0;b<8;b++) for (int c=0;c<4;c++) acc[a][b][c]=0.f;

    const int m0 = (wid >> 1) * 32, n0 = (wid & 1) * 64;
    const uint32_t arow = (uint32_t)(m0 + (lane & 15));
    const uint32_t acol = (uint32_t)((lane >> 4) * 16);
    const uint32_t brow = (uint32_t)(n0 + (lane & 7) + ((lane >> 4) & 1) * 8);
    const uint32_t bcol = (uint32_t)(((lane >> 3) & 1) * 16);

    auto compute = [&](int t){
        const uint32_t base = sb + (uint32_t)(t % NSTAGE) * STAGE;
        #pragma unroll
        for (int ks = 0; ks < 4; ks++){
            const uint32_t kb2 = (uint32_t)(ks * 32);
            uint32_t ah[2][4], al[2][4];
            #pragma unroll
            for (int mt = 0; mt < 2; mt++){
                uint32_t off = SWZ((arow + mt*16)*128 + kb2 + acol);
                ldsm4(ah[mt], base + off);
                if (DT == 0) ldsm4(al[mt], base + ABYTES + off);
            }
            #pragma unroll
            for (int g = 0; g < 4; g++){
                uint32_t off = SWZ((brow + g*16)*128 + kb2 + bcol);
                uint32_t bh[4], bl[4];
                ldsm4(bh, base + BOFF + off);
                ldsm4(bl, base + BOFF + 16384 + off);
                #pragma unroll
                for (int mt = 0; mt < 2; mt++){
                    #pragma unroll
                    for (int sub = 0; sub < 2; sub++){
                        float* d = acc[mt][g*2 + sub];
                        if (DT == 0){
                            mma16(d, ah[mt], bh[sub*2], bh[sub*2+1]);
                            mma16(d, ah[mt], bl[sub*2], bl[sub*2+1]);
                            mma16(d, al[mt], bh[sub*2], bh[sub*2+1]);
                        } else {
                            mma16h(d, ah[mt], bh[sub*2], bh[sub*2+1]);
                            mma16h(d, ah[mt], bl[sub*2], bl[sub*2+1]);
                        }
                    }
                }
            }
        }
    };

    cp_stage(0);
    if (NT > 1) cp_stage(1);
    for (int t = 0; t < NT; t++){
        if (t + 1 < NT) asm volatile("cp.async.wait_group 1;":::"memory");
        else            asm volatile("cp.async.wait_group 0;":::"memory");
        __syncthreads();
        compute(t);
        if (NSTAGE == 2) __syncthreads();
        if (t + 2 < NT) cp_stage(t + 2);
    }

    #pragma unroll
    for (int mt = 0; mt < 2; mt++){
        #pragma unroll
        for (int h2 = 0; h2 < 2; h2++){
            int row = bm + m0 + mt*16 + (lane>>2) + h2*8;
            float* crow = OUTBF ? nullptr : (Cf + (size_t)row * Nn);
            const float* rrow = resid ? resid + (size_t)row * Nn : nullptr;
            #pragma unroll
            for (int nt = 0; nt < 8; nt++){
                int col = bn + n0 + nt*8 + (lane&3)*2;
                if (col >= Nn) continue;
                float v0 = acc[mt][nt][h2*2+0];
                float v1 = acc[mt][nt][h2*2+1];
                bool has1 = (col + 1 < Nn);
                if (bias){ v0 += bias[col]; if (has1) v1 += bias[col+1]; }
                if (ACT == 1){ v0 = gelu_f(v0); v1 = gelu_f(v1); }
                if (rrow){ v0 += rrow[col]; if (has1) v1 += rrow[col+1]; }
                if (OUTBF){
                    size_t o = (size_t)row * Nn + col;
                    uint32_t lo2, hi2 = packsplit(v0, v1, lo2);
                    *reinterpret_cast<uint32_t*>(Chi + o) = hi2;
                    *reinterpret_cast<uint32_t*>(Clo + o) = lo2;
                } else if (((Nn & 1) == 0) && has1){
                    float2 st; st.x = v0; st.y = v1;
                    *reinterpret_cast<float2*>(crow + col) = st;
                } else {
                    crow[col] = v0;
                    if (has1) crow[col + 1] = v1;
                }
            }
        }
    }
}

// ---------------------------------------------------------------------------
// FlashAttention: one block = 128 q-rows x one (b,h).
// ---------------------------------------------------------------------------
#define FLASH_SMEM (163840 + 1024)

__global__ void __launch_bounds__(256) flash_kernel(
    const bf16* __restrict__ qkvh, const bf16* __restrict__ qkvl,
    const float* __restrict__ bias2,
    bf16* __restrict__ yhi, bf16* __restrict__ ylo)
{
    extern __shared__ char ds[];
    const uint32_t sb = (smem_u32(ds) + 1023) & ~1023u;
    const uint32_t sQh = sb, sQl = sb + 16384;

    const int tid = threadIdx.x, lane = tid & 31, w = tid >> 5;
    const int bh = blockIdx.y, b = bh / H_, h = bh % H_;
    const int i0 = (int)(gridDim.x - 1 - blockIdx.x) * 128;
    const int nj = (i0 >> 7) + 1;

    const bf16* qh = qkvh + (size_t)b * T_ * 3 * C_ + h * D_;
    const bf16* ql = qkvl + (size_t)b * T_ * 3 * C_ + h * D_;
    const bf16* kh = qh + C_,   * kl = ql + C_;
    const bf16* vh = qh + 2*C_, * vl = ql + 2*C_;

    auto cp_q = [&](){
        #pragma unroll
        for (int i = 0; i < 4; i++){
            int idx = tid + i*256;
            int r = idx >> 3, c = idx & 7;
            uint32_t off = SWZ((uint32_t)(r*128 + c*16));
            size_t g = (size_t)(i0 + r) * 3 * C_ + c*8;
            cpa16(sQh + off, qh + g);
            cpa16(sQl + off, ql + g);
        }
    };
    auto cp_kv = [&](int jt){
        int st = jt & 1, j0 = jt << 7;
        uint32_t kb = sb + 32768 + (uint32_t)st * 32768;
        uint32_t vb = sb + 98304 + (uint32_t)st * 32768;
        #pragma unroll
        for (int i = 0; i < 4; i++){
            int idx = tid + i*256;
            int r = idx >> 3, c = idx & 7;
            uint32_t off = SWZ((uint32_t)(r*128 + c*16));
            size_t g = (size_t)(j0 + r) * 3 * C_ + c*8;
            cpa16(kb + off,         kh + g);
            cpa16(kb + 16384 + off, kl + g);
            cpa16(vb + off,         vh + g);
            cpa16(vb + 16384 + off, vl + g);
        }
        asm volatile("cp.async.commit_group;":::"memory");
    };

    cp_q(); cp_kv(0);
    if (nj > 1) cp_kv(1);
    if (nj > 1) asm volatile("cp.async.wait_group 1;":::"memory");
    else        asm volatile("cp.async.wait_group 0;":::"memory");
    __syncthreads();

    uint32_t qfh[4][4], qfl[4][4];
    {
        uint32_t arow = (uint32_t)(w*16 + (lane & 15));
        uint32_t acol = (uint32_t)((lane >> 4) * 16);
        #pragma unroll
        for (int kt = 0; kt < 4; kt++){
            uint32_t off = SWZ(arow*128 + (uint32_t)kt*32 + acol);
            ldsm4(qfh[kt], sQh + off);
            ldsm4(qfl[kt], sQl + off);
        }
    }

    float O[8][4];
    #pragma unroll
    for (int i=0;i<8;i++) for (int j=0;j<4;j++) O[i][j]=0.f;
    float mr0 = -INFINITY, mr1 = -INFINITY, l0 = 0.f, l1 = 0.f;

    const float SC = 0.125f * 1.4426950408889634f;
    const uint32_t brow = (uint32_t)((lane & 7) + ((lane >> 4) & 1) * 8);
    const uint32_t bcol = (uint32_t)(((lane >> 3) & 1) * 16);
    const uint32_t vrow = (uint32_t)((lane & 7) + ((lane >> 3) & 1) * 8);
    const uint32_t vcol = (uint32_t)((lane >> 4) * 16);

    for (int jt = 0; jt < nj; jt++){
        const int st = jt & 1, j0 = jt << 7;
        const uint32_t kb = sb + 32768 + (uint32_t)st * 32768;
        const uint32_t vb = sb + 98304 + (uint32_t)st * 32768;

        float S[16][4];
        #pragma unroll
        for (int i=0;i<16;i++) for (int j=0;j<4;j++) S[i][j]=0.f;
        #pragma unroll
        for (int kt = 0; kt < 4; kt++){
            const uint32_t kb2 = (uint32_t)kt * 32;
            #pragma unroll
            for (int g = 0; g < 8; g++){
                uint32_t off = SWZ((brow + g*16)*128 + kb2 + bcol);
                uint32_t kh4[4], kl4[4];
                ldsm4(kh4, kb + off);
                ldsm4(kl4, kb + 16384 + off);
                #pragma unroll
                for (int sub = 0; sub < 2; sub++){
                    float* d = S[g*2 + sub];
                    mma16(d, qfh[kt], kh4[sub*2], kh4[sub*2+1]);
                    mma16(d, qfh[kt], kl4[sub*2], kl4[sub*2+1]);
                    mma16(d, qfl[kt], kh4[sub*2], kh4[sub*2+1]);
                }
            }
        }

        {
            int gi = i0 + w*16 + (lane >> 2);
            int gjb = j0 + (lane & 3) * 2;
            const float* b0 = bias2 + (size_t)gi * T_ + gjb;
            const float* b1 = bias2 + (size_t)(gi + 8) * T_ + gjb;
            #pragma unroll
            for (int nt = 0; nt < 16; nt++){
                float2 ba = *reinterpret_cast<const float2*>(b0 + nt*8);
                float2 bb = *reinterpret_cast<const float2*>(b1 + nt*8);
                S[nt][0] = S[nt][0]*SC + ba.x;
                S[nt][1] = S[nt][1]*SC + ba.y;
                S[nt][2] = S[nt][2]*SC + bb.x;
                S[nt][3] = S[nt][3]*SC + bb.y;
            }
        }

        float mn0 = mr0, mn1 = mr1;
        #pragma unroll
        for (int nt = 0; nt < 16; nt++){
            mn0 = fmaxf(mn0, fmaxf(S[nt][0], S[nt][1]));
            mn1 = fmaxf(mn1, fmaxf(S[nt][2], S[nt][3]));
        }
        mn0 = fmaxf(mn0, __shfl_xor_sync(0xffffffffu, mn0, 1));
        mn0 = fmaxf(mn0, __shfl_xor_sync(0xffffffffu, mn0, 2));
        mn1 = fmaxf(mn1, __shfl_xor_sync(0xffffffffu, mn1, 1));
        mn1 = fmaxf(mn1, __shfl_xor_sync(0xffffffffu, mn1, 2));
        float sc0 = exp2a(mr0 - mn0), sc1 = exp2a(mr1 - mn1);
        mr0 = mn0; mr1 = mn1;
        float rs0 = 0.f, rs1 = 0.f;
        #pragma unroll
        for (int nt = 0; nt < 16; nt++){
            S[nt][0] = exp2a(S[nt][0] - mn0);
            S[nt][1] = exp2a(S[nt][1] - mn0);
            S[nt][2] = exp2a(S[nt][2] - mn1);
            S[nt][3] = exp2a(S[nt][3] - mn1);
            rs0 += S[nt][0] + S[nt][1];
            rs1 += S[nt][2] + S[nt][3];
        }
        rs0 += __shfl_xor_sync(0xffffffffu, rs0, 1);
        rs0 += __shfl_xor_sync(0xffffffffu, rs0, 2);
        rs1 += __shfl_xor_sync(0xffffffffu, rs1, 1);
        rs1 += __shfl_xor_sync(0xffffffffu, rs1, 2);
        l0 = l0 * sc0 + rs0;
        l1 = l1 * sc1 + rs1;
        #pragma unroll
        for (int nt = 0; nt < 8; nt++){
            O[nt][0] *= sc0; O[nt][1] *= sc0;
            O[nt][2] *= sc1; O[nt][3] *= sc1;
        }

        #pragma unroll
        for (int g = 0; g < 8; g++){
            uint32_t pah[4], pal[4];
            pah[0] = packsplit(S[2*g  ][0], S[2*g  ][1], pal[0]);
            pah[1] = packsplit(S[2*g  ][2], S[2*g  ][3], pal[1]);
            pah[2] = packsplit(S[2*g+1][0], S[2*g+1][1], pal[2]);
            pah[3] = packsplit(S[2*g+1][2], S[2*g+1][3], pal[3]);
            #pragma unroll
            for (int dv = 0; dv < 4; dv++){
                uint32_t off = SWZ((vrow + g*16)*128 + (uint32_t)dv*32 + vcol);
                uint32_t vh4[4], vl4[4];
                ldsm4t(vh4, vb + off);
                ldsm4t(vl4, vb + 16384 + off);
                #pragma unroll
                for (int sub = 0; sub < 2; sub++){
                    float* d = O[dv*2 + sub];
                    mma16(d, pah, vh4[sub*2], vh4[sub*2+1]);
                    mma16(d, pah, vl4[sub*2], vl4[sub*2+1]);
                    mma16(d, pal, vh4[sub*2], vh4[sub*2+1]);
                }
            }
        }

        __syncthreads();
        if (jt + 2 < nj) cp_kv(jt + 2);
        if (jt + 1 < nj){
            if (jt + 2 < nj) asm volatile("cp.async.wait_group 1;":::"memory");
            else             asm volatile("cp.async.wait_group 0;":::"memory");
            __syncthreads();
        }
    }

    float li0 = 1.f / l0, li1 = 1.f / l1;
    int r0 = i0 + w*16 + (lane >> 2);
    size_t base0 = (size_t)b * T_ * C_ + (size_t)r0 * C_ + h * D_;
    size_t base1 = base0 + (size_t)8 * C_;
    #pragma unroll
    for (int nt = 0; nt < 8; nt++){
        int col = nt*8 + (lane & 3)*2;
        uint32_t lo2, hi2;
        hi2 = packsplit(O[nt][0]*li0, O[nt][1]*li0, lo2);
        *reinterpret_cast<uint32_t*>(yhi + base0 + col) = hi2;
        *reinterpret_cast<uint32_t*>(ylo + base0 + col) = lo2;
        hi2 = packsplit(O[nt][2]*li1, O[nt][3]*li1, lo2);
        *reinterpret_cast<uint32_t*>(yhi + base1 + col) = hi2;
        *reinterpret_cast<uint32_t*>(ylo + base1 + col) = lo2;
    }
}

// ---------------------------------------------------------------------------
// Weight prep
// ---------------------------------------------------------------------------
__device__ __forceinline__ void bsplit(float v, bf16& h, bf16& l){
    h = __float2bfloat16(v);
    l = __float2bfloat16(v - __bfloat162float(h));
}

__global__ void wsplit_t_kernel(const float* __restrict__ in,
                                bf16* __restrict__ ohi, bf16* __restrict__ olo,
                                int K, int N){
    __shared__ float t[32][33];
    size_t lb = (size_t)blockIdx.z * K * N;
    const float* inp = in + lb;
    int kb = blockIdx.y*32, nb = blockIdx.x*32;
    int tx = threadIdx.x, ty = threadIdx.y;
    #pragma unroll
    for (int j = 0; j < 4; j++)
        t[ty + 8*j][tx] = inp[(size_t)(kb + ty + 8*j) * N + nb + tx];
    __syncthreads();
    #pragma unroll
    for (int j = 0; j < 4; j++){
        int n = nb + ty + 8*j, k = kb + tx;
        float v = t[tx][ty + 8*j];
        bf16 h, l; bsplit(v, h, l);
        size_t o = lb + (size_t)n * K + k;
        ohi[o] = h; olo[o] = l;
    }
}

// fp16 split for wte
__global__ void split_f16_kernel(const float* __restrict__ in,
                                 __half* __restrict__ ohi, __half* __restrict__ olo, int n){
    int i = blockIdx.x * 256 + threadIdx.x;
    if (i < n){
        float v = in[i];
        __half h = __float2half_rn(v);
        ohi[i] = h;
        olo[i] = __float2half_rn(v - __half2float(h));
    }
}

// ---------------------------------------------------------------------------
// FIRE bias (pre-scaled by log2e)
// ---------------------------------------------------------------------------
__global__ void fire_bias_kernel(const float* __restrict__ log_c,
                                 const float* __restrict__ v1w, const float* __restrict__ v1b,
                                 const float* __restrict__ v2w, const float* __restrict__ v2b,
                                 const float* __restrict__ v3w, const float* __restrict__ v3b,
                                 float* __restrict__ bias) {
    __shared__ float s1w[32], s1b[32], s2w[1024], s2b[32], s3w[32];
    __shared__ float s3b, sc;
    int tid = threadIdx.x;
    if (tid < 32) { s1w[tid] = v1w[tid]; s1b[tid] = v1b[tid]; s2b[tid] = v2b[tid]; s3w[tid] = v3w[tid]; }
    for (int i = tid; i < 1024; i += blockDim.x) s2w[i] = v2w[i];
    if (tid == 0) { s3b = v3b[0]; sc = expf(log_c[0]); }
    __syncthreads();

    int idx = blockIdx.x * blockDim.x + tid;
    if (idx >= T_*T_) return;
    int i = idx / T_, j = idx % T_;
    if (j > i) { bias[idx] = -1e30f; return; }

    float c = sc;
    float fi = (float)(i + 1), fj = (float)(j + 1);
    float pv = logf(c * (fi - fj) + 1.0f) / logf(c * fi + 1.0f);

    float h1[32];
    #pragma unroll
    for (int k = 0; k < 32; k++) h1[k] = fmaxf(pv * s1w[k] + s1b[k], 0.f);
    float out = s3b;
    #pragma unroll
    for (int k2 = 0; k2 < 32; k2++) {
        float a = s2b[k2];
        #pragma unroll
        for (int k1 = 0; k1 < 32; k1++) a += h1[k1] * s2w[k1*32 + k2];
        out += fmaxf(a, 0.f) * s3w[k2];
    }
    bias[idx] = out * 1.4426950408889634f;
}

// ---------------------------------------------------------------------------
// Embedding gather
// ---------------------------------------------------------------------------
__global__ void embed_kernel(const int* __restrict__ idx, const float* __restrict__ wte,
                             float* __restrict__ x) {
    int row = blockIdx.x;
    const float* src = wte + (size_t)idx[row] * C_;
    float* dst = x + (size_t)row * C_;
    for (int c = threadIdx.x; c < C_; c += blockDim.x) dst[c] = src[c];
}

// ---------------------------------------------------------------------------
// LayerNorm: warp-per-row -> bf16 hi/lo planes
// ---------------------------------------------------------------------------
__global__ void __launch_bounds__(256) ln_kernel(
    const float* __restrict__ x, const float* __restrict__ g,
    const float* __restrict__ b,
    bf16* __restrict__ ohi, bf16* __restrict__ olo) {
    const int wid = threadIdx.x >> 5, lane = threadIdx.x & 31;
    const int row = blockIdx.x * 8 + wid;
    const float4* xr = reinterpret_cast<const float4*>(x + (size_t)row * C_);
    const float4* g4 = reinterpret_cast<const float4*>(g);
    const float4* b4 = reinterpret_cast<const float4*>(b);

    float4 v[6];
    float s = 0.f;
    #pragma unroll
    for (int c = 0; c < 6; c++){
        v[c] = xr[lane + c*32];
        s += v[c].x + v[c].y + v[c].z + v[c].w;
    }
    #pragma unroll
    for (int o = 16; o > 0; o >>= 1) s += __shfl_xor_sync(0xffffffffu, s, o);
    const float mean = s * (1.0f / C_);

    float q = 0.f;
    #pragma unroll
    for (int c = 0; c < 6; c++){
        v[c].x -= mean; v[c].y -= mean; v[c].z -= mean; v[c].w -= mean;
        q += v[c].x*v[c].x + v[c].y*v[c].y + v[c].z*v[c].z + v[c].w*v[c].w;
    }
    #pragma unroll
    for (int o = 16; o > 0; o >>= 1) q += __shfl_xor_sync(0xffffffffu, q, o);
    const float rs = rsqrtf(q * (1.0f / C_) + 1e-5f);

    const size_t base = (size_t)row * C_;
    #pragma unroll
    for (int c = 0; c < 6; c++){
        int c4 = lane + c*32;
        float4 gg = g4[c4], bb = b4[c4];
        float o0 = v[c].x*rs*gg.x + bb.x;
        float o1 = v[c].y*rs*gg.y + bb.y;
        float o2 = v[c].z*rs*gg.z + bb.z;
        float o3 = v[c].w*rs*gg.w + bb.w;
        uint32_t lo01, lo23;
        uint32_t hi01 = packsplit(o0, o1, lo01);
        uint32_t hi23 = packsplit(o2, o3, lo23);
        uint2 hh; hh.x = hi01; hh.y = hi23;
        uint2 ll; ll.x = lo01; ll.y = lo23;
        *reinterpret_cast<uint2*>(ohi + base + c4*4) = hh;
        *reinterpret_cast<uint2*>(olo + base + c4*4) = ll;
    }
}

// Final LayerNorm -> single fp16 plane (for 2-product LM head)
__global__ void __launch_bounds__(256) ln_f16_kernel(
    const float* __restrict__ x, const float* __restrict__ g,
    const float* __restrict__ b, __half* __restrict__ oh) {
    const int wid = threadIdx.x >> 5, lane = threadIdx.x & 31;
    const int row = blockIdx.x * 8 + wid;
    const float4* xr = reinterpret_cast<const float4*>(x + (size_t)row * C_);
    const float4* g4 = reinterpret_cast<const float4*>(g);
    const float4* b4 = reinterpret_cast<const float4*>(b);

    float4 v[6];
    float s = 0.f;
    #pragma unroll
    for (int c = 0; c < 6; c++){
        v[c] = xr[lane + c*32];
        s += v[c].x + v[c].y + v[c].z + v[c].w;
    }
    #pragma unroll
    for (int o = 16; o > 0; o >>= 1) s += __shfl_xor_sync(0xffffffffu, s, o);
    const float mean = s * (1.0f / C_);

    float q = 0.f;
    #pragma unroll
    for (int c = 0; c < 6; c++){
        v[c].x -= mean; v[c].y -= mean; v[c].z -= mean; v[c].w -= mean;
        q += v[c].x*v[c].x + v[c].y*v[c].y + v[c].z*v[c].z + v[c].w*v[c].w;
    }
    #pragma unroll
    for (int o = 16; o > 0; o >>= 1) q += __shfl_xor_sync(0xffffffffu, q, o);
    const float rs = rsqrtf(q * (1.0f / C_) + 1e-5f);

    const size_t base = (size_t)row * C_;
    #pragma unroll
    for (int c = 0; c < 6; c++){
        int c4 = lane + c*32;
        float4 gg = g4[c4], bb = b4[c4];
        __half2 p0 = __floats2half2_rn(v[c].x*rs*gg.x + bb.x, v[c].y*rs*gg.y + bb.y);
        __half2 p1 = __floats2half2_rn(v[c].z*rs*gg.z + bb.z, v[c].w*rs*gg.w + bb.w);
        uint2 hh;
        hh.x = *reinterpret_cast<uint32_t*>(&p0);
        hh.y = *reinterpret_cast<uint32_t*>(&p1);
        *reinterpret_cast<uint2*>(oh + base + c4*4) = hh;
    }
}

// ---------------------------------------------------------------------------
// Launch
// ---------------------------------------------------------------------------
extern "C" void kernel_launch(void* const* d_in, const int* in_sizes, int n_in,
                              void* d_out, int out_size) {
    int o = (n_in >= 2 && in_sizes[1] == 1) ? 1 : 0;

    const int*   idx   = (const int*)  d_in[0];
    const float* wte   = (const float*)d_in[1 + o];
    const float* log_c = (const float*)d_in[2 + o];
    const float* v1w   = (const float*)d_in[3 + o];
    const float* v1b   = (const float*)d_in[4 + o];
    const float* v2w   = (const float*)d_in[5 + o];
    const float* v2b   = (const float*)d_in[6 + o];
    const float* v3w   = (const float*)d_in[7 + o];
    const float* v3b   = (const float*)d_in[8 + o];
    const float* ln1g  = (const float*)d_in[9 + o];
    const float* ln1b  = (const float*)d_in[10 + o];
    const float* attnw = (const float*)d_in[11 + o];
    const float* attnb = (const float*)d_in[12 + o];
    const float* projw = (const float*)d_in[13 + o];
    const float* projb = (const float*)d_in[14 + o];
    const float* ln2g  = (const float*)d_in[15 + o];
    const float* ln2b  = (const float*)d_in[16 + o];
    const float* fcw   = (const float*)d_in[17 + o];
    const float* fcb   = (const float*)d_in[18 + o];
    const float* fc2w  = (const float*)d_in[19 + o];
    const float* fc2b  = (const float*)d_in[20 + o];
    const float* lnfg  = (const float*)d_in[21 + o];
    const float* lnfb  = (const float*)d_in[22 + o];

    float *bias, *x;
    bf16 *h_hi, *h_lo, *qkvh, *qkvl, *y_hi, *y_lo, *mlp_hi, *mlp_lo;
    bf16 *wa_hi, *wa_lo, *wp_hi, *wp_lo, *wf_hi, *wf_lo, *wf2_hi, *wf2_lo;
    __half *wteh, *wtel, *hf16;
    cudaGetSymbolAddress((void**)&bias,   g_bias);
    cudaGetSymbolAddress((void**)&x,      g_x);
    cudaGetSymbolAddress((void**)&h_hi,   g_h_hi);   cudaGetSymbolAddress((void**)&h_lo,   g_h_lo);
    cudaGetSymbolAddress((void**)&qkvh,   g_qkvh);   cudaGetSymbolAddress((void**)&qkvl,   g_qkvl);
    cudaGetSymbolAddress((void**)&y_hi,   g_y_hi);   cudaGetSymbolAddress((void**)&y_lo,   g_y_lo);
    cudaGetSymbolAddress((void**)&mlp_hi, g_mlp_hi); cudaGetSymbolAddress((void**)&mlp_lo, g_mlp_lo);
    cudaGetSymbolAddress((void**)&wa_hi,  g_wa_hi);  cudaGetSymbolAddress((void**)&wa_lo,  g_wa_lo);
    cudaGetSymbolAddress((void**)&wp_hi,  g_wp_hi);  cudaGetSymbolAddress((void**)&wp_lo,  g_wp_lo);
    cudaGetSymbolAddress((void**)&wf_hi,  g_wf_hi);  cudaGetSymbolAddress((void**)&wf_lo,  g_wf_lo);
    cudaGetSymbolAddress((void**)&wf2_hi, g_wf2_hi); cudaGetSymbolAddress((void**)&wf2_lo, g_wf2_lo);
    cudaGetSymbolAddress((void**)&wteh,   g_wteh);   cudaGetSymbolAddress((void**)&wtel,   g_wtel);
    cudaGetSymbolAddress((void**)&hf16,   g_hf16);

    // smem sizes per GEMM variant
    const int SM128 = 3*65536 + 1024;            // DT0, BM=128, 3 stages
    const int SM64  = 2*49152 + 1024;            // DT0, BM=64, 2 stages
    const int SMLM  = 3*49152 + 1024;            // DT1, BM=128, 3 stages

    cudaFuncSetAttribute(mma_gemm<0,true ,128,3,0>, cudaFuncAttributeMaxDynamicSharedMemorySize, SM128);
    cudaFuncSetAttribute(mma_gemm<1,true ,128,3,0>, cudaFuncAttributeMaxDynamicSharedMemorySize, SM128);
    cudaFuncSetAttribute(mma_gemm<0,false, 64,2,0>, cudaFuncAttributeMaxDynamicSharedMemorySize, SM64);
    cudaFuncSetAttribute(mma_gemm<0,false,128,3,1>, cudaFuncAttributeMaxDynamicSharedMemorySize, SMLM);
    cudaFuncSetAttribute(flash_kernel,              cudaFuncAttributeMaxDynamicSharedMemorySize, FLASH_SMEM);

    // 1. FIRE bias + embedding + weight prep
    fire_bias_kernel<<<(T_*T_ + 255) / 256, 256>>>(log_c, v1w, v1b, v2w, v2b, v3w, v3b, bias);
    embed_kernel<<<M_, 256>>>(idx, wte, x);
    {
        dim3 tb(32, 8);
        wsplit_t_kernel<<<dim3(3*C_/32,  C_/32,  L_), tb>>>(attnw, wa_hi,  wa_lo,  C_,   3*C_);
        wsplit_t_kernel<<<dim3(C_/32,    C_/32,  L_), tb>>>(projw, wp_hi,  wp_lo,  C_,   C_);
        wsplit_t_kernel<<<dim3(4*C_/32,  C_/32,  L_), tb>>>(fcw,   wf_hi,  wf_lo,  C_,   4*C_);
        wsplit_t_kernel<<<dim3(C_/32,  4*C_/32,  L_), tb>>>(fc2w,  wf2_hi, wf2_lo, 4*C_, C_);
        split_f16_kernel<<<(V_*C_ + 255)/256, 256>>>(wte, wteh, wtel, V_*C_);
    }

    // 2. Transformer layers (grids: x = M-tiles for B-tile L2 reuse)
    const dim3 g_qkvd(M_/128, 3*C_/128);
    const dim3 g_cc64(M_/64,  C_/128);
    const dim3 g_fc  (M_/128, 4*C_/128);
    const dim3 g_fl  (T_/128, B_*H_);

    for (int l = 0; l < L_; l++) {
        size_t wa = (size_t)l*3*C_*C_, wp = (size_t)l*C_*C_, wf = (size_t)l*4*C_*C_;
        ln_kernel<<<M_/8, 256>>>(x, ln1g + (size_t)l*C_, ln1b + (size_t)l*C_, h_hi, h_lo);
        mma_gemm<0,true,128,3,0><<<g_qkvd, 256, SM128>>>(h_hi, h_lo, wa_hi + wa, wa_lo + wa,
                                                         attnb + (size_t)l*3*C_, nullptr,
                                                         nullptr, qkvh, qkvl, 3*C_, C_);
        flash_kernel<<<g_fl, 256, FLASH_SMEM>>>(qkvh, qkvl, bias, y_hi, y_lo);
        mma_gemm<0,false,64,2,0><<<g_cc64, 128, SM64>>>(y_hi, y_lo, wp_hi + wp, wp_lo + wp,
                                                        projb + (size_t)l*C_, x,
                                                        x, nullptr, nullptr, C_, C_);
        ln_kernel<<<M_/8, 256>>>(x, ln2g + (size_t)l*C_, ln2b + (size_t)l*C_, h_hi, h_lo);
        mma_gemm<1,true,128,3,0><<<g_fc, 256, SM128>>>(h_hi, h_lo, wf_hi + wf, wf_lo + wf,
                                                       fcb + (size_t)l*4*C_, nullptr,
                                                       nullptr, mlp_hi, mlp_lo, 4*C_, C_);
        mma_gemm<0,false,64,2,0><<<g_cc64, 128, SM64>>>(mlp_hi, mlp_lo, wf2_hi + wf, wf2_lo + wf,
                                                        fc2b + (size_t)l*C_, x,
                                                        x, nullptr, nullptr, C_, 4*C_);
    }

    // 3. Final LN (fp16) + tied LM head (fp16 2-product, M-fastest grid)
    ln_f16_kernel<<<M_/8, 256>>>(x, lnfg, lnfb, hf16);
    const dim3 g_lm(M_/128, (V_ + 127)/128);
    mma_gemm<0,false,128,3,1><<<g_lm, 256, SMLM>>>(
        (const bf16*)hf16, nullptr, (const bf16*)wteh, (const bf16*)wtel,
        nullptr, nullptr, (float*)d_out, nullptr, nullptr, V_, C_);
}

// round 10
// speedup vs baseline: 6.3324x; 1.0544x over previous
#include <cuda_runtime.h>
#include <cuda_bf16.h>
#include <cuda_fp16.h>
#include <math.h>
#include <stdint.h>

// Problem constants
#define L_ 12
#define H_ 12
#define C_ 768
#define V_ 50257
#define B_ 2
#define T_ 1024
#define D_ 64
#define M_ (B_*T_)   // 2048 rows

typedef __nv_bfloat16 bf16;

// ---------------------------------------------------------------------------
// Scratch (static device globals)
// ---------------------------------------------------------------------------
__device__ float g_bias[T_*T_];
__device__ float g_x   [M_*C_];

__device__ bf16 g_h_hi [M_*C_],    g_h_lo [M_*C_];
__device__ bf16 g_qkvh [M_*3*C_],  g_qkvl [M_*3*C_];
__device__ bf16 g_y_hi [M_*C_],    g_y_lo [M_*C_];
__device__ bf16 g_mlp_hi[M_*4*C_], g_mlp_lo[M_*4*C_];

__device__ bf16 g_wa_hi [L_*3*C_*C_], g_wa_lo [L_*3*C_*C_];
__device__ bf16 g_wp_hi [L_*C_*C_],   g_wp_lo [L_*C_*C_];
__device__ bf16 g_wf_hi [L_*4*C_*C_], g_wf_lo [L_*4*C_*C_];
__device__ bf16 g_wf2_hi[L_*C_*4*C_], g_wf2_lo[L_*C_*4*C_];

// LM head: fp16 planes (2-product path)
__device__ __half g_wteh[(size_t)V_*C_], g_wtel[(size_t)V_*C_];
__device__ __half g_hf16[M_*C_];

// ---------------------------------------------------------------------------
// Helpers
// ---------------------------------------------------------------------------
__device__ __forceinline__ uint32_t smem_u32(const void* p){
    uint32_t a;
    asm("{ .reg .u64 t; cvta.to.shared.u64 t, %1; cvt.u32.u64 %0, t; }":"=r"(a):"l"(p));
    return a;
}
__device__ __forceinline__ void cpa16(uint32_t saddr, const void* gptr){
    asm volatile("cp.async.cg.shared.global [%0], [%1], 16;"::"r"(saddr),"l"(gptr));
}
__device__ __forceinline__ void cpa16z(uint32_t saddr, const void* gptr, int ssz){
    asm volatile("cp.async.cg.shared.global [%0], [%1], 16, %2;"::"r"(saddr),"l"(gptr),"r"(ssz));
}
__device__ __forceinline__ void ldsm4(uint32_t* r, uint32_t addr){
    asm volatile("ldmatrix.sync.aligned.m8n8.x4.shared.b16 {%0,%1,%2,%3}, [%4];"
      : "=r"(r[0]),"=r"(r[1]),"=r"(r[2]),"=r"(r[3]) : "r"(addr));
}
__device__ __forceinline__ void ldsm4t(uint32_t* r, uint32_t addr){
    asm volatile("ldmatrix.sync.aligned.m8n8.x4.trans.shared.b16 {%0,%1,%2,%3}, [%4];"
      : "=r"(r[0]),"=r"(r[1]),"=r"(r[2]),"=r"(r[3]) : "r"(addr));
}
__device__ __forceinline__ void mma16(float* d, const uint32_t* a, uint32_t b0, uint32_t b1){
    asm volatile("mma.sync.aligned.m16n8k16.row.col.f32.bf16.bf16.f32 "
      "{%0,%1,%2,%3}, {%4,%5,%6,%7}, {%8,%9}, {%0,%1,%2,%3};"
      : "+f"(d[0]),"+f"(d[1]),"+f"(d[2]),"+f"(d[3])
      : "r"(a[0]),"r"(a[1]),"r"(a[2]),"r"(a[3]),"r"(b0),"r"(b1));
}
__device__ __forceinline__ void mma16h(float* d, const uint32_t* a, uint32_t b0, uint32_t b1){
    asm volatile("mma.sync.aligned.m16n8k16.row.col.f32.f16.f16.f32 "
      "{%0,%1,%2,%3}, {%4,%5,%6,%7}, {%8,%9}, {%0,%1,%2,%3};"
      : "+f"(d[0]),"+f"(d[1]),"+f"(d[2]),"+f"(d[3])
      : "r"(a[0]),"r"(a[1]),"r"(a[2]),"r"(a[3]),"r"(b0),"r"(b1));
}
__device__ __forceinline__ float exp2a(float x){
    float y; asm("ex2.approx.ftz.f32 %0, %1;":"=f"(y):"f"(x)); return y;
}
__device__ __forceinline__ float rcpa(float x){
    float y; asm("rcp.approx.ftz.f32 %0, %1;":"=f"(y):"f"(x)); return y;
}
// fast exact-ish tanh-GELU: 0.5x(1+tanh(u)) = x - x/(e^{2u}+1)
__device__ __forceinline__ float gelu_f(float v){
    float u = 0.7978845608028654f*(v + 0.044715f*v*v*v);
    float t = exp2a(u * 2.8853900817779268f);     // e^{2u}
    return v - v * rcpa(t + 1.0f);
}
// pack two f32 -> bf16x2 (lower = c0), and residual pack
__device__ __forceinline__ uint32_t packsplit(float c0, float c1, uint32_t& lo){
    uint32_t hi;
    asm("cvt.rn.bf16x2.f32 %0, %1, %2;" : "=r"(hi) : "f"(c1), "f"(c0));
    float h0 = __uint_as_float(hi << 16);
    float h1 = __uint_as_float(hi & 0xffff0000u);
    asm("cvt.rn.bf16x2.f32 %0, %1, %2;" : "=r"(lo) : "f"(c1 - h1), "f"(c0 - h0));
    return hi;
}
#define SWZ(o) ((o) ^ (((o)>>3)&0x70))

// ---------------------------------------------------------------------------
// Split GEMM via mma.m16n8k16, cp.async multi-stage pipeline.
//   DT=0: bf16 planes, 3 products (Ahi,Alo,Bhi,Blo).
//   DT=1: fp16, 2 products, SINGLE A plane (Ahi) x (Bhi,Blo). For LM head.
//   Grid: bm = blockIdx.x*BM_ (M fastest -> B-tile L2 reuse), bn = blockIdx.y*128.
//   BM_=64 / NSTAGE=2 everywhere -> 2 CTAs/SM (occupancy for latency hiding).
// ---------------------------------------------------------------------------
template<int ACT, bool OUTBF, int BM_, int NSTAGE, int DT>
__global__ void __launch_bounds__(BM_*2) mma_gemm(
    const bf16* __restrict__ Ahi, const bf16* __restrict__ Alo,
    const bf16* __restrict__ Bhi, const bf16* __restrict__ Blo,
    const float* __restrict__ bias, const float* __restrict__ resid,
    float* __restrict__ Cf, bf16* __restrict__ Chi, bf16* __restrict__ Clo,
    int Nn, int Kk)
{
    constexpr int T = BM_ * 2;
    constexpr uint32_t ABYTES = BM_ * 128;                        // per A plane
    constexpr uint32_t BOFF   = (DT==0) ? 2*ABYTES : ABYTES;      // B planes base
    constexpr uint32_t STAGE  = BOFF + 32768;
    constexpr int NBIT = 1024 / T;
    constexpr int NAIT = (BM_ * 8) / T;                           // A cp iterations

    extern __shared__ char ds[];
    const uint32_t sb = (smem_u32(ds) + 1023) & ~1023u;

    const int tid = threadIdx.x, lane = tid & 31, wid = tid >> 5;
    const int bm = blockIdx.x * BM_, bn = blockIdx.y * 128;
    const int NT = Kk >> 6;

    auto cp_stage = [&](int t){
        const uint32_t base = sb + (uint32_t)(t % NSTAGE) * STAGE;
        const int k0 = t << 6;
        #pragma unroll
        for (int i = 0; i < NAIT; i++){
            int idx = tid + i*T;
            int r = idx >> 3, c = idx & 7;
            uint32_t off = SWZ((uint32_t)(r*128 + c*16));
            size_t ka = (size_t)(bm + r) * Kk + k0 + c*8;
            cpa16(base + off, Ahi + ka);
            if (DT == 0) cpa16(base + ABYTES + off, Alo + ka);
        }
        #pragma unroll
        for (int i = 0; i < NBIT; i++){
            int idx = tid + i*T;
            int r = idx >> 3, c = idx & 7;
            uint32_t off = SWZ((uint32_t)(r*128 + c*16));
            int gn = bn + r;
            size_t kb = (size_t)gn * Kk + k0 + c*8;
            int ssz = (gn < Nn) ? 16 : 0;
            cpa16z(base + BOFF + off,         Bhi + kb, ssz);
            cpa16z(base + BOFF + 16384 + off, Blo + kb, ssz);
        }
        asm volatile("cp.async.commit_group;":::"memory");
    };

    float acc[2][8][4];
    #pragma unroll
    for (int a=0;a<2;a++) for (int b=0;b<8;b++) for (int c=0;c<4;c++) acc[a][b][c]=0.f;

    const int m0 = (wid >> 1) * 32, n0 = (wid & 1) * 64;
    const uint32_t arow = (uint32_t)(m0 + (lane & 15));
    const uint32_t acol = (uint32_t)((lane >> 4) * 16);
    const uint32_t brow = (uint32_t)(n0 + (lane & 7) + ((lane >> 4) & 1) * 8);
    const uint32_t bcol = (uint32_t)(((lane >> 3) & 1) * 16);

    auto compute = [&](int t){
        const uint32_t base = sb + (uint32_t)(t % NSTAGE) * STAGE;
        #pragma unroll
        for (int ks = 0; ks < 4; ks++){
            const uint32_t kb2 = (uint32_t)(ks * 32);
            uint32_t ah[2][4], al[2][4];
            #pragma unroll
            for (int mt = 0; mt < 2; mt++){
                uint32_t off = SWZ((arow + mt*16)*128 + kb2 + acol);
                ldsm4(ah[mt], base + off);
                if (DT == 0) ldsm4(al[mt], base + ABYTES + off);
            }
            #pragma unroll
            for (int g = 0; g < 4; g++){
                uint32_t off = SWZ((brow + g*16)*128 + kb2 + bcol);
                uint32_t bh[4], bl[4];
                ldsm4(bh, base + BOFF + off);
                ldsm4(bl, base + BOFF + 16384 + off);
                #pragma unroll
                for (int mt = 0; mt < 2; mt++){
                    #pragma unroll
                    for (int sub = 0; sub < 2; sub++){
                        float* d = acc[mt][g*2 + sub];
                        if (DT == 0){
                            mma16(d, ah[mt], bh[sub*2], bh[sub*2+1]);
                            mma16(d, ah[mt], bl[sub*2], bl[sub*2+1]);
                            mma16(d, al[mt], bh[sub*2], bh[sub*2+1]);
                        } else {
                            mma16h(d, ah[mt], bh[sub*2], bh[sub*2+1]);
                            mma16h(d, ah[mt], bl[sub*2], bl[sub*2+1]);
                        }
                    }
                }
            }
        }
    };

    cp_stage(0);
    if (NT > 1) cp_stage(1);
    for (int t = 0; t < NT; t++){
        if (t + 1 < NT) asm volatile("cp.async.wait_group 1;":::"memory");
        else            asm volatile("cp.async.wait_group 0;":::"memory");
        __syncthreads();
        compute(t);
        if (NSTAGE == 2) __syncthreads();
        if (t + 2 < NT) cp_stage(t + 2);
    }

    #pragma unroll
    for (int mt = 0; mt < 2; mt++){
        #pragma unroll
        for (int h2 = 0; h2 < 2; h2++){
            int row = bm + m0 + mt*16 + (lane>>2) + h2*8;
            float* crow = OUTBF ? nullptr : (Cf + (size_t)row * Nn);
            const float* rrow = resid ? resid + (size_t)row * Nn : nullptr;
            #pragma unroll
            for (int nt = 0; nt < 8; nt++){
                int col = bn + n0 + nt*8 + (lane&3)*2;
                if (col >= Nn) continue;
                float v0 = acc[mt][nt][h2*2+0];
                float v1 = acc[mt][nt][h2*2+1];
                bool has1 = (col + 1 < Nn);
                if (bias){ v0 += bias[col]; if (has1) v1 += bias[col+1]; }
                if (ACT == 1){ v0 = gelu_f(v0); v1 = gelu_f(v1); }
                if (rrow){ v0 += rrow[col]; if (has1) v1 += rrow[col+1]; }
                if (OUTBF){
                    size_t o = (size_t)row * Nn + col;
                    uint32_t lo2, hi2 = packsplit(v0, v1, lo2);
                    *reinterpret_cast<uint32_t*>(Chi + o) = hi2;
                    *reinterpret_cast<uint32_t*>(Clo + o) = lo2;
                } else if (((Nn & 1) == 0) && has1){
                    float2 st; st.x = v0; st.y = v1;
                    *reinterpret_cast<float2*>(crow + col) = st;
                } else {
                    crow[col] = v0;
                    if (has1) crow[col + 1] = v1;
                }
            }
        }
    }
}

// ---------------------------------------------------------------------------
// FlashAttention: one block = 128 q-rows x one (b,h).
// ---------------------------------------------------------------------------
#define FLASH_SMEM (163840 + 1024)

__global__ void __launch_bounds__(256) flash_kernel(
    const bf16* __restrict__ qkvh, const bf16* __restrict__ qkvl,
    const float* __restrict__ bias2,
    bf16* __restrict__ yhi, bf16* __restrict__ ylo)
{
    extern __shared__ char ds[];
    const uint32_t sb = (smem_u32(ds) + 1023) & ~1023u;
    const uint32_t sQh = sb, sQl = sb + 16384;

    const int tid = threadIdx.x, lane = tid & 31, w = tid >> 5;
    const int bh = blockIdx.y, b = bh / H_, h = bh % H_;
    const int i0 = (int)(gridDim.x - 1 - blockIdx.x) * 128;
    const int nj = (i0 >> 7) + 1;

    const bf16* qh = qkvh + (size_t)b * T_ * 3 * C_ + h * D_;
    const bf16* ql = qkvl + (size_t)b * T_ * 3 * C_ + h * D_;
    const bf16* kh = qh + C_,   * kl = ql + C_;
    const bf16* vh = qh + 2*C_, * vl = ql + 2*C_;

    auto cp_q = [&](){
        #pragma unroll
        for (int i = 0; i < 4; i++){
            int idx = tid + i*256;
            int r = idx >> 3, c = idx & 7;
            uint32_t off = SWZ((uint32_t)(r*128 + c*16));
            size_t g = (size_t)(i0 + r) * 3 * C_ + c*8;
            cpa16(sQh + off, qh + g);
            cpa16(sQl + off, ql + g);
        }
    };
    auto cp_kv = [&](int jt){
        int st = jt & 1, j0 = jt << 7;
        uint32_t kb = sb + 32768 + (uint32_t)st * 32768;
        uint32_t vb = sb + 98304 + (uint32_t)st * 32768;
        #pragma unroll
        for (int i = 0; i < 4; i++){
            int idx = tid + i*256;
            int r = idx >> 3, c = idx & 7;
            uint32_t off = SWZ((uint32_t)(r*128 + c*16));
            size_t g = (size_t)(j0 + r) * 3 * C_ + c*8;
            cpa16(kb + off,         kh + g);
            cpa16(kb + 16384 + off, kl + g);
            cpa16(vb + off,         vh + g);
            cpa16(vb + 16384 + off, vl + g);
        }
        asm volatile("cp.async.commit_group;":::"memory");
    };

    cp_q(); cp_kv(0);
    if (nj > 1) cp_kv(1);
    if (nj > 1) asm volatile("cp.async.wait_group 1;":::"memory");
    else        asm volatile("cp.async.wait_group 0;":::"memory");
    __syncthreads();

    uint32_t qfh[4][4], qfl[4][4];
    {
        uint32_t arow = (uint32_t)(w*16 + (lane & 15));
        uint32_t acol = (uint32_t)((lane >> 4) * 16);
        #pragma unroll
        for (int kt = 0; kt < 4; kt++){
            uint32_t off = SWZ(arow*128 + (uint32_t)kt*32 + acol);
            ldsm4(qfh[kt], sQh + off);
            ldsm4(qfl[kt], sQl + off);
        }
    }

    float O[8][4];
    #pragma unroll
    for (int i=0;i<8;i++) for (int j=0;j<4;j++) O[i][j]=0.f;
    float mr0 = -INFINITY, mr1 = -INFINITY, l0 = 0.f, l1 = 0.f;

    const float SC = 0.125f * 1.4426950408889634f;
    const uint32_t brow = (uint32_t)((lane & 7) + ((lane >> 4) & 1) * 8);
    const uint32_t bcol = (uint32_t)(((lane >> 3) & 1) * 16);
    const uint32_t vrow = (uint32_t)((lane & 7) + ((lane >> 3) & 1) * 8);
    const uint32_t vcol = (uint32_t)((lane >> 4) * 16);

    for (int jt = 0; jt < nj; jt++){
        const int st = jt & 1, j0 = jt << 7;
        const uint32_t kb = sb + 32768 + (uint32_t)st * 32768;
        const uint32_t vb = sb + 98304 + (uint32_t)st * 32768;

        float S[16][4];
        #pragma unroll
        for (int i=0;i<16;i++) for (int j=0;j<4;j++) S[i][j]=0.f;
        #pragma unroll
        for (int kt = 0; kt < 4; kt++){
            const uint32_t kb2 = (uint32_t)kt * 32;
            #pragma unroll
            for (int g = 0; g < 8; g++){
                uint32_t off = SWZ((brow + g*16)*128 + kb2 + bcol);
                uint32_t kh4[4], kl4[4];
                ldsm4(kh4, kb + off);
                ldsm4(kl4, kb + 16384 + off);
                #pragma unroll
                for (int sub = 0; sub < 2; sub++){
                    float* d = S[g*2 + sub];
                    mma16(d, qfh[kt], kh4[sub*2], kh4[sub*2+1]);
                    mma16(d, qfh[kt], kl4[sub*2], kl4[sub*2+1]);
                    mma16(d, qfl[kt], kh4[sub*2], kh4[sub*2+1]);
                }
            }
        }

        {
            int gi = i0 + w*16 + (lane >> 2);
            int gjb = j0 + (lane & 3) * 2;
            const float* b0 = bias2 + (size_t)gi * T_ + gjb;
            const float* b1 = bias2 + (size_t)(gi + 8) * T_ + gjb;
            #pragma unroll
            for (int nt = 0; nt < 16; nt++){
                float2 ba = *reinterpret_cast<const float2*>(b0 + nt*8);
                float2 bb = *reinterpret_cast<const float2*>(b1 + nt*8);
                S[nt][0] = S[nt][0]*SC + ba.x;
                S[nt][1] = S[nt][1]*SC + ba.y;
                S[nt][2] = S[nt][2]*SC + bb.x;
                S[nt][3] = S[nt][3]*SC + bb.y;
            }
        }

        float mn0 = mr0, mn1 = mr1;
        #pragma unroll
        for (int nt = 0; nt < 16; nt++){
            mn0 = fmaxf(mn0, fmaxf(S[nt][0], S[nt][1]));
            mn1 = fmaxf(mn1, fmaxf(S[nt][2], S[nt][3]));
        }
        mn0 = fmaxf(mn0, __shfl_xor_sync(0xffffffffu, mn0, 1));
        mn0 = fmaxf(mn0, __shfl_xor_sync(0xffffffffu, mn0, 2));
        mn1 = fmaxf(mn1, __shfl_xor_sync(0xffffffffu, mn1, 1));
        mn1 = fmaxf(mn1, __shfl_xor_sync(0xffffffffu, mn1, 2));
        float sc0 = exp2a(mr0 - mn0), sc1 = exp2a(mr1 - mn1);
        mr0 = mn0; mr1 = mn1;
        float rs0 = 0.f, rs1 = 0.f;
        #pragma unroll
        for (int nt = 0; nt < 16; nt++){
            S[nt][0] = exp2a(S[nt][0] - mn0);
            S[nt][1] = exp2a(S[nt][1] - mn0);
            S[nt][2] = exp2a(S[nt][2] - mn1);
            S[nt][3] = exp2a(S[nt][3] - mn1);
            rs0 += S[nt][0] + S[nt][1];
            rs1 += S[nt][2] + S[nt][3];
        }
        rs0 += __shfl_xor_sync(0xffffffffu, rs0, 1);
        rs0 += __shfl_xor_sync(0xffffffffu, rs0, 2);
        rs1 += __shfl_xor_sync(0xffffffffu, rs1, 1);
        rs1 += __shfl_xor_sync(0xffffffffu, rs1, 2);
        l0 = l0 * sc0 + rs0;
        l1 = l1 * sc1 + rs1;
        #pragma unroll
        for (int nt = 0; nt < 8; nt++){
            O[nt][0] *= sc0; O[nt][1] *= sc0;
            O[nt][2] *= sc1; O[nt][3] *= sc1;
        }

        #pragma unroll
        for (int g = 0; g < 8; g++){
            uint32_t pah[4], pal[4];
            pah[0] = packsplit(S[2*g  ][0], S[2*g  ][1], pal[0]);
            pah[1] = packsplit(S[2*g  ][2], S[2*g  ][3], pal[1]);
            pah[2] = packsplit(S[2*g+1][0], S[2*g+1][1], pal[2]);
            pah[3] = packsplit(S[2*g+1][2], S[2*g+1][3], pal[3]);
            #pragma unroll
            for (int dv = 0; dv < 4; dv++){
                uint32_t off = SWZ((vrow + g*16)*128 + (uint32_t)dv*32 + vcol);
                uint32_t vh4[4], vl4[4];
                ldsm4t(vh4, vb + off);
                ldsm4t(vl4, vb + 16384 + off);
                #pragma unroll
                for (int sub = 0; sub < 2; sub++){
                    float* d = O[dv*2 + sub];
                    mma16(d, pah, vh4[sub*2], vh4[sub*2+1]);
                    mma16(d, pah, vl4[sub*2], vl4[sub*2+1]);
                    mma16(d, pal, vh4[sub*2], vh4[sub*2+1]);
                }
            }
        }

        __syncthreads();
        if (jt + 2 < nj) cp_kv(jt + 2);
        if (jt + 1 < nj){
            if (jt + 2 < nj) asm volatile("cp.async.wait_group 1;":::"memory");
            else             asm volatile("cp.async.wait_group 0;":::"memory");
            __syncthreads();
        }
    }

    float li0 = 1.f / l0, li1 = 1.f / l1;
    int r0 = i0 + w*16 + (lane >> 2);
    size_t base0 = (size_t)b * T_ * C_ + (size_t)r0 * C_ + h * D_;
    size_t base1 = base0 + (size_t)8 * C_;
    #pragma unroll
    for (int nt = 0; nt < 8; nt++){
        int col = nt*8 + (lane & 3)*2;
        uint32_t lo2, hi2;
        hi2 = packsplit(O[nt][0]*li0, O[nt][1]*li0, lo2);
        *reinterpret_cast<uint32_t*>(yhi + base0 + col) = hi2;
        *reinterpret_cast<uint32_t*>(ylo + base0 + col) = lo2;
        hi2 = packsplit(O[nt][2]*li1, O[nt][3]*li1, lo2);
        *reinterpret_cast<uint32_t*>(yhi + base1 + col) = hi2;
        *reinterpret_cast<uint32_t*>(ylo + base1 + col) = lo2;
    }
}

// ---------------------------------------------------------------------------
// Weight prep
// ---------------------------------------------------------------------------
__device__ __forceinline__ void bsplit(float v, bf16& h, bf16& l){
    h = __float2bfloat16(v);
    l = __float2bfloat16(v - __bfloat162float(h));
}

__global__ void wsplit_t_kernel(const float* __restrict__ in,
                                bf16* __restrict__ ohi, bf16* __restrict__ olo,
                                int K, int N){
    __shared__ float t[32][33];
    size_t lb = (size_t)blockIdx.z * K * N;
    const float* inp = in + lb;
    int kb = blockIdx.y*32, nb = blockIdx.x*32;
    int tx = threadIdx.x, ty = threadIdx.y;
    #pragma unroll
    for (int j = 0; j < 4; j++)
        t[ty + 8*j][tx] = inp[(size_t)(kb + ty + 8*j) * N + nb + tx];
    __syncthreads();
    #pragma unroll
    for (int j = 0; j < 4; j++){
        int n = nb + ty + 8*j, k = kb + tx;
        float v = t[tx][ty + 8*j];
        bf16 h, l; bsplit(v, h, l);
        size_t o = lb + (size_t)n * K + k;
        ohi[o] = h; olo[o] = l;
    }
}

// fp16 split for wte
__global__ void split_f16_kernel(const float* __restrict__ in,
                                 __half* __restrict__ ohi, __half* __restrict__ olo, int n){
    int i = blockIdx.x * 256 + threadIdx.x;
    if (i < n){
        float v = in[i];
        __half h = __float2half_rn(v);
        ohi[i] = h;
        olo[i] = __float2half_rn(v - __half2float(h));
    }
}

// ---------------------------------------------------------------------------
// FIRE bias (pre-scaled by log2e)
// ---------------------------------------------------------------------------
__global__ void fire_bias_kernel(const float* __restrict__ log_c,
                                 const float* __restrict__ v1w, const float* __restrict__ v1b,
                                 const float* __restrict__ v2w, const float* __restrict__ v2b,
                                 const float* __restrict__ v3w, const float* __restrict__ v3b,
                                 float* __restrict__ bias) {
    __shared__ float s1w[32], s1b[32], s2w[1024], s2b[32], s3w[32];
    __shared__ float s3b, sc;
    int tid = threadIdx.x;
    if (tid < 32) { s1w[tid] = v1w[tid]; s1b[tid] = v1b[tid]; s2b[tid] = v2b[tid]; s3w[tid] = v3w[tid]; }
    for (int i = tid; i < 1024; i += blockDim.x) s2w[i] = v2w[i];
    if (tid == 0) { s3b = v3b[0]; sc = expf(log_c[0]); }
    __syncthreads();

    int idx = blockIdx.x * blockDim.x + tid;
    if (idx >= T_*T_) return;
    int i = idx / T_, j = idx % T_;
    if (j > i) { bias[idx] = -1e30f; return; }

    float c = sc;
    float fi = (float)(i + 1), fj = (float)(j + 1);
    float pv = logf(c * (fi - fj) + 1.0f) / logf(c * fi + 1.0f);

    float h1[32];
    #pragma unroll
    for (int k = 0; k < 32; k++) h1[k] = fmaxf(pv * s1w[k] + s1b[k], 0.f);
    float out = s3b;
    #pragma unroll
    for (int k2 = 0; k2 < 32; k2++) {
        float a = s2b[k2];
        #pragma unroll
        for (int k1 = 0; k1 < 32; k1++) a += h1[k1] * s2w[k1*32 + k2];
        out += fmaxf(a, 0.f) * s3w[k2];
    }
    bias[idx] = out * 1.4426950408889634f;
}

// ---------------------------------------------------------------------------
// Embedding gather
// ---------------------------------------------------------------------------
__global__ void embed_kernel(const int* __restrict__ idx, const float* __restrict__ wte,
                             float* __restrict__ x) {
    int row = blockIdx.x;
    const float* src = wte + (size_t)idx[row] * C_;
    float* dst = x + (size_t)row * C_;
    for (int c = threadIdx.x; c < C_; c += blockDim.x) dst[c] = src[c];
}

// ---------------------------------------------------------------------------
// LayerNorm: warp-per-row -> bf16 hi/lo planes
// ---------------------------------------------------------------------------
__global__ void __launch_bounds__(256) ln_kernel(
    const float* __restrict__ x, const float* __restrict__ g,
    const float* __restrict__ b,
    bf16* __restrict__ ohi, bf16* __restrict__ olo) {
    const int wid = threadIdx.x >> 5, lane = threadIdx.x & 31;
    const int row = blockIdx.x * 8 + wid;
    const float4* xr = reinterpret_cast<const float4*>(x + (size_t)row * C_);
    const float4* g4 = reinterpret_cast<const float4*>(g);
    const float4* b4 = reinterpret_cast<const float4*>(b);

    float4 v[6];
    float s = 0.f;
    #pragma unroll
    for (int c = 0; c < 6; c++){
        v[c] = xr[lane + c*32];
        s += v[c].x + v[c].y + v[c].z + v[c].w;
    }
    #pragma unroll
    for (int o = 16; o > 0; o >>= 1) s += __shfl_xor_sync(0xffffffffu, s, o);
    const float mean = s * (1.0f / C_);

    float q = 0.f;
    #pragma unroll
    for (int c = 0; c < 6; c++){
        v[c].x -= mean; v[c].y -= mean; v[c].z -= mean; v[c].w -= mean;
        q += v[c].x*v[c].x + v[c].y*v[c].y + v[c].z*v[c].z + v[c].w*v[c].w;
    }
    #pragma unroll
    for (int o = 16; o > 0; o >>= 1) q += __shfl_xor_sync(0xffffffffu, q, o);
    const float rs = rsqrtf(q * (1.0f / C_) + 1e-5f);

    const size_t base = (size_t)row * C_;
    #pragma unroll
    for (int c = 0; c < 6; c++){
        int c4 = lane + c*32;
        float4 gg = g4[c4], bb = b4[c4];
        float o0 = v[c].x*rs*gg.x + bb.x;
        float o1 = v[c].y*rs*gg.y + bb.y;
        float o2 = v[c].z*rs*gg.z + bb.z;
        float o3 = v[c].w*rs*gg.w + bb.w;
        uint32_t lo01, lo23;
        uint32_t hi01 = packsplit(o0, o1, lo01);
        uint32_t hi23 = packsplit(o2, o3, lo23);
        uint2 hh; hh.x = hi01; hh.y = hi23;
        uint2 ll; ll.x = lo01; ll.y = lo23;
        *reinterpret_cast<uint2*>(ohi + base + c4*4) = hh;
        *reinterpret_cast<uint2*>(olo + base + c4*4) = ll;
    }
}

// Final LayerNorm -> single fp16 plane (for 2-product LM head)
__global__ void __launch_bounds__(256) ln_f16_kernel(
    const float* __restrict__ x, const float* __restrict__ g,
    const float* __restrict__ b, __half* __restrict__ oh) {
    const int wid = threadIdx.x >> 5, lane = threadIdx.x & 31;
    const int row = blockIdx.x * 8 + wid;
    const float4* xr = reinterpret_cast<const float4*>(x + (size_t)row * C_);
    const float4* g4 = reinterpret_cast<const float4*>(g);
    const float4* b4 = reinterpret_cast<const float4*>(b);

    float4 v[6];
    float s = 0.f;
    #pragma unroll
    for (int c = 0; c < 6; c++){
        v[c] = xr[lane + c*32];
        s += v[c].x + v[c].y + v[c].z + v[c].w;
    }
    #pragma unroll
    for (int o = 16; o > 0; o >>= 1) s += __shfl_xor_sync(0xffffffffu, s, o);
    const float mean = s * (1.0f / C_);

    float q = 0.f;
    #pragma unroll
    for (int c = 0; c < 6; c++){
        v[c].x -= mean; v[c].y -= mean; v[c].z -= mean; v[c].w -= mean;
        q += v[c].x*v[c].x + v[c].y*v[c].y + v[c].z*v[c].z + v[c].w*v[c].w;
    }
    #pragma unroll
    for (int o = 16; o > 0; o >>= 1) q += __shfl_xor_sync(0xffffffffu, q, o);
    const float rs = rsqrtf(q * (1.0f / C_) + 1e-5f);

    const size_t base = (size_t)row * C_;
    #pragma unroll
    for (int c = 0; c < 6; c++){
        int c4 = lane + c*32;
        float4 gg = g4[c4], bb = b4[c4];
        __half2 p0 = __floats2half2_rn(v[c].x*rs*gg.x + bb.x, v[c].y*rs*gg.y + bb.y);
        __half2 p1 = __floats2half2_rn(v[c].z*rs*gg.z + bb.z, v[c].w*rs*gg.w + bb.w);
        uint2 hh;
        hh.x = *reinterpret_cast<uint32_t*>(&p0);
        hh.y = *reinterpret_cast<uint32_t*>(&p1);
        *reinterpret_cast<uint2*>(oh + base + c4*4) = hh;
    }
}

// ---------------------------------------------------------------------------
// Launch
// ---------------------------------------------------------------------------
extern "C" void kernel_launch(void* const* d_in, const int* in_sizes, int n_in,
                              void* d_out, int out_size) {
    int o = (n_in >= 2 && in_sizes[1] == 1) ? 1 : 0;

    const int*   idx   = (const int*)  d_in[0];
    const float* wte   = (const float*)d_in[1 + o];
    const float* log_c = (const float*)d_in[2 + o];
    const float* v1w   = (const float*)d_in[3 + o];
    const float* v1b   = (const float*)d_in[4 + o];
    const float* v2w   = (const float*)d_in[5 + o];
    const float* v2b   = (const float*)d_in[6 + o];
    const float* v3w   = (const float*)d_in[7 + o];
    const float* v3b   = (const float*)d_in[8 + o];
    const float* ln1g  = (const float*)d_in[9 + o];
    const float* ln1b  = (const float*)d_in[10 + o];
    const float* attnw = (const float*)d_in[11 + o];
    const float* attnb = (const float*)d_in[12 + o];
    const float* projw = (const float*)d_in[13 + o];
    const float* projb = (const float*)d_in[14 + o];
    const float* ln2g  = (const float*)d_in[15 + o];
    const float* ln2b  = (const float*)d_in[16 + o];
    const float* fcw   = (const float*)d_in[17 + o];
    const float* fcb   = (const float*)d_in[18 + o];
    const float* fc2w  = (const float*)d_in[19 + o];
    const float* fc2b  = (const float*)d_in[20 + o];
    const float* lnfg  = (const float*)d_in[21 + o];
    const float* lnfb  = (const float*)d_in[22 + o];

    float *bias, *x;
    bf16 *h_hi, *h_lo, *qkvh, *qkvl, *y_hi, *y_lo, *mlp_hi, *mlp_lo;
    bf16 *wa_hi, *wa_lo, *wp_hi, *wp_lo, *wf_hi, *wf_lo, *wf2_hi, *wf2_lo;
    __half *wteh, *wtel, *hf16;
    cudaGetSymbolAddress((void**)&bias,   g_bias);
    cudaGetSymbolAddress((void**)&x,      g_x);
    cudaGetSymbolAddress((void**)&h_hi,   g_h_hi);   cudaGetSymbolAddress((void**)&h_lo,   g_h_lo);
    cudaGetSymbolAddress((void**)&qkvh,   g_qkvh);   cudaGetSymbolAddress((void**)&qkvl,   g_qkvl);
    cudaGetSymbolAddress((void**)&y_hi,   g_y_hi);   cudaGetSymbolAddress((void**)&y_lo,   g_y_lo);
    cudaGetSymbolAddress((void**)&mlp_hi, g_mlp_hi); cudaGetSymbolAddress((void**)&mlp_lo, g_mlp_lo);
    cudaGetSymbolAddress((void**)&wa_hi,  g_wa_hi);  cudaGetSymbolAddress((void**)&wa_lo,  g_wa_lo);
    cudaGetSymbolAddress((void**)&wp_hi,  g_wp_hi);  cudaGetSymbolAddress((void**)&wp_lo,  g_wp_lo);
    cudaGetSymbolAddress((void**)&wf_hi,  g_wf_hi);  cudaGetSymbolAddress((void**)&wf_lo,  g_wf_lo);
    cudaGetSymbolAddress((void**)&wf2_hi, g_wf2_hi); cudaGetSymbolAddress((void**)&wf2_lo, g_wf2_lo);
    cudaGetSymbolAddress((void**)&wteh,   g_wteh);   cudaGetSymbolAddress((void**)&wtel,   g_wtel);
    cudaGetSymbolAddress((void**)&hf16,   g_hf16);

    // smem sizes: BM=64 variants, all 2 CTAs/SM
    const int SM64  = 2*49152 + 1024;   // DT0: stage = 16K(A) + 32K(B)
    const int SMLM  = 2*40960 + 1024;   // DT1: stage =  8K(A) + 32K(B)

    cudaFuncSetAttribute(mma_gemm<0,true , 64,2,0>, cudaFuncAttributeMaxDynamicSharedMemorySize, SM64);
    cudaFuncSetAttribute(mma_gemm<1,true , 64,2,0>, cudaFuncAttributeMaxDynamicSharedMemorySize, SM64);
    cudaFuncSetAttribute(mma_gemm<0,false, 64,2,0>, cudaFuncAttributeMaxDynamicSharedMemorySize, SM64);
    cudaFuncSetAttribute(mma_gemm<0,false, 64,2,1>, cudaFuncAttributeMaxDynamicSharedMemorySize, SMLM);
    cudaFuncSetAttribute(flash_kernel,              cudaFuncAttributeMaxDynamicSharedMemorySize, FLASH_SMEM);

    // 1. FIRE bias + embedding + weight prep
    fire_bias_kernel<<<(T_*T_ + 255) / 256, 256>>>(log_c, v1w, v1b, v2w, v2b, v3w, v3b, bias);
    embed_kernel<<<M_, 256>>>(idx, wte, x);
    {
        dim3 tb(32, 8);
        wsplit_t_kernel<<<dim3(3*C_/32,  C_/32,  L_), tb>>>(attnw, wa_hi,  wa_lo,  C_,   3*C_);
        wsplit_t_kernel<<<dim3(C_/32,    C_/32,  L_), tb>>>(projw, wp_hi,  wp_lo,  C_,   C_);
        wsplit_t_kernel<<<dim3(4*C_/32,  C_/32,  L_), tb>>>(fcw,   wf_hi,  wf_lo,  C_,   4*C_);
        wsplit_t_kernel<<<dim3(C_/32,  4*C_/32,  L_), tb>>>(fc2w,  wf2_hi, wf2_lo, 4*C_, C_);
        split_f16_kernel<<<(V_*C_ + 255)/256, 256>>>(wte, wteh, wtel, V_*C_);
    }

    // 2. Transformer layers (grids: x = M-tiles for B-tile L2 reuse)
    const dim3 g_qkvd(M_/64, 3*C_/128);
    const dim3 g_cc64(M_/64, C_/128);
    const dim3 g_fc  (M_/64, 4*C_/128);
    const dim3 g_fl  (T_/128, B_*H_);

    for (int l = 0; l < L_; l++) {
        size_t wa = (size_t)l*3*C_*C_, wp = (size_t)l*C_*C_, wf = (size_t)l*4*C_*C_;
        ln_kernel<<<M_/8, 256>>>(x, ln1g + (size_t)l*C_, ln1b + (size_t)l*C_, h_hi, h_lo);
        mma_gemm<0,true,64,2,0><<<g_qkvd, 128, SM64>>>(h_hi, h_lo, wa_hi + wa, wa_lo + wa,
                                                       attnb + (size_t)l*3*C_, nullptr,
                                                       nullptr, qkvh, qkvl, 3*C_, C_);
        flash_kernel<<<g_fl, 256, FLASH_SMEM>>>(qkvh, qkvl, bias, y_hi, y_lo);
        mma_gemm<0,false,64,2,0><<<g_cc64, 128, SM64>>>(y_hi, y_lo, wp_hi + wp, wp_lo + wp,
                                                        projb + (size_t)l*C_, x,
                                                        x, nullptr, nullptr, C_, C_);
        ln_kernel<<<M_/8, 256>>>(x, ln2g + (size_t)l*C_, ln2b + (size_t)l*C_, h_hi, h_lo);
        mma_gemm<1,true,64,2,0><<<g_fc, 128, SM64>>>(h_hi, h_lo, wf_hi + wf, wf_lo + wf,
                                                     fcb + (size_t)l*4*C_, nullptr,
                                                     nullptr, mlp_hi, mlp_lo, 4*C_, C_);
        mma_gemm<0,false,64,2,0><<<g_cc64, 128, SM64>>>(mlp_hi, mlp_lo, wf2_hi + wf, wf2_lo + wf,
                                                        fc2b + (size_t)l*C_, x,
                                                        x, nullptr, nullptr, C_, 4*C_);
    }

    // 3. Final LN (fp16) + tied LM head (fp16 2-product, BM=64, 2 CTAs/SM)
    ln_f16_kernel<<<M_/8, 256>>>(x, lnfg, lnfb, hf16);
    const dim3 g_lm(M_/64, (V_ + 127)/128);
    mma_gemm<0,false,64,2,1><<<g_lm, 128, SMLM>>>(
        (const bf16*)hf16, nullptr, (const bf16*)wteh, (const bf16*)wtel,
        nullptr, nullptr, (float*)d_out, nullptr, nullptr, V_, C_);
}

// round 11
// speedup vs baseline: 8.4768x; 1.3386x over previous
#include <cuda_runtime.h>
#include <cuda_bf16.h>
#include <cuda_fp16.h>
#include <math.h>
#include <stdint.h>

// Problem constants
#define L_ 12
#define H_ 12
#define C_ 768
#define V_ 50257
#define B_ 2
#define T_ 1024
#define D_ 64
#define M_ (B_*T_)   // 2048 rows

// ---------------------------------------------------------------------------
// Scratch (static device globals) — all-fp16 pipeline
// ---------------------------------------------------------------------------
__device__ float g_bias[T_*T_];
__device__ float g_x   [M_*C_];

__device__ __half g_h16 [M_*C_];       // LN outputs
__device__ __half g_qkv16[M_*3*C_];
__device__ __half g_y16 [M_*C_];
__device__ __half g_mlp16[M_*4*C_];

__device__ __half g_wa_h [L_*3*C_*C_], g_wa_l [L_*3*C_*C_];
__device__ __half g_wp_h [L_*C_*C_],   g_wp_l [L_*C_*C_];
__device__ __half g_wf_h [L_*4*C_*C_], g_wf_l [L_*4*C_*C_];
__device__ __half g_wf2_h[L_*C_*4*C_], g_wf2_l[L_*C_*4*C_];
__device__ __half g_wteh[(size_t)V_*C_], g_wtel[(size_t)V_*C_];

// ---------------------------------------------------------------------------
// Helpers
// ---------------------------------------------------------------------------
__device__ __forceinline__ uint32_t smem_u32(const void* p){
    uint32_t a;
    asm("{ .reg .u64 t; cvta.to.shared.u64 t, %1; cvt.u32.u64 %0, t; }":"=r"(a):"l"(p));
    return a;
}
__device__ __forceinline__ void cpa16(uint32_t saddr, const void* gptr){
    asm volatile("cp.async.cg.shared.global [%0], [%1], 16;"::"r"(saddr),"l"(gptr));
}
__device__ __forceinline__ void cpa16z(uint32_t saddr, const void* gptr, int ssz){
    asm volatile("cp.async.cg.shared.global [%0], [%1], 16, %2;"::"r"(saddr),"l"(gptr),"r"(ssz));
}
__device__ __forceinline__ void ldsm4(uint32_t* r, uint32_t addr){
    asm volatile("ldmatrix.sync.aligned.m8n8.x4.shared.b16 {%0,%1,%2,%3}, [%4];"
      : "=r"(r[0]),"=r"(r[1]),"=r"(r[2]),"=r"(r[3]) : "r"(addr));
}
__device__ __forceinline__ void ldsm4t(uint32_t* r, uint32_t addr){
    asm volatile("ldmatrix.sync.aligned.m8n8.x4.trans.shared.b16 {%0,%1,%2,%3}, [%4];"
      : "=r"(r[0]),"=r"(r[1]),"=r"(r[2]),"=r"(r[3]) : "r"(addr));
}
__device__ __forceinline__ void mma16h(float* d, const uint32_t* a, uint32_t b0, uint32_t b1){
    asm volatile("mma.sync.aligned.m16n8k16.row.col.f32.f16.f16.f32 "
      "{%0,%1,%2,%3}, {%4,%5,%6,%7}, {%8,%9}, {%0,%1,%2,%3};"
      : "+f"(d[0]),"+f"(d[1]),"+f"(d[2]),"+f"(d[3])
      : "r"(a[0]),"r"(a[1]),"r"(a[2]),"r"(a[3]),"r"(b0),"r"(b1));
}
__device__ __forceinline__ float exp2a(float x){
    float y; asm("ex2.approx.ftz.f32 %0, %1;":"=f"(y):"f"(x)); return y;
}
__device__ __forceinline__ float rcpa(float x){
    float y; asm("rcp.approx.ftz.f32 %0, %1;":"=f"(y):"f"(x)); return y;
}
// fast exact-ish tanh-GELU: 0.5x(1+tanh(u)) = x - x/(e^{2u}+1)
__device__ __forceinline__ float gelu_f(float v){
    float u = 0.7978845608028654f*(v + 0.044715f*v*v*v);
    float t = exp2a(u * 2.8853900817779268f);     // e^{2u}
    return v - v * rcpa(t + 1.0f);
}
// pack two f32 -> f16x2 (lower = c0)
__device__ __forceinline__ uint32_t packh2(float c0, float c1){
    uint32_t r; asm("cvt.rn.f16x2.f32 %0, %1, %2;" : "=r"(r) : "f"(c1), "f"(c0));
    return r;
}
#define SWZ(o) ((o) ^ (((o)>>3)&0x70))

// ---------------------------------------------------------------------------
// FP16 2-product GEMM: C = act(A @ (Bh+Bl)^T + bias) (+resid)
//   A: [M,K] fp16 single plane.  Bh/Bl: [N,K] fp16 hi/lo planes.
//   BM=64, 128 threads, 2 stages, 2 CTAs/SM.
//   Grid: bm = blockIdx.x*64 (M fastest -> B-tile L2 reuse), bn = blockIdx.y*128.
// ---------------------------------------------------------------------------
#define GEMM_SMEM (2*40960 + 1024)

template<int ACT, bool OUTH>
__global__ void __launch_bounds__(128) mma_gemm(
    const __half* __restrict__ A,
    const __half* __restrict__ Bh, const __half* __restrict__ Bl,
    const float* __restrict__ bias, const float* __restrict__ resid,
    float* __restrict__ Cf, __half* __restrict__ Ch,
    int Nn, int Kk)
{
    constexpr uint32_t ABYTES = 8192;      // 64 rows x 128B
    constexpr uint32_t STAGE  = ABYTES + 32768;

    extern __shared__ char ds[];
    const uint32_t sb = (smem_u32(ds) + 1023) & ~1023u;

    const int tid = threadIdx.x, lane = tid & 31, wid = tid >> 5;
    const int bm = blockIdx.x * 64, bn = blockIdx.y * 128;
    const int NT = Kk >> 6;

    auto cp_stage = [&](int t){
        const uint32_t base = sb + (uint32_t)(t & 1) * STAGE;
        const int k0 = t << 6;
        #pragma unroll
        for (int i = 0; i < 4; i++){
            int idx = tid + i*128;
            int r = idx >> 3, c = idx & 7;
            uint32_t off = SWZ((uint32_t)(r*128 + c*16));
            cpa16(base + off, A + (size_t)(bm + r) * Kk + k0 + c*8);
        }
        #pragma unroll
        for (int i = 0; i < 8; i++){
            int idx = tid + i*128;
            int r = idx >> 3, c = idx & 7;
            uint32_t off = SWZ((uint32_t)(r*128 + c*16));
            int gn = bn + r;
            size_t kb = (size_t)gn * Kk + k0 + c*8;
            int ssz = (gn < Nn) ? 16 : 0;
            cpa16z(base + ABYTES + off,         Bh + kb, ssz);
            cpa16z(base + ABYTES + 16384 + off, Bl + kb, ssz);
        }
        asm volatile("cp.async.commit_group;":::"memory");
    };

    float acc[2][8][4];
    #pragma unroll
    for (int a=0;a<2;a++) for (int b=0;b<8;b++) for (int c=0;c<4;c++) acc[a][b][c]=0.f;

    const int m0 = (wid >> 1) * 32, n0 = (wid & 1) * 64;
    const uint32_t arow = (uint32_t)(m0 + (lane & 15));
    const uint32_t acol = (uint32_t)((lane >> 4) * 16);
    const uint32_t brow = (uint32_t)(n0 + (lane & 7) + ((lane >> 4) & 1) * 8);
    const uint32_t bcol = (uint32_t)(((lane >> 3) & 1) * 16);

    auto compute = [&](int t){
        const uint32_t base = sb + (uint32_t)(t & 1) * STAGE;
        #pragma unroll
        for (int ks = 0; ks < 4; ks++){
            const uint32_t kb2 = (uint32_t)(ks * 32);
            uint32_t ah[2][4];
            #pragma unroll
            for (int mt = 0; mt < 2; mt++){
                uint32_t off = SWZ((arow + mt*16)*128 + kb2 + acol);
                ldsm4(ah[mt], base + off);
            }
            #pragma unroll
            for (int g = 0; g < 4; g++){
                uint32_t off = SWZ((brow + g*16)*128 + kb2 + bcol);
                uint32_t bh[4], bl[4];
                ldsm4(bh, base + ABYTES + off);
                ldsm4(bl, base + ABYTES + 16384 + off);
                #pragma unroll
                for (int mt = 0; mt < 2; mt++){
                    #pragma unroll
                    for (int sub = 0; sub < 2; sub++){
                        float* d = acc[mt][g*2 + sub];
                        mma16h(d, ah[mt], bh[sub*2], bh[sub*2+1]);
                        mma16h(d, ah[mt], bl[sub*2], bl[sub*2+1]);
                    }
                }
            }
        }
    };

    cp_stage(0);
    if (NT > 1) cp_stage(1);
    for (int t = 0; t < NT; t++){
        if (t + 1 < NT) asm volatile("cp.async.wait_group 1;":::"memory");
        else            asm volatile("cp.async.wait_group 0;":::"memory");
        __syncthreads();
        compute(t);
        __syncthreads();
        if (t + 2 < NT) cp_stage(t + 2);
    }

    #pragma unroll
    for (int mt = 0; mt < 2; mt++){
        #pragma unroll
        for (int h2 = 0; h2 < 2; h2++){
            int row = bm + m0 + mt*16 + (lane>>2) + h2*8;
            float* crow = OUTH ? nullptr : (Cf + (size_t)row * Nn);
            const float* rrow = resid ? resid + (size_t)row * Nn : nullptr;
            #pragma unroll
            for (int nt = 0; nt < 8; nt++){
                int col = bn + n0 + nt*8 + (lane&3)*2;
                if (col >= Nn) continue;
                float v0 = acc[mt][nt][h2*2+0];
                float v1 = acc[mt][nt][h2*2+1];
                bool has1 = (col + 1 < Nn);
                if (bias){ v0 += bias[col]; if (has1) v1 += bias[col+1]; }
                if (ACT == 1){ v0 = gelu_f(v0); v1 = gelu_f(v1); }
                if (rrow){ v0 += rrow[col]; if (has1) v1 += rrow[col+1]; }
                if (OUTH){
                    // OUTH targets have even Nn, col even -> 4B-aligned packed store
                    *reinterpret_cast<uint32_t*>(Ch + (size_t)row * Nn + col) = packh2(v0, v1);
                } else if (((Nn & 1) == 0) && has1){
                    float2 st; st.x = v0; st.y = v1;
                    *reinterpret_cast<float2*>(crow + col) = st;
                } else {
                    crow[col] = v0;
                    if (has1) crow[col + 1] = v1;
                }
            }
        }
    }
}

// ---------------------------------------------------------------------------
// FlashAttention, plain fp16: one block = 128 q-rows x one (b,h).
// smem: Q 16K | K 2st 32K | V 2st 32K = 80K -> 2 CTAs/SM.
// ---------------------------------------------------------------------------
#define FLASH_SMEM (81920 + 1024)

__global__ void __launch_bounds__(256) flash_kernel(
    const __half* __restrict__ qkv,
    const float* __restrict__ bias2,
    __half* __restrict__ y)
{
    extern __shared__ char ds[];
    const uint32_t sb = (smem_u32(ds) + 1023) & ~1023u;
    const uint32_t sQ = sb;

    const int tid = threadIdx.x, lane = tid & 31, w = tid >> 5;
    const int bh = blockIdx.y, b = bh / H_, h = bh % H_;
    const int i0 = (int)(gridDim.x - 1 - blockIdx.x) * 128;
    const int nj = (i0 >> 7) + 1;

    const __half* qp = qkv + (size_t)b * T_ * 3 * C_ + h * D_;
    const __half* kp = qp + C_;
    const __half* vp = qp + 2*C_;

    auto cp_q = [&](){
        #pragma unroll
        for (int i = 0; i < 4; i++){
            int idx = tid + i*256;
            int r = idx >> 3, c = idx & 7;
            uint32_t off = SWZ((uint32_t)(r*128 + c*16));
            cpa16(sQ + off, qp + (size_t)(i0 + r) * 3 * C_ + c*8);
        }
    };
    auto cp_kv = [&](int jt){
        int st = jt & 1, j0 = jt << 7;
        uint32_t kb = sb + 16384 + (uint32_t)st * 16384;
        uint32_t vb = sb + 49152 + (uint32_t)st * 16384;
        #pragma unroll
        for (int i = 0; i < 4; i++){
            int idx = tid + i*256;
            int r = idx >> 3, c = idx & 7;
            uint32_t off = SWZ((uint32_t)(r*128 + c*16));
            size_t g = (size_t)(j0 + r) * 3 * C_ + c*8;
            cpa16(kb + off, kp + g);
            cpa16(vb + off, vp + g);
        }
        asm volatile("cp.async.commit_group;":::"memory");
    };

    cp_q(); cp_kv(0);
    if (nj > 1) cp_kv(1);
    if (nj > 1) asm volatile("cp.async.wait_group 1;":::"memory");
    else        asm volatile("cp.async.wait_group 0;":::"memory");
    __syncthreads();

    // cache Q fragments
    uint32_t qf[4][4];
    {
        uint32_t arow = (uint32_t)(w*16 + (lane & 15));
        uint32_t acol = (uint32_t)((lane >> 4) * 16);
        #pragma unroll
        for (int kt = 0; kt < 4; kt++){
            uint32_t off = SWZ(arow*128 + (uint32_t)kt*32 + acol);
            ldsm4(qf[kt], sQ + off);
        }
    }

    float O[8][4];
    #pragma unroll
    for (int i=0;i<8;i++) for (int j=0;j<4;j++) O[i][j]=0.f;
    float mr0 = -INFINITY, mr1 = -INFINITY, l0 = 0.f, l1 = 0.f;

    const float SC = 0.125f * 1.4426950408889634f;
    const uint32_t brow = (uint32_t)((lane & 7) + ((lane >> 4) & 1) * 8);
    const uint32_t bcol = (uint32_t)(((lane >> 3) & 1) * 16);
    const uint32_t vrow = (uint32_t)((lane & 7) + ((lane >> 3) & 1) * 8);
    const uint32_t vcol = (uint32_t)((lane >> 4) * 16);

    for (int jt = 0; jt < nj; jt++){
        const int st = jt & 1, j0 = jt << 7;
        const uint32_t kb = sb + 16384 + (uint32_t)st * 16384;
        const uint32_t vb = sb + 49152 + (uint32_t)st * 16384;

        // --- S = Q K^T ---
        float S[16][4];
        #pragma unroll
        for (int i=0;i<16;i++) for (int j=0;j<4;j++) S[i][j]=0.f;
        #pragma unroll
        for (int kt = 0; kt < 4; kt++){
            const uint32_t kb2 = (uint32_t)kt * 32;
            #pragma unroll
            for (int g = 0; g < 8; g++){
                uint32_t off = SWZ((brow + g*16)*128 + kb2 + bcol);
                uint32_t kf[4];
                ldsm4(kf, kb + off);
                mma16h(S[g*2    ], qf[kt], kf[0], kf[1]);
                mma16h(S[g*2 + 1], qf[kt], kf[2], kf[3]);
            }
        }

        // --- scale + bias (log2 domain; bias2 includes -1e30 mask) ---
        {
            int gi = i0 + w*16 + (lane >> 2);
            int gjb = j0 + (lane & 3) * 2;
            const float* b0 = bias2 + (size_t)gi * T_ + gjb;
            const float* b1 = bias2 + (size_t)(gi + 8) * T_ + gjb;
            #pragma unroll
            for (int nt = 0; nt < 16; nt++){
                float2 ba = *reinterpret_cast<const float2*>(b0 + nt*8);
                float2 bb = *reinterpret_cast<const float2*>(b1 + nt*8);
                S[nt][0] = S[nt][0]*SC + ba.x;
                S[nt][1] = S[nt][1]*SC + ba.y;
                S[nt][2] = S[nt][2]*SC + bb.x;
                S[nt][3] = S[nt][3]*SC + bb.y;
            }
        }

        // --- online softmax ---
        float mn0 = mr0, mn1 = mr1;
        #pragma unroll
        for (int nt = 0; nt < 16; nt++){
            mn0 = fmaxf(mn0, fmaxf(S[nt][0], S[nt][1]));
            mn1 = fmaxf(mn1, fmaxf(S[nt][2], S[nt][3]));
        }
        mn0 = fmaxf(mn0, __shfl_xor_sync(0xffffffffu, mn0, 1));
        mn0 = fmaxf(mn0, __shfl_xor_sync(0xffffffffu, mn0, 2));
        mn1 = fmaxf(mn1, __shfl_xor_sync(0xffffffffu, mn1, 1));
        mn1 = fmaxf(mn1, __shfl_xor_sync(0xffffffffu, mn1, 2));
        float sc0 = exp2a(mr0 - mn0), sc1 = exp2a(mr1 - mn1);
        mr0 = mn0; mr1 = mn1;
        float rs0 = 0.f, rs1 = 0.f;
        #pragma unroll
        for (int nt = 0; nt < 16; nt++){
            S[nt][0] = exp2a(S[nt][0] - mn0);
            S[nt][1] = exp2a(S[nt][1] - mn0);
            S[nt][2] = exp2a(S[nt][2] - mn1);
            S[nt][3] = exp2a(S[nt][3] - mn1);
            rs0 += S[nt][0] + S[nt][1];
            rs1 += S[nt][2] + S[nt][3];
        }
        rs0 += __shfl_xor_sync(0xffffffffu, rs0, 1);
        rs0 += __shfl_xor_sync(0xffffffffu, rs0, 2);
        rs1 += __shfl_xor_sync(0xffffffffu, rs1, 1);
        rs1 += __shfl_xor_sync(0xffffffffu, rs1, 2);
        l0 = l0 * sc0 + rs0;
        l1 = l1 * sc1 + rs1;
        #pragma unroll
        for (int nt = 0; nt < 8; nt++){
            O[nt][0] *= sc0; O[nt][1] *= sc0;
            O[nt][2] *= sc1; O[nt][3] *= sc1;
        }

        // --- O += P V ---
        #pragma unroll
        for (int g = 0; g < 8; g++){
            uint32_t pa[4];
            pa[0] = packh2(S[2*g  ][0], S[2*g  ][1]);
            pa[1] = packh2(S[2*g  ][2], S[2*g  ][3]);
            pa[2] = packh2(S[2*g+1][0], S[2*g+1][1]);
            pa[3] = packh2(S[2*g+1][2], S[2*g+1][3]);
            #pragma unroll
            for (int dv = 0; dv < 4; dv++){
                uint32_t off = SWZ((vrow + g*16)*128 + (uint32_t)dv*32 + vcol);
                uint32_t vf[4];
                ldsm4t(vf, vb + off);
                mma16h(O[dv*2    ], pa, vf[0], vf[1]);
                mma16h(O[dv*2 + 1], pa, vf[2], vf[3]);
            }
        }

        __syncthreads();
        if (jt + 2 < nj) cp_kv(jt + 2);
        if (jt + 1 < nj){
            if (jt + 2 < nj) asm volatile("cp.async.wait_group 1;":::"memory");
            else             asm volatile("cp.async.wait_group 0;":::"memory");
            __syncthreads();
        }
    }

    // --- epilogue: normalize, write y fp16 ---
    float li0 = 1.f / l0, li1 = 1.f / l1;
    int r0 = i0 + w*16 + (lane >> 2);
    size_t base0 = (size_t)b * T_ * C_ + (size_t)r0 * C_ + h * D_;
    size_t base1 = base0 + (size_t)8 * C_;
    #pragma unroll
    for (int nt = 0; nt < 8; nt++){
        int col = nt*8 + (lane & 3)*2;
        *reinterpret_cast<uint32_t*>(y + base0 + col) = packh2(O[nt][0]*li0, O[nt][1]*li0);
        *reinterpret_cast<uint32_t*>(y + base1 + col) = packh2(O[nt][2]*li1, O[nt][3]*li1);
    }
}

// ---------------------------------------------------------------------------
// Weight prep: transpose [K,N]->[N,K] + fp16 hi/lo split
// ---------------------------------------------------------------------------
__global__ void wsplit16_t_kernel(const float* __restrict__ in,
                                  __half* __restrict__ ohi, __half* __restrict__ olo,
                                  int K, int N){
    __shared__ float t[32][33];
    size_t lb = (size_t)blockIdx.z * K * N;
    const float* inp = in + lb;
    int kb = blockIdx.y*32, nb = blockIdx.x*32;
    int tx = threadIdx.x, ty = threadIdx.y;
    #pragma unroll
    for (int j = 0; j < 4; j++)
        t[ty + 8*j][tx] = inp[(size_t)(kb + ty + 8*j) * N + nb + tx];
    __syncthreads();
    #pragma unroll
    for (int j = 0; j < 4; j++){
        int n = nb + ty + 8*j, k = kb + tx;
        float v = t[tx][ty + 8*j];
        __half hh = __float2half_rn(v);
        size_t o = lb + (size_t)n * K + k;
        ohi[o] = hh;
        olo[o] = __float2half_rn(v - __half2float(hh));
    }
}

// fp16 split for wte (already [N,K])
__global__ void split_f16_kernel(const float* __restrict__ in,
                                 __half* __restrict__ ohi, __half* __restrict__ olo, int n){
    int i = blockIdx.x * 256 + threadIdx.x;
    if (i < n){
        float v = in[i];
        __half h = __float2half_rn(v);
        ohi[i] = h;
        olo[i] = __float2half_rn(v - __half2float(h));
    }
}

// ---------------------------------------------------------------------------
// FIRE bias (pre-scaled by log2e)
// ---------------------------------------------------------------------------
__global__ void fire_bias_kernel(const float* __restrict__ log_c,
                                 const float* __restrict__ v1w, const float* __restrict__ v1b,
                                 const float* __restrict__ v2w, const float* __restrict__ v2b,
                                 const float* __restrict__ v3w, const float* __restrict__ v3b,
                                 float* __restrict__ bias) {
    __shared__ float s1w[32], s1b[32], s2w[1024], s2b[32], s3w[32];
    __shared__ float s3b, sc;
    int tid = threadIdx.x;
    if (tid < 32) { s1w[tid] = v1w[tid]; s1b[tid] = v1b[tid]; s2b[tid] = v2b[tid]; s3w[tid] = v3w[tid]; }
    for (int i = tid; i < 1024; i += blockDim.x) s2w[i] = v2w[i];
    if (tid == 0) { s3b = v3b[0]; sc = expf(log_c[0]); }
    __syncthreads();

    int idx = blockIdx.x * blockDim.x + tid;
    if (idx >= T_*T_) return;
    int i = idx / T_, j = idx % T_;
    if (j > i) { bias[idx] = -1e30f; return; }

    float c = sc;
    float fi = (float)(i + 1), fj = (float)(j + 1);
    float pv = logf(c * (fi - fj) + 1.0f) / logf(c * fi + 1.0f);

    float h1[32];
    #pragma unroll
    for (int k = 0; k < 32; k++) h1[k] = fmaxf(pv * s1w[k] + s1b[k], 0.f);
    float out = s3b;
    #pragma unroll
    for (int k2 = 0; k2 < 32; k2++) {
        float a = s2b[k2];
        #pragma unroll
        for (int k1 = 0; k1 < 32; k1++) a += h1[k1] * s2w[k1*32 + k2];
        out += fmaxf(a, 0.f) * s3w[k2];
    }
    bias[idx] = out * 1.4426950408889634f;
}

// ---------------------------------------------------------------------------
// Embedding gather
// ---------------------------------------------------------------------------
__global__ void embed_kernel(const int* __restrict__ idx, const float* __restrict__ wte,
                             float* __restrict__ x) {
    int row = blockIdx.x;
    const float* src = wte + (size_t)idx[row] * C_;
    float* dst = x + (size_t)row * C_;
    for (int c = threadIdx.x; c < C_; c += blockDim.x) dst[c] = src[c];
}

// ---------------------------------------------------------------------------
// LayerNorm: warp-per-row -> fp16 plane
// ---------------------------------------------------------------------------
__global__ void __launch_bounds__(256) ln_kernel(
    const float* __restrict__ x, const float* __restrict__ g,
    const float* __restrict__ b, __half* __restrict__ oh) {
    const int wid = threadIdx.x >> 5, lane = threadIdx.x & 31;
    const int row = blockIdx.x * 8 + wid;
    const float4* xr = reinterpret_cast<const float4*>(x + (size_t)row * C_);
    const float4* g4 = reinterpret_cast<const float4*>(g);
    const float4* b4 = reinterpret_cast<const float4*>(b);

    float4 v[6];
    float s = 0.f;
    #pragma unroll
    for (int c = 0; c < 6; c++){
        v[c] = xr[lane + c*32];
        s += v[c].x + v[c].y + v[c].z + v[c].w;
    }
    #pragma unroll
    for (int o = 16; o > 0; o >>= 1) s += __shfl_xor_sync(0xffffffffu, s, o);
    const float mean = s * (1.0f / C_);

    float q = 0.f;
    #pragma unroll
    for (int c = 0; c < 6; c++){
        v[c].x -= mean; v[c].y -= mean; v[c].z -= mean; v[c].w -= mean;
        q += v[c].x*v[c].x + v[c].y*v[c].y + v[c].z*v[c].z + v[c].w*v[c].w;
    }
    #pragma unroll
    for (int o = 16; o > 0; o >>= 1) q += __shfl_xor_sync(0xffffffffu, q, o);
    const float rs = rsqrtf(q * (1.0f / C_) + 1e-5f);

    const size_t base = (size_t)row * C_;
    #pragma unroll
    for (int c = 0; c < 6; c++){
        int c4 = lane + c*32;
        float4 gg = g4[c4], bb = b4[c4];
        uint2 hh;
        hh.x = packh2(v[c].x*rs*gg.x + bb.x, v[c].y*rs*gg.y + bb.y);
        hh.y = packh2(v[c].z*rs*gg.z + bb.z, v[c].w*rs*gg.w + bb.w);
        *reinterpret_cast<uint2*>(oh + base + c4*4) = hh;
    }
}

// ---------------------------------------------------------------------------
// Launch
// ---------------------------------------------------------------------------
extern "C" void kernel_launch(void* const* d_in, const int* in_sizes, int n_in,
                              void* d_out, int out_size) {
    int o = (n_in >= 2 && in_sizes[1] == 1) ? 1 : 0;

    const int*   idx   = (const int*)  d_in[0];
    const float* wte   = (const float*)d_in[1 + o];
    const float* log_c = (const float*)d_in[2 + o];
    const float* v1w   = (const float*)d_in[3 + o];
    const float* v1b   = (const float*)d_in[4 + o];
    const float* v2w   = (const float*)d_in[5 + o];
    const float* v2b   = (const float*)d_in[6 + o];
    const float* v3w   = (const float*)d_in[7 + o];
    const float* v3b   = (const float*)d_in[8 + o];
    const float* ln1g  = (const float*)d_in[9 + o];
    const float* ln1b  = (const float*)d_in[10 + o];
    const float* attnw = (const float*)d_in[11 + o];
    const float* attnb = (const float*)d_in[12 + o];
    const float* projw = (const float*)d_in[13 + o];
    const float* projb = (const float*)d_in[14 + o];
    const float* ln2g  = (const float*)d_in[15 + o];
    const float* ln2b  = (const float*)d_in[16 + o];
    const float* fcw   = (const float*)d_in[17 + o];
    const float* fcb   = (const float*)d_in[18 + o];
    const float* fc2w  = (const float*)d_in[19 + o];
    const float* fc2b  = (const float*)d_in[20 + o];
    const float* lnfg  = (const float*)d_in[21 + o];
    const float* lnfb  = (const float*)d_in[22 + o];

    float *bias, *x;
    __half *h16, *qkv16, *y16, *mlp16;
    __half *wa_h, *wa_l, *wp_h, *wp_l, *wf_h, *wf_l, *wf2_h, *wf2_l, *wteh, *wtel;
    cudaGetSymbolAddress((void**)&bias,  g_bias);
    cudaGetSymbolAddress((void**)&x,     g_x);
    cudaGetSymbolAddress((void**)&h16,   g_h16);
    cudaGetSymbolAddress((void**)&qkv16, g_qkv16);
    cudaGetSymbolAddress((void**)&y16,   g_y16);
    cudaGetSymbolAddress((void**)&mlp16, g_mlp16);
    cudaGetSymbolAddress((void**)&wa_h,  g_wa_h);  cudaGetSymbolAddress((void**)&wa_l,  g_wa_l);
    cudaGetSymbolAddress((void**)&wp_h,  g_wp_h);  cudaGetSymbolAddress((void**)&wp_l,  g_wp_l);
    cudaGetSymbolAddress((void**)&wf_h,  g_wf_h);  cudaGetSymbolAddress((void**)&wf_l,  g_wf_l);
    cudaGetSymbolAddress((void**)&wf2_h, g_wf2_h); cudaGetSymbolAddress((void**)&wf2_l, g_wf2_l);
    cudaGetSymbolAddress((void**)&wteh,  g_wteh);  cudaGetSymbolAddress((void**)&wtel,  g_wtel);

    cudaFuncSetAttribute(mma_gemm<0,true >, cudaFuncAttributeMaxDynamicSharedMemorySize, GEMM_SMEM);
    cudaFuncSetAttribute(mma_gemm<1,true >, cudaFuncAttributeMaxDynamicSharedMemorySize, GEMM_SMEM);
    cudaFuncSetAttribute(mma_gemm<0,false>, cudaFuncAttributeMaxDynamicSharedMemorySize, GEMM_SMEM);
    cudaFuncSetAttribute(flash_kernel,      cudaFuncAttributeMaxDynamicSharedMemorySize, FLASH_SMEM);

    // 1. FIRE bias + embedding + weight prep
    fire_bias_kernel<<<(T_*T_ + 255) / 256, 256>>>(log_c, v1w, v1b, v2w, v2b, v3w, v3b, bias);
    embed_kernel<<<M_, 256>>>(idx, wte, x);
    {
        dim3 tb(32, 8);
        wsplit16_t_kernel<<<dim3(3*C_/32,  C_/32,  L_), tb>>>(attnw, wa_h,  wa_l,  C_,   3*C_);
        wsplit16_t_kernel<<<dim3(C_/32,    C_/32,  L_), tb>>>(projw, wp_h,  wp_l,  C_,   C_);
        wsplit16_t_kernel<<<dim3(4*C_/32,  C_/32,  L_), tb>>>(fcw,   wf_h,  wf_l,  C_,   4*C_);
        wsplit16_t_kernel<<<dim3(C_/32,  4*C_/32,  L_), tb>>>(fc2w,  wf2_h, wf2_l, 4*C_, C_);
        split_f16_kernel<<<(V_*C_ + 255)/256, 256>>>(wte, wteh, wtel, V_*C_);
    }

    // 2. Transformer layers
    const dim3 g_qkvd(M_/64, 3*C_/128);
    const dim3 g_cc  (M_/64, C_/128);
    const dim3 g_fc  (M_/64, 4*C_/128);
    const dim3 g_fl  (T_/128, B_*H_);

    for (int l = 0; l < L_; l++) {
        size_t wa = (size_t)l*3*C_*C_, wp = (size_t)l*C_*C_, wf = (size_t)l*4*C_*C_;
        ln_kernel<<<M_/8, 256>>>(x, ln1g + (size_t)l*C_, ln1b + (size_t)l*C_, h16);
        mma_gemm<0,true><<<g_qkvd, 128, GEMM_SMEM>>>(h16, wa_h + wa, wa_l + wa,
                                                     attnb + (size_t)l*3*C_, nullptr,
                                                     nullptr, qkv16, 3*C_, C_);
        flash_kernel<<<g_fl, 256, FLASH_SMEM>>>(qkv16, bias, y16);
        mma_gemm<0,false><<<g_cc, 128, GEMM_SMEM>>>(y16, wp_h + wp, wp_l + wp,
                                                    projb + (size_t)l*C_, x,
                                                    x, nullptr, C_, C_);
        ln_kernel<<<M_/8, 256>>>(x, ln2g + (size_t)l*C_, ln2b + (size_t)l*C_, h16);
        mma_gemm<1,true><<<g_fc, 128, GEMM_SMEM>>>(h16, wf_h + wf, wf_l + wf,
                                                   fcb + (size_t)l*4*C_, nullptr,
                                                   nullptr, mlp16, 4*C_, C_);
        mma_gemm<0,false><<<g_cc, 128, GEMM_SMEM>>>(mlp16, wf2_h + wf, wf2_l + wf,
                                                    fc2b + (size_t)l*C_, x,
                                                    x, nullptr, C_, 4*C_);
    }

    // 3. Final LN + tied LM head
    ln_kernel<<<M_/8, 256>>>(x, lnfg, lnfb, h16);
    const dim3 g_lm(M_/64, (V_ + 127)/128);
    mma_gemm<0,false><<<g_lm, 128, GEMM_SMEM>>>(h16, wteh, wtel,
                                                nullptr, nullptr,
                                                (float*)d_out, nullptr, V_, C_);
}

// round 12
// speedup vs baseline: 11.1015x; 1.3096x over previous
#include <cuda_runtime.h>
#include <cuda_bf16.h>
#include <cuda_fp16.h>
#include <math.h>
#include <stdint.h>

// Problem constants
#define L_ 12
#define H_ 12
#define C_ 768
#define V_ 50257
#define B_ 2
#define T_ 1024
#define D_ 64
#define M_ (B_*T_)   // 2048 rows

// ---------------------------------------------------------------------------
// Scratch (static device globals) — all-fp16 pipeline
// ---------------------------------------------------------------------------
__device__ float g_bias[T_*T_];
__device__ float g_x   [M_*C_];

__device__ __half g_h16 [M_*C_];
__device__ __half g_qkv16[M_*3*C_];
__device__ __half g_y16 [M_*C_];
__device__ __half g_mlp16[M_*4*C_];

// Layer weights: single fp16 plane (1-product; branch attenuation absorbs error)
__device__ __half g_wa  [L_*3*C_*C_];
__device__ __half g_wp  [L_*C_*C_];
__device__ __half g_wf  [L_*4*C_*C_];
__device__ __half g_wf2 [L_*C_*4*C_];
// LM head: fp16 hi/lo (2-product; unattenuated)
__device__ __half g_wteh[(size_t)V_*C_], g_wtel[(size_t)V_*C_];

// ---------------------------------------------------------------------------
// Helpers
// ---------------------------------------------------------------------------
__device__ __forceinline__ uint32_t smem_u32(const void* p){
    uint32_t a;
    asm("{ .reg .u64 t; cvta.to.shared.u64 t, %1; cvt.u32.u64 %0, t; }":"=r"(a):"l"(p));
    return a;
}
__device__ __forceinline__ void cpa16(uint32_t saddr, const void* gptr){
    asm volatile("cp.async.cg.shared.global [%0], [%1], 16;"::"r"(saddr),"l"(gptr));
}
__device__ __forceinline__ void cpa16z(uint32_t saddr, const void* gptr, int ssz){
    asm volatile("cp.async.cg.shared.global [%0], [%1], 16, %2;"::"r"(saddr),"l"(gptr),"r"(ssz));
}
__device__ __forceinline__ void ldsm4(uint32_t* r, uint32_t addr){
    asm volatile("ldmatrix.sync.aligned.m8n8.x4.shared.b16 {%0,%1,%2,%3}, [%4];"
      : "=r"(r[0]),"=r"(r[1]),"=r"(r[2]),"=r"(r[3]) : "r"(addr));
}
__device__ __forceinline__ void ldsm4t(uint32_t* r, uint32_t addr){
    asm volatile("ldmatrix.sync.aligned.m8n8.x4.trans.shared.b16 {%0,%1,%2,%3}, [%4];"
      : "=r"(r[0]),"=r"(r[1]),"=r"(r[2]),"=r"(r[3]) : "r"(addr));
}
__device__ __forceinline__ void mma16h(float* d, const uint32_t* a, uint32_t b0, uint32_t b1){
    asm volatile("mma.sync.aligned.m16n8k16.row.col.f32.f16.f16.f32 "
      "{%0,%1,%2,%3}, {%4,%5,%6,%7}, {%8,%9}, {%0,%1,%2,%3};"
      : "+f"(d[0]),"+f"(d[1]),"+f"(d[2]),"+f"(d[3])
      : "r"(a[0]),"r"(a[1]),"r"(a[2]),"r"(a[3]),"r"(b0),"r"(b1));
}
__device__ __forceinline__ float exp2a(float x){
    float y; asm("ex2.approx.ftz.f32 %0, %1;":"=f"(y):"f"(x)); return y;
}
__device__ __forceinline__ float rcpa(float x){
    float y; asm("rcp.approx.ftz.f32 %0, %1;":"=f"(y):"f"(x)); return y;
}
// fast exact-ish tanh-GELU: 0.5x(1+tanh(u)) = x - x/(e^{2u}+1)
__device__ __forceinline__ float gelu_f(float v){
    float u = 0.7978845608028654f*(v + 0.044715f*v*v*v);
    float t = exp2a(u * 2.8853900817779268f);     // e^{2u}
    return v - v * rcpa(t + 1.0f);
}
// pack two f32 -> f16x2 (lower = c0)
__device__ __forceinline__ uint32_t packh2(float c0, float c1){
    uint32_t r; asm("cvt.rn.f16x2.f32 %0, %1, %2;" : "=r"(r) : "f"(c1), "f"(c0));
    return r;
}
#define SWZ(o) ((o) ^ (((o)>>3)&0x70))

// ---------------------------------------------------------------------------
// FP16 GEMM: C = act(A @ B^T + bias) (+resid)
//   A: [M,K] fp16 single plane. B: [N,K] fp16; WPROD=2 adds a lo plane.
//   BM=64, 128 threads. WPROD=1: 3-stage, 1 sync/tile. WPROD=2: 2-stage.
//   2 CTAs/SM in both configs.
//   Grid: bm = blockIdx.x*64 (M fastest -> B-tile L2 reuse), bn = blockIdx.y*128.
// ---------------------------------------------------------------------------
template<int ACT, bool OUTH, int WPROD, int NSTAGE>
__global__ void __launch_bounds__(128) mma_gemm(
    const __half* __restrict__ A,
    const __half* __restrict__ Bh, const __half* __restrict__ Bl,
    const float* __restrict__ bias, const float* __restrict__ resid,
    float* __restrict__ Cf, __half* __restrict__ Ch,
    int Nn, int Kk)
{
    constexpr uint32_t ABYTES = 8192;                        // 64 rows x 128B
    constexpr uint32_t BBYTES = (WPROD==2) ? 32768u : 16384u;
    constexpr uint32_t STAGE  = ABYTES + BBYTES;

    extern __shared__ char ds[];
    const uint32_t sb = (smem_u32(ds) + 1023) & ~1023u;

    const int tid = threadIdx.x, lane = tid & 31, wid = tid >> 5;
    const int bm = blockIdx.x * 64, bn = blockIdx.y * 128;
    const int NT = Kk >> 6;

    auto cp_stage = [&](int t){
        const uint32_t base = sb + (uint32_t)(t % NSTAGE) * STAGE;
        const int k0 = t << 6;
        #pragma unroll
        for (int i = 0; i < 4; i++){
            int idx = tid + i*128;
            int r = idx >> 3, c = idx & 7;
            uint32_t off = SWZ((uint32_t)(r*128 + c*16));
            cpa16(base + off, A + (size_t)(bm + r) * Kk + k0 + c*8);
        }
        #pragma unroll
        for (int i = 0; i < 8; i++){
            int idx = tid + i*128;
            int r = idx >> 3, c = idx & 7;
            uint32_t off = SWZ((uint32_t)(r*128 + c*16));
            int gn = bn + r;
            size_t kb = (size_t)gn * Kk + k0 + c*8;
            int ssz = (gn < Nn) ? 16 : 0;
            cpa16z(base + ABYTES + off, Bh + kb, ssz);
            if (WPROD == 2) cpa16z(base + ABYTES + 16384 + off, Bl + kb, ssz);
        }
        asm volatile("cp.async.commit_group;":::"memory");
    };

    float acc[2][8][4];
    #pragma unroll
    for (int a=0;a<2;a++) for (int b=0;b<8;b++) for (int c=0;c<4;c++) acc[a][b][c]=0.f;

    const int m0 = (wid >> 1) * 32, n0 = (wid & 1) * 64;
    const uint32_t arow = (uint32_t)(m0 + (lane & 15));
    const uint32_t acol = (uint32_t)((lane >> 4) * 16);
    const uint32_t brow = (uint32_t)(n0 + (lane & 7) + ((lane >> 4) & 1) * 8);
    const uint32_t bcol = (uint32_t)(((lane >> 3) & 1) * 16);

    auto compute = [&](int t){
        const uint32_t base = sb + (uint32_t)(t % NSTAGE) * STAGE;
        #pragma unroll
        for (int ks = 0; ks < 4; ks++){
            const uint32_t kb2 = (uint32_t)(ks * 32);
            uint32_t ah[2][4];
            #pragma unroll
            for (int mt = 0; mt < 2; mt++){
                uint32_t off = SWZ((arow + mt*16)*128 + kb2 + acol);
                ldsm4(ah[mt], base + off);
            }
            #pragma unroll
            for (int g = 0; g < 4; g++){
                uint32_t off = SWZ((brow + g*16)*128 + kb2 + bcol);
                uint32_t bh[4], bl[4];
                ldsm4(bh, base + ABYTES + off);
                if (WPROD == 2) ldsm4(bl, base + ABYTES + 16384 + off);
                #pragma unroll
                for (int mt = 0; mt < 2; mt++){
                    #pragma unroll
                    for (int sub = 0; sub < 2; sub++){
                        float* d = acc[mt][g*2 + sub];
                        mma16h(d, ah[mt], bh[sub*2], bh[sub*2+1]);
                        if (WPROD == 2) mma16h(d, ah[mt], bl[sub*2], bl[sub*2+1]);
                    }
                }
            }
        }
    };

    cp_stage(0);
    if (NT > 1) cp_stage(1);
    for (int t = 0; t < NT; t++){
        if (t + 1 < NT) asm volatile("cp.async.wait_group 1;":::"memory");
        else            asm volatile("cp.async.wait_group 0;":::"memory");
        __syncthreads();
        compute(t);
        if (NSTAGE == 2) __syncthreads();
        if (t + 2 < NT) cp_stage(t + 2);
    }

    #pragma unroll
    for (int mt = 0; mt < 2; mt++){
        #pragma unroll
        for (int h2 = 0; h2 < 2; h2++){
            int row = bm + m0 + mt*16 + (lane>>2) + h2*8;
            float* crow = OUTH ? nullptr : (Cf + (size_t)row * Nn);
            const float* rrow = resid ? resid + (size_t)row * Nn : nullptr;
            #pragma unroll
            for (int nt = 0; nt < 8; nt++){
                int col = bn + n0 + nt*8 + (lane&3)*2;
                if (col >= Nn) continue;
                float v0 = acc[mt][nt][h2*2+0];
                float v1 = acc[mt][nt][h2*2+1];
                bool has1 = (col + 1 < Nn);
                if (bias){ v0 += bias[col]; if (has1) v1 += bias[col+1]; }
                if (ACT == 1){ v0 = gelu_f(v0); v1 = gelu_f(v1); }
                if (rrow){ v0 += rrow[col]; if (has1) v1 += rrow[col+1]; }
                if (OUTH){
                    *reinterpret_cast<uint32_t*>(Ch + (size_t)row * Nn + col) = packh2(v0, v1);
                } else if (((Nn & 1) == 0) && has1){
                    float2 st; st.x = v0; st.y = v1;
                    *reinterpret_cast<float2*>(crow + col) = st;
                } else {
                    crow[col] = v0;
                    if (has1) crow[col + 1] = v1;
                }
            }
        }
    }
}

// ---------------------------------------------------------------------------
// FlashAttention, plain fp16: one block = 128 q-rows x one (b,h).
// smem: Q 16K | K 2st 32K | V 2st 32K = 80K -> 2 CTAs/SM.
// ---------------------------------------------------------------------------
#define FLASH_SMEM (81920 + 1024)

__global__ void __launch_bounds__(256) flash_kernel(
    const __half* __restrict__ qkv,
    const float* __restrict__ bias2,
    __half* __restrict__ y)
{
    extern __shared__ char ds[];
    const uint32_t sb = (smem_u32(ds) + 1023) & ~1023u;
    const uint32_t sQ = sb;

    const int tid = threadIdx.x, lane = tid & 31, w = tid >> 5;
    const int bh = blockIdx.y, b = bh / H_, h = bh % H_;
    const int i0 = (int)(gridDim.x - 1 - blockIdx.x) * 128;
    const int nj = (i0 >> 7) + 1;

    const __half* qp = qkv + (size_t)b * T_ * 3 * C_ + h * D_;
    const __half* kp = qp + C_;
    const __half* vp = qp + 2*C_;

    auto cp_q = [&](){
        #pragma unroll
        for (int i = 0; i < 4; i++){
            int idx = tid + i*256;
            int r = idx >> 3, c = idx & 7;
            uint32_t off = SWZ((uint32_t)(r*128 + c*16));
            cpa16(sQ + off, qp + (size_t)(i0 + r) * 3 * C_ + c*8);
        }
    };
    auto cp_kv = [&](int jt){
        int st = jt & 1, j0 = jt << 7;
        uint32_t kb = sb + 16384 + (uint32_t)st * 16384;
        uint32_t vb = sb + 49152 + (uint32_t)st * 16384;
        #pragma unroll
        for (int i = 0; i < 4; i++){
            int idx = tid + i*256;
            int r = idx >> 3, c = idx & 7;
            uint32_t off = SWZ((uint32_t)(r*128 + c*16));
            size_t g = (size_t)(j0 + r) * 3 * C_ + c*8;
            cpa16(kb + off, kp + g);
            cpa16(vb + off, vp + g);
        }
        asm volatile("cp.async.commit_group;":::"memory");
    };

    cp_q(); cp_kv(0);
    if (nj > 1) cp_kv(1);
    if (nj > 1) asm volatile("cp.async.wait_group 1;":::"memory");
    else        asm volatile("cp.async.wait_group 0;":::"memory");
    __syncthreads();

    uint32_t qf[4][4];
    {
        uint32_t arow = (uint32_t)(w*16 + (lane & 15));
        uint32_t acol = (uint32_t)((lane >> 4) * 16);
        #pragma unroll
        for (int kt = 0; kt < 4; kt++){
            uint32_t off = SWZ(arow*128 + (uint32_t)kt*32 + acol);
            ldsm4(qf[kt], sQ + off);
        }
    }

    float O[8][4];
    #pragma unroll
    for (int i=0;i<8;i++) for (int j=0;j<4;j++) O[i][j]=0.f;
    float mr0 = -INFINITY, mr1 = -INFINITY, l0 = 0.f, l1 = 0.f;

    const float SC = 0.125f * 1.4426950408889634f;
    const uint32_t brow = (uint32_t)((lane & 7) + ((lane >> 4) & 1) * 8);
    const uint32_t bcol = (uint32_t)(((lane >> 3) & 1) * 16);
    const uint32_t vrow = (uint32_t)((lane & 7) + ((lane >> 3) & 1) * 8);
    const uint32_t vcol = (uint32_t)((lane >> 4) * 16);

    for (int jt = 0; jt < nj; jt++){
        const int st = jt & 1, j0 = jt << 7;
        const uint32_t kb = sb + 16384 + (uint32_t)st * 16384;
        const uint32_t vb = sb + 49152 + (uint32_t)st * 16384;

        float S[16][4];
        #pragma unroll
        for (int i=0;i<16;i++) for (int j=0;j<4;j++) S[i][j]=0.f;
        #pragma unroll
        for (int kt = 0; kt < 4; kt++){
            const uint32_t kb2 = (uint32_t)kt * 32;
            #pragma unroll
            for (int g = 0; g < 8; g++){
                uint32_t off = SWZ((brow + g*16)*128 + kb2 + bcol);
                uint32_t kf[4];
                ldsm4(kf, kb + off);
                mma16h(S[g*2    ], qf[kt], kf[0], kf[1]);
                mma16h(S[g*2 + 1], qf[kt], kf[2], kf[3]);
            }
        }

        {
            int gi = i0 + w*16 + (lane >> 2);
            int gjb = j0 + (lane & 3) * 2;
            const float* b0 = bias2 + (size_t)gi * T_ + gjb;
            const float* b1 = bias2 + (size_t)(gi + 8) * T_ + gjb;
            #pragma unroll
            for (int nt = 0; nt < 16; nt++){
                float2 ba = *reinterpret_cast<const float2*>(b0 + nt*8);
                float2 bb = *reinterpret_cast<const float2*>(b1 + nt*8);
                S[nt][0] = S[nt][0]*SC + ba.x;
                S[nt][1] = S[nt][1]*SC + ba.y;
                S[nt][2] = S[nt][2]*SC + bb.x;
                S[nt][3] = S[nt][3]*SC + bb.y;
            }
        }

        float mn0 = mr0, mn1 = mr1;
        #pragma unroll
        for (int nt = 0; nt < 16; nt++){
            mn0 = fmaxf(mn0, fmaxf(S[nt][0], S[nt][1]));
            mn1 = fmaxf(mn1, fmaxf(S[nt][2], S[nt][3]));
        }
        mn0 = fmaxf(mn0, __shfl_xor_sync(0xffffffffu, mn0, 1));
        mn0 = fmaxf(mn0, __shfl_xor_sync(0xffffffffu, mn0, 2));
        mn1 = fmaxf(mn1, __shfl_xor_sync(0xffffffffu, mn1, 1));
        mn1 = fmaxf(mn1, __shfl_xor_sync(0xffffffffu, mn1, 2));
        float sc0 = exp2a(mr0 - mn0), sc1 = exp2a(mr1 - mn1);
        mr0 = mn0; mr1 = mn1;
        float rs0 = 0.f, rs1 = 0.f;
        #pragma unroll
        for (int nt = 0; nt < 16; nt++){
            S[nt][0] = exp2a(S[nt][0] - mn0);
            S[nt][1] = exp2a(S[nt][1] - mn0);
            S[nt][2] = exp2a(S[nt][2] - mn1);
            S[nt][3] = exp2a(S[nt][3] - mn1);
            rs0 += S[nt][0] + S[nt][1];
            rs1 += S[nt][2] + S[nt][3];
        }
        rs0 += __shfl_xor_sync(0xffffffffu, rs0, 1);
        rs0 += __shfl_xor_sync(0xffffffffu, rs0, 2);
        rs1 += __shfl_xor_sync(0xffffffffu, rs1, 1);
        rs1 += __shfl_xor_sync(0xffffffffu, rs1, 2);
        l0 = l0 * sc0 + rs0;
        l1 = l1 * sc1 + rs1;
        #pragma unroll
        for (int nt = 0; nt < 8; nt++){
            O[nt][0] *= sc0; O[nt][1] *= sc0;
            O[nt][2] *= sc1; O[nt][3] *= sc1;
        }

        #pragma unroll
        for (int g = 0; g < 8; g++){
            uint32_t pa[4];
            pa[0] = packh2(S[2*g  ][0], S[2*g  ][1]);
            pa[1] = packh2(S[2*g  ][2], S[2*g  ][3]);
            pa[2] = packh2(S[2*g+1][0], S[2*g+1][1]);
            pa[3] = packh2(S[2*g+1][2], S[2*g+1][3]);
            #pragma unroll
            for (int dv = 0; dv < 4; dv++){
                uint32_t off = SWZ((vrow + g*16)*128 + (uint32_t)dv*32 + vcol);
                uint32_t vf[4];
                ldsm4t(vf, vb + off);
                mma16h(O[dv*2    ], pa, vf[0], vf[1]);
                mma16h(O[dv*2 + 1], pa, vf[2], vf[3]);
            }
        }

        __syncthreads();
        if (jt + 2 < nj) cp_kv(jt + 2);
        if (jt + 1 < nj){
            if (jt + 2 < nj) asm volatile("cp.async.wait_group 1;":::"memory");
            else             asm volatile("cp.async.wait_group 0;":::"memory");
            __syncthreads();
        }
    }

    float li0 = 1.f / l0, li1 = 1.f / l1;
    int r0 = i0 + w*16 + (lane >> 2);
    size_t base0 = (size_t)b * T_ * C_ + (size_t)r0 * C_ + h * D_;
    size_t base1 = base0 + (size_t)8 * C_;
    #pragma unroll
    for (int nt = 0; nt < 8; nt++){
        int col = nt*8 + (lane & 3)*2;
        *reinterpret_cast<uint32_t*>(y + base0 + col) = packh2(O[nt][0]*li0, O[nt][1]*li0);
        *reinterpret_cast<uint32_t*>(y + base1 + col) = packh2(O[nt][2]*li1, O[nt][3]*li1);
    }
}

// ---------------------------------------------------------------------------
// Weight prep: transpose [K,N]->[N,K], single fp16 plane (layer weights)
// ---------------------------------------------------------------------------
__global__ void wtrans16_kernel(const float* __restrict__ in,
                                __half* __restrict__ oh, int K, int N){
    __shared__ float t[32][33];
    size_t lb = (size_t)blockIdx.z * K * N;
    const float* inp = in + lb;
    int kb = blockIdx.y*32, nb = blockIdx.x*32;
    int tx = threadIdx.x, ty = threadIdx.y;
    #pragma unroll
    for (int j = 0; j < 4; j++)
        t[ty + 8*j][tx] = inp[(size_t)(kb + ty + 8*j) * N + nb + tx];
    __syncthreads();
    #pragma unroll
    for (int j = 0; j < 4; j++){
        int n = nb + ty + 8*j, k = kb + tx;
        oh[lb + (size_t)n * K + k] = __float2half_rn(t[tx][ty + 8*j]);
    }
}

// fp16 hi/lo split for wte (already [N,K])
__global__ void split_f16_kernel(const float* __restrict__ in,
                                 __half* __restrict__ ohi, __half* __restrict__ olo, int n){
    int i = blockIdx.x * 256 + threadIdx.x;
    if (i < n){
        float v = in[i];
        __half h = __float2half_rn(v);
        ohi[i] = h;
        olo[i] = __float2half_rn(v - __half2float(h));
    }
}

// ---------------------------------------------------------------------------
// FIRE bias (pre-scaled by log2e)
// ---------------------------------------------------------------------------
__global__ void fire_bias_kernel(const float* __restrict__ log_c,
                                 const float* __restrict__ v1w, const float* __restrict__ v1b,
                                 const float* __restrict__ v2w, const float* __restrict__ v2b,
                                 const float* __restrict__ v3w, const float* __restrict__ v3b,
                                 float* __restrict__ bias) {
    __shared__ float s1w[32], s1b[32], s2w[1024], s2b[32], s3w[32];
    __shared__ float s3b, sc;
    int tid = threadIdx.x;
    if (tid < 32) { s1w[tid] = v1w[tid]; s1b[tid] = v1b[tid]; s2b[tid] = v2b[tid]; s3w[tid] = v3w[tid]; }
    for (int i = tid; i < 1024; i += blockDim.x) s2w[i] = v2w[i];
    if (tid == 0) { s3b = v3b[0]; sc = expf(log_c[0]); }
    __syncthreads();

    int idx = blockIdx.x * blockDim.x + tid;
    if (idx >= T_*T_) return;
    int i = idx / T_, j = idx % T_;
    if (j > i) { bias[idx] = -1e30f; return; }

    float c = sc;
    float fi = (float)(i + 1), fj = (float)(j + 1);
    float pv = logf(c * (fi - fj) + 1.0f) / logf(c * fi + 1.0f);

    float h1[32];
    #pragma unroll
    for (int k = 0; k < 32; k++) h1[k] = fmaxf(pv * s1w[k] + s1b[k], 0.f);
    float out = s3b;
    #pragma unroll
    for (int k2 = 0; k2 < 32; k2++) {
        float a = s2b[k2];
        #pragma unroll
        for (int k1 = 0; k1 < 32; k1++) a += h1[k1] * s2w[k1*32 + k2];
        out += fmaxf(a, 0.f) * s3w[k2];
    }
    bias[idx] = out * 1.4426950408889634f;
}

// ---------------------------------------------------------------------------
// Embedding gather
// ---------------------------------------------------------------------------
__global__ void embed_kernel(const int* __restrict__ idx, const float* __restrict__ wte,
                             float* __restrict__ x) {
    int row = blockIdx.x;
    const float* src = wte + (size_t)idx[row] * C_;
    float* dst = x + (size_t)row * C_;
    for (int c = threadIdx.x; c < C_; c += blockDim.x) dst[c] = src[c];
}

// ---------------------------------------------------------------------------
// LayerNorm: warp-per-row -> fp16 plane
// ---------------------------------------------------------------------------
__global__ void __launch_bounds__(256) ln_kernel(
    const float* __restrict__ x, const float* __restrict__ g,
    const float* __restrict__ b, __half* __restrict__ oh) {
    const int wid = threadIdx.x >> 5, lane = threadIdx.x & 31;
    const int row = blockIdx.x * 8 + wid;
    const float4* xr = reinterpret_cast<const float4*>(x + (size_t)row * C_);
    const float4* g4 = reinterpret_cast<const float4*>(g);
    const float4* b4 = reinterpret_cast<const float4*>(b);

    float4 v[6];
    float s = 0.f;
    #pragma unroll
    for (int c = 0; c < 6; c++){
        v[c] = xr[lane + c*32];
        s += v[c].x + v[c].y + v[c].z + v[c].w;
    }
    #pragma unroll
    for (int o = 16; o > 0; o >>= 1) s += __shfl_xor_sync(0xffffffffu, s, o);
    const float mean = s * (1.0f / C_);

    float q = 0.f;
    #pragma unroll
    for (int c = 0; c < 6; c++){
        v[c].x -= mean; v[c].y -= mean; v[c].z -= mean; v[c].w -= mean;
        q += v[c].x*v[c].x + v[c].y*v[c].y + v[c].z*v[c].z + v[c].w*v[c].w;
    }
    #pragma unroll
    for (int o = 16; o > 0; o >>= 1) q += __shfl_xor_sync(0xffffffffu, q, o);
    const float rs = rsqrtf(q * (1.0f / C_) + 1e-5f);

    const size_t base = (size_t)row * C_;
    #pragma unroll
    for (int c = 0; c < 6; c++){
        int c4 = lane + c*32;
        float4 gg = g4[c4], bb = b4[c4];
        uint2 hh;
        hh.x = packh2(v[c].x*rs*gg.x + bb.x, v[c].y*rs*gg.y + bb.y);
        hh.y = packh2(v[c].z*rs*gg.z + bb.z, v[c].w*rs*gg.w + bb.w);
        *reinterpret_cast<uint2*>(oh + base + c4*4) = hh;
    }
}

// ---------------------------------------------------------------------------
// Launch
// ---------------------------------------------------------------------------
extern "C" void kernel_launch(void* const* d_in, const int* in_sizes, int n_in,
                              void* d_out, int out_size) {
    int o = (n_in >= 2 && in_sizes[1] == 1) ? 1 : 0;

    const int*   idx   = (const int*)  d_in[0];
    const float* wte   = (const float*)d_in[1 + o];
    const float* log_c = (const float*)d_in[2 + o];
    const float* v1w   = (const float*)d_in[3 + o];
    const float* v1b   = (const float*)d_in[4 + o];
    const float* v2w   = (const float*)d_in[5 + o];
    const float* v2b   = (const float*)d_in[6 + o];
    const float* v3w   = (const float*)d_in[7 + o];
    const float* v3b   = (const float*)d_in[8 + o];
    const float* ln1g  = (const float*)d_in[9 + o];
    const float* ln1b  = (const float*)d_in[10 + o];
    const float* attnw = (const float*)d_in[11 + o];
    const float* attnb = (const float*)d_in[12 + o];
    const float* projw = (const float*)d_in[13 + o];
    const float* projb = (const float*)d_in[14 + o];
    const float* ln2g  = (const float*)d_in[15 + o];
    const float* ln2b  = (const float*)d_in[16 + o];
    const float* fcw   = (const float*)d_in[17 + o];
    const float* fcb   = (const float*)d_in[18 + o];
    const float* fc2w  = (const float*)d_in[19 + o];
    const float* fc2b  = (const float*)d_in[20 + o];
    const float* lnfg  = (const float*)d_in[21 + o];
    const float* lnfb  = (const float*)d_in[22 + o];

    float *bias, *x;
    __half *h16, *qkv16, *y16, *mlp16;
    __half *wa, *wp, *wf, *wf2, *wteh, *wtel;
    cudaGetSymbolAddress((void**)&bias,  g_bias);
    cudaGetSymbolAddress((void**)&x,     g_x);
    cudaGetSymbolAddress((void**)&h16,   g_h16);
    cudaGetSymbolAddress((void**)&qkv16, g_qkv16);
    cudaGetSymbolAddress((void**)&y16,   g_y16);
    cudaGetSymbolAddress((void**)&mlp16, g_mlp16);
    cudaGetSymbolAddress((void**)&wa,    g_wa);
    cudaGetSymbolAddress((void**)&wp,    g_wp);
    cudaGetSymbolAddress((void**)&wf,    g_wf);
    cudaGetSymbolAddress((void**)&wf2,   g_wf2);
    cudaGetSymbolAddress((void**)&wteh,  g_wteh);
    cudaGetSymbolAddress((void**)&wtel,  g_wtel);

    // smem sizes
    const int SM1 = 3*24576 + 1024;   // WPROD=1, 3 stages (73.7KB -> 2 CTAs/SM)
    const int SM2 = 2*40960 + 1024;   // WPROD=2, 2 stages (82.9KB -> 2 CTAs/SM)

    cudaFuncSetAttribute(mma_gemm<0,true ,1,3>, cudaFuncAttributeMaxDynamicSharedMemorySize, SM1);
    cudaFuncSetAttribute(mma_gemm<1,true ,1,3>, cudaFuncAttributeMaxDynamicSharedMemorySize, SM1);
    cudaFuncSetAttribute(mma_gemm<0,false,1,3>, cudaFuncAttributeMaxDynamicSharedMemorySize, SM1);
    cudaFuncSetAttribute(mma_gemm<0,false,2,2>, cudaFuncAttributeMaxDynamicSharedMemorySize, SM2);
    cudaFuncSetAttribute(flash_kernel,          cudaFuncAttributeMaxDynamicSharedMemorySize, FLASH_SMEM);

    // 1. FIRE bias + embedding + weight prep
    fire_bias_kernel<<<(T_*T_ + 255) / 256, 256>>>(log_c, v1w, v1b, v2w, v2b, v3w, v3b, bias);
    embed_kernel<<<M_, 256>>>(idx, wte, x);
    {
        dim3 tb(32, 8);
        wtrans16_kernel<<<dim3(3*C_/32,  C_/32,  L_), tb>>>(attnw, wa,  C_,   3*C_);
        wtrans16_kernel<<<dim3(C_/32,    C_/32,  L_), tb>>>(projw, wp,  C_,   C_);
        wtrans16_kernel<<<dim3(4*C_/32,  C_/32,  L_), tb>>>(fcw,   wf,  C_,   4*C_);
        wtrans16_kernel<<<dim3(C_/32,  4*C_/32,  L_), tb>>>(fc2w,  wf2, 4*C_, C_);
        split_f16_kernel<<<(V_*C_ + 255)/256, 256>>>(wte, wteh, wtel, V_*C_);
    }

    // 2. Transformer layers
    const dim3 g_qkvd(M_/64, 3*C_/128);
    const dim3 g_cc  (M_/64, C_/128);
    const dim3 g_fc  (M_/64, 4*C_/128);
    const dim3 g_fl  (T_/128, B_*H_);

    for (int l = 0; l < L_; l++) {
        size_t wao = (size_t)l*3*C_*C_, wpo = (size_t)l*C_*C_, wfo = (size_t)l*4*C_*C_;
        ln_kernel<<<M_/8, 256>>>(x, ln1g + (size_t)l*C_, ln1b + (size_t)l*C_, h16);
        mma_gemm<0,true,1,3><<<g_qkvd, 128, SM1>>>(h16, wa + wao, nullptr,
                                                   attnb + (size_t)l*3*C_, nullptr,
                                                   nullptr, qkv16, 3*C_, C_);
        flash_kernel<<<g_fl, 256, FLASH_SMEM>>>(qkv16, bias, y16);
        mma_gemm<0,false,1,3><<<g_cc, 128, SM1>>>(y16, wp + wpo, nullptr,
                                                  projb + (size_t)l*C_, x,
                                                  x, nullptr, C_, C_);
        ln_kernel<<<M_/8, 256>>>(x, ln2g + (size_t)l*C_, ln2b + (size_t)l*C_, h16);
        mma_gemm<1,true,1,3><<<g_fc, 128, SM1>>>(h16, wf + wfo, nullptr,
                                                 fcb + (size_t)l*4*C_, nullptr,
                                                 nullptr, mlp16, 4*C_, C_);
        mma_gemm<0,false,1,3><<<g_cc, 128, SM1>>>(mlp16, wf2 + wfo, nullptr,
                                                  fc2b + (size_t)l*C_, x,
                                                  x, nullptr, C_, 4*C_);
    }

    // 3. Final LN + tied LM head (fp16 2-product)
    ln_kernel<<<M_/8, 256>>>(x, lnfg, lnfb, h16);
    const dim3 g_lm(M_/64, (V_ + 127)/128);
    mma_gemm<0,false,2,2><<<g_lm, 128, SM2>>>(h16, wteh, wtel,
                                              nullptr, nullptr,
                                              (float*)d_out, nullptr, V_, C_);
}

// round 13
// speedup vs baseline: 11.5843x; 1.0435x over previous
#include <cuda_runtime.h>
#include <cuda_bf16.h>
#include <cuda_fp16.h>
#include <math.h>
#include <stdint.h>

// Problem constants
#define L_ 12
#define H_ 12
#define C_ 768
#define V_ 50257
#define B_ 2
#define T_ 1024
#define D_ 64
#define M_ (B_*T_)   // 2048 rows

// ---------------------------------------------------------------------------
// Scratch (static device globals) — all-fp16 pipeline
// ---------------------------------------------------------------------------
__device__ float g_bias[T_*T_];
__device__ float g_x   [M_*C_];

__device__ __half g_h16 [M_*C_];
__device__ __half g_qkv16[M_*3*C_];
__device__ __half g_y16 [M_*C_];
__device__ __half g_mlp16[M_*4*C_];

// Layer weights: single fp16 plane (1-product)
__device__ __half g_wa  [L_*3*C_*C_];
__device__ __half g_wp  [L_*C_*C_];
__device__ __half g_wf  [L_*4*C_*C_];
__device__ __half g_wf2 [L_*C_*4*C_];
// LM head: fp16 hi/lo (2-product)
__device__ __half g_wteh[(size_t)V_*C_], g_wtel[(size_t)V_*C_];

// ---------------------------------------------------------------------------
// Helpers
// ---------------------------------------------------------------------------
__device__ __forceinline__ uint32_t smem_u32(const void* p){
    uint32_t a;
    asm("{ .reg .u64 t; cvta.to.shared.u64 t, %1; cvt.u32.u64 %0, t; }":"=r"(a):"l"(p));
    return a;
}
__device__ __forceinline__ void cpa16(uint32_t saddr, const void* gptr){
    asm volatile("cp.async.cg.shared.global [%0], [%1], 16;"::"r"(saddr),"l"(gptr));
}
__device__ __forceinline__ void cpa16z(uint32_t saddr, const void* gptr, int ssz){
    asm volatile("cp.async.cg.shared.global [%0], [%1], 16, %2;"::"r"(saddr),"l"(gptr),"r"(ssz));
}
__device__ __forceinline__ void ldsm4(uint32_t* r, uint32_t addr){
    asm volatile("ldmatrix.sync.aligned.m8n8.x4.shared.b16 {%0,%1,%2,%3}, [%4];"
      : "=r"(r[0]),"=r"(r[1]),"=r"(r[2]),"=r"(r[3]) : "r"(addr));
}
__device__ __forceinline__ void ldsm4t(uint32_t* r, uint32_t addr){
    asm volatile("ldmatrix.sync.aligned.m8n8.x4.trans.shared.b16 {%0,%1,%2,%3}, [%4];"
      : "=r"(r[0]),"=r"(r[1]),"=r"(r[2]),"=r"(r[3]) : "r"(addr));
}
__device__ __forceinline__ void mma16h(float* d, const uint32_t* a, uint32_t b0, uint32_t b1){
    asm volatile("mma.sync.aligned.m16n8k16.row.col.f32.f16.f16.f32 "
      "{%0,%1,%2,%3}, {%4,%5,%6,%7}, {%8,%9}, {%0,%1,%2,%3};"
      : "+f"(d[0]),"+f"(d[1]),"+f"(d[2]),"+f"(d[3])
      : "r"(a[0]),"r"(a[1]),"r"(a[2]),"r"(a[3]),"r"(b0),"r"(b1));
}
__device__ __forceinline__ float exp2a(float x){
    float y; asm("ex2.approx.ftz.f32 %0, %1;":"=f"(y):"f"(x)); return y;
}
__device__ __forceinline__ float rcpa(float x){
    float y; asm("rcp.approx.ftz.f32 %0, %1;":"=f"(y):"f"(x)); return y;
}
__device__ __forceinline__ float gelu_f(float v){
    float u = 0.7978845608028654f*(v + 0.044715f*v*v*v);
    float t = exp2a(u * 2.8853900817779268f);
    return v - v * rcpa(t + 1.0f);
}
__device__ __forceinline__ uint32_t packh2(float c0, float c1){
    uint32_t r; asm("cvt.rn.f16x2.f32 %0, %1, %2;" : "=r"(r) : "f"(c1), "f"(c0));
    return r;
}
#define SWZ(o) ((o) ^ (((o)>>3)&0x70))

// ---------------------------------------------------------------------------
// FP16 GEMM: C = act(A @ B^T + bias) (+resid)
//   A: [M,K] fp16. B: [N,K] fp16 (WPROD=2 adds lo plane).
//   BM=64, 128 threads. BN_ in {128, 64}.
//   Occupancy: WPROD2 -> 2 CTAs/SM; BN128 WPROD1 -> 3; BN64 WPROD1 -> 4.
//   Grid: bm = blockIdx.x*64 (M fastest), bn = blockIdx.y*BN_.
// ---------------------------------------------------------------------------
template<int ACT, bool OUTH, int WPROD, int NSTAGE, int BN_>
__global__ void __launch_bounds__(128, (WPROD==2) ? 2 : ((BN_==64) ? 4 : 3))
mma_gemm(
    const __half* __restrict__ A,
    const __half* __restrict__ Bh, const __half* __restrict__ Bl,
    const float* __restrict__ bias, const float* __restrict__ resid,
    float* __restrict__ Cf, __half* __restrict__ Ch,
    int Nn, int Kk)
{
    constexpr uint32_t ABYTES = 8192;                 // 64 rows x 128B
    constexpr uint32_t BPLANE = (uint32_t)BN_ * 128;  // per B plane
    constexpr uint32_t BBYTES = (WPROD==2) ? 2*BPLANE : BPLANE;
    constexpr uint32_t STAGE  = ABYTES + BBYTES;
    constexpr int NBIT  = (BN_*8)/128;                // B cp iterations
    constexpr int NHALF = BN_/2;                      // cols per warp
    constexpr int NGRP  = NHALF/16;                   // 16-col ldsm groups/warp

    extern __shared__ char ds[];
    const uint32_t sb = (smem_u32(ds) + 1023) & ~1023u;

    const int tid = threadIdx.x, lane = tid & 31, wid = tid >> 5;
    const int bm = blockIdx.x * 64, bn = blockIdx.y * BN_;
    const int NT = Kk >> 6;

    auto cp_stage = [&](int t){
        const uint32_t base = sb + (uint32_t)(t % NSTAGE) * STAGE;
        const int k0 = t << 6;
        #pragma unroll
        for (int i = 0; i < 4; i++){
            int idx = tid + i*128;
            int r = idx >> 3, c = idx & 7;
            uint32_t off = SWZ((uint32_t)(r*128 + c*16));
            cpa16(base + off, A + (size_t)(bm + r) * Kk + k0 + c*8);
        }
        #pragma unroll
        for (int i = 0; i < NBIT; i++){
            int idx = tid + i*128;
            int r = idx >> 3, c = idx & 7;
            uint32_t off = SWZ((uint32_t)(r*128 + c*16));
            int gn = bn + r;
            size_t kb = (size_t)gn * Kk + k0 + c*8;
            int ssz = (gn < Nn) ? 16 : 0;
            cpa16z(base + ABYTES + off, Bh + kb, ssz);
            if (WPROD == 2) cpa16z(base + ABYTES + BPLANE + off, Bl + kb, ssz);
        }
        asm volatile("cp.async.commit_group;":::"memory");
    };

    float acc[2][NGRP*2][4];
    #pragma unroll
    for (int a=0;a<2;a++) for (int b=0;b<NGRP*2;b++) for (int c=0;c<4;c++) acc[a][b][c]=0.f;

    const int m0 = (wid >> 1) * 32, n0 = (wid & 1) * NHALF;
    const uint32_t arow = (uint32_t)(m0 + (lane & 15));
    const uint32_t acol = (uint32_t)((lane >> 4) * 16);
    const uint32_t brow = (uint32_t)(n0 + (lane & 7) + ((lane >> 4) & 1) * 8);
    const uint32_t bcol = (uint32_t)(((lane >> 3) & 1) * 16);

    auto compute = [&](int t){
        const uint32_t base = sb + (uint32_t)(t % NSTAGE) * STAGE;
        #pragma unroll
        for (int ks = 0; ks < 4; ks++){
            const uint32_t kb2 = (uint32_t)(ks * 32);
            uint32_t ah[2][4];
            #pragma unroll
            for (int mt = 0; mt < 2; mt++){
                uint32_t off = SWZ((arow + mt*16)*128 + kb2 + acol);
                ldsm4(ah[mt], base + off);
            }
            #pragma unroll
            for (int g = 0; g < NGRP; g++){
                uint32_t off = SWZ((brow + g*16)*128 + kb2 + bcol);
                uint32_t bh[4], bl[4];
                ldsm4(bh, base + ABYTES + off);
                if (WPROD == 2) ldsm4(bl, base + ABYTES + BPLANE + off);
                #pragma unroll
                for (int mt = 0; mt < 2; mt++){
                    #pragma unroll
                    for (int sub = 0; sub < 2; sub++){
                        float* d = acc[mt][g*2 + sub];
                        mma16h(d, ah[mt], bh[sub*2], bh[sub*2+1]);
                        if (WPROD == 2) mma16h(d, ah[mt], bl[sub*2], bl[sub*2+1]);
                    }
                }
            }
        }
    };

    cp_stage(0);
    if (NT > 1) cp_stage(1);
    for (int t = 0; t < NT; t++){
        if (t + 1 < NT) asm volatile("cp.async.wait_group 1;":::"memory");
        else            asm volatile("cp.async.wait_group 0;":::"memory");
        __syncthreads();
        compute(t);
        if (NSTAGE == 2) __syncthreads();
        if (t + 2 < NT) cp_stage(t + 2);
    }

    #pragma unroll
    for (int mt = 0; mt < 2; mt++){
        #pragma unroll
        for (int h2 = 0; h2 < 2; h2++){
            int row = bm + m0 + mt*16 + (lane>>2) + h2*8;
            float* crow = OUTH ? nullptr : (Cf + (size_t)row * Nn);
            const float* rrow = resid ? resid + (size_t)row * Nn : nullptr;
            #pragma unroll
            for (int nt = 0; nt < NGRP*2; nt++){
                int col = bn + n0 + nt*8 + (lane&3)*2;
                if (col >= Nn) continue;
                float v0 = acc[mt][nt][h2*2+0];
                float v1 = acc[mt][nt][h2*2+1];
                bool has1 = (col + 1 < Nn);
                if (bias){ v0 += bias[col]; if (has1) v1 += bias[col+1]; }
                if (ACT == 1){ v0 = gelu_f(v0); v1 = gelu_f(v1); }
                if (rrow){ v0 += rrow[col]; if (has1) v1 += rrow[col+1]; }
                if (OUTH){
                    *reinterpret_cast<uint32_t*>(Ch + (size_t)row * Nn + col) = packh2(v0, v1);
                } else if (((Nn & 1) == 0) && has1){
                    float2 st; st.x = v0; st.y = v1;
                    *reinterpret_cast<float2*>(crow + col) = st;
                } else {
                    crow[col] = v0;
                    if (has1) crow[col + 1] = v1;
                }
            }
        }
    }
}

// ---------------------------------------------------------------------------
// FlashAttention, plain fp16: one block = 128 q-rows x one (b,h).
// smem: Q 16K | K 2st 32K | V 2st 32K = 80K -> 2 CTAs/SM.
// ---------------------------------------------------------------------------
#define FLASH_SMEM (81920 + 1024)

__global__ void __launch_bounds__(256) flash_kernel(
    const __half* __restrict__ qkv,
    const float* __restrict__ bias2,
    __half* __restrict__ y)
{
    extern __shared__ char ds[];
    const uint32_t sb = (smem_u32(ds) + 1023) & ~1023u;
    const uint32_t sQ = sb;

    const int tid = threadIdx.x, lane = tid & 31, w = tid >> 5;
    const int bh = blockIdx.y, b = bh / H_, h = bh % H_;
    const int i0 = (int)(gridDim.x - 1 - blockIdx.x) * 128;
    const int nj = (i0 >> 7) + 1;

    const __half* qp = qkv + (size_t)b * T_ * 3 * C_ + h * D_;
    const __half* kp = qp + C_;
    const __half* vp = qp + 2*C_;

    auto cp_q = [&](){
        #pragma unroll
        for (int i = 0; i < 4; i++){
            int idx = tid + i*256;
            int r = idx >> 3, c = idx & 7;
            uint32_t off = SWZ((uint32_t)(r*128 + c*16));
            cpa16(sQ + off, qp + (size_t)(i0 + r) * 3 * C_ + c*8);
        }
    };
    auto cp_kv = [&](int jt){
        int st = jt & 1, j0 = jt << 7;
        uint32_t kb = sb + 16384 + (uint32_t)st * 16384;
        uint32_t vb = sb + 49152 + (uint32_t)st * 16384;
        #pragma unroll
        for (int i = 0; i < 4; i++){
            int idx = tid + i*256;
            int r = idx >> 3, c = idx & 7;
            uint32_t off = SWZ((uint32_t)(r*128 + c*16));
            size_t g = (size_t)(j0 + r) * 3 * C_ + c*8;
            cpa16(kb + off, kp + g);
            cpa16(vb + off, vp + g);
        }
        asm volatile("cp.async.commit_group;":::"memory");
    };

    cp_q(); cp_kv(0);
    if (nj > 1) cp_kv(1);
    if (nj > 1) asm volatile("cp.async.wait_group 1;":::"memory");
    else        asm volatile("cp.async.wait_group 0;":::"memory");
    __syncthreads();

    uint32_t qf[4][4];
    {
        uint32_t arow = (uint32_t)(w*16 + (lane & 15));
        uint32_t acol = (uint32_t)((lane >> 4) * 16);
        #pragma unroll
        for (int kt = 0; kt < 4; kt++){
            uint32_t off = SWZ(arow*128 + (uint32_t)kt*32 + acol);
            ldsm4(qf[kt], sQ + off);
        }
    }

    float O[8][4];
    #pragma unroll
    for (int i=0;i<8;i++) for (int j=0;j<4;j++) O[i][j]=0.f;
    float mr0 = -INFINITY, mr1 = -INFINITY, l0 = 0.f, l1 = 0.f;

    const float SC = 0.125f * 1.4426950408889634f;
    const uint32_t brow = (uint32_t)((lane & 7) + ((lane >> 4) & 1) * 8);
    const uint32_t bcol = (uint32_t)(((lane >> 3) & 1) * 16);
    const uint32_t vrow = (uint32_t)((lane & 7) + ((lane >> 3) & 1) * 8);
    const uint32_t vcol = (uint32_t)((lane >> 4) * 16);

    for (int jt = 0; jt < nj; jt++){
        const int st = jt & 1, j0 = jt << 7;
        const uint32_t kb = sb + 16384 + (uint32_t)st * 16384;
        const uint32_t vb = sb + 49152 + (uint32_t)st * 16384;

        float S[16][4];
        #pragma unroll
        for (int i=0;i<16;i++) for (int j=0;j<4;j++) S[i][j]=0.f;
        #pragma unroll
        for (int kt = 0; kt < 4; kt++){
            const uint32_t kb2 = (uint32_t)kt * 32;
            #pragma unroll
            for (int g = 0; g < 8; g++){
                uint32_t off = SWZ((brow + g*16)*128 + kb2 + bcol);
                uint32_t kf[4];
                ldsm4(kf, kb + off);
                mma16h(S[g*2    ], qf[kt], kf[0], kf[1]);
                mma16h(S[g*2 + 1], qf[kt], kf[2], kf[3]);
            }
        }

        {
            int gi = i0 + w*16 + (lane >> 2);
            int gjb = j0 + (lane & 3) * 2;
            const float* b0 = bias2 + (size_t)gi * T_ + gjb;
            const float* b1 = bias2 + (size_t)(gi + 8) * T_ + gjb;
            #pragma unroll
            for (int nt = 0; nt < 16; nt++){
                float2 ba = *reinterpret_cast<const float2*>(b0 + nt*8);
                float2 bb = *reinterpret_cast<const float2*>(b1 + nt*8);
                S[nt][0] = S[nt][0]*SC + ba.x;
                S[nt][1] = S[nt][1]*SC + ba.y;
                S[nt][2] = S[nt][2]*SC + bb.x;
                S[nt][3] = S[nt][3]*SC + bb.y;
            }
        }

        float mn0 = mr0, mn1 = mr1;
        #pragma unroll
        for (int nt = 0; nt < 16; nt++){
            mn0 = fmaxf(mn0, fmaxf(S[nt][0], S[nt][1]));
            mn1 = fmaxf(mn1, fmaxf(S[nt][2], S[nt][3]));
        }
        mn0 = fmaxf(mn0, __shfl_xor_sync(0xffffffffu, mn0, 1));
        mn0 = fmaxf(mn0, __shfl_xor_sync(0xffffffffu, mn0, 2));
        mn1 = fmaxf(mn1, __shfl_xor_sync(0xffffffffu, mn1, 1));
        mn1 = fmaxf(mn1, __shfl_xor_sync(0xffffffffu, mn1, 2));
        float sc0 = exp2a(mr0 - mn0), sc1 = exp2a(mr1 - mn1);
        mr0 = mn0; mr1 = mn1;
        float rs0 = 0.f, rs1 = 0.f;
        #pragma unroll
        for (int nt = 0; nt < 16; nt++){
            S[nt][0] = exp2a(S[nt][0] - mn0);
            S[nt][1] = exp2a(S[nt][1] - mn0);
            S[nt][2] = exp2a(S[nt][2] - mn1);
            S[nt][3] = exp2a(S[nt][3] - mn1);
            rs0 += S[nt][0] + S[nt][1];
            rs1 += S[nt][2] + S[nt][3];
        }
        rs0 += __shfl_xor_sync(0xffffffffu, rs0, 1);
        rs0 += __shfl_xor_sync(0xffffffffu, rs0, 2);
        rs1 += __shfl_xor_sync(0xffffffffu, rs1, 1);
        rs1 += __shfl_xor_sync(0xffffffffu, rs1, 2);
        l0 = l0 * sc0 + rs0;
        l1 = l1 * sc1 + rs1;
        #pragma unroll
        for (int nt = 0; nt < 8; nt++){
            O[nt][0] *= sc0; O[nt][1] *= sc0;
            O[nt][2] *= sc1; O[nt][3] *= sc1;
        }

        #pragma unroll
        for (int g = 0; g < 8; g++){
            uint32_t pa[4];
            pa[0] = packh2(S[2*g  ][0], S[2*g  ][1]);
            pa[1] = packh2(S[2*g  ][2], S[2*g  ][3]);
            pa[2] = packh2(S[2*g+1][0], S[2*g+1][1]);
            pa[3] = packh2(S[2*g+1][2], S[2*g+1][3]);
            #pragma unroll
            for (int dv = 0; dv < 4; dv++){
                uint32_t off = SWZ((vrow + g*16)*128 + (uint32_t)dv*32 + vcol);
                uint32_t vf[4];
                ldsm4t(vf, vb + off);
                mma16h(O[dv*2    ], pa, vf[0], vf[1]);
                mma16h(O[dv*2 + 1], pa, vf[2], vf[3]);
            }
        }

        __syncthreads();
        if (jt + 2 < nj) cp_kv(jt + 2);
        if (jt + 1 < nj){
            if (jt + 2 < nj) asm volatile("cp.async.wait_group 1;":::"memory");
            else             asm volatile("cp.async.wait_group 0;":::"memory");
            __syncthreads();
        }
    }

    float li0 = 1.f / l0, li1 = 1.f / l1;
    int r0 = i0 + w*16 + (lane >> 2);
    size_t base0 = (size_t)b * T_ * C_ + (size_t)r0 * C_ + h * D_;
    size_t base1 = base0 + (size_t)8 * C_;
    #pragma unroll
    for (int nt = 0; nt < 8; nt++){
        int col = nt*8 + (lane & 3)*2;
        *reinterpret_cast<uint32_t*>(y + base0 + col) = packh2(O[nt][0]*li0, O[nt][1]*li0);
        *reinterpret_cast<uint32_t*>(y + base1 + col) = packh2(O[nt][2]*li1, O[nt][3]*li1);
    }
}

// ---------------------------------------------------------------------------
// Weight prep: transpose [K,N]->[N,K], single fp16 plane
// ---------------------------------------------------------------------------
__global__ void wtrans16_kernel(const float* __restrict__ in,
                                __half* __restrict__ oh, int K, int N){
    __shared__ float t[32][33];
    size_t lb = (size_t)blockIdx.z * K * N;
    const float* inp = in + lb;
    int kb = blockIdx.y*32, nb = blockIdx.x*32;
    int tx = threadIdx.x, ty = threadIdx.y;
    #pragma unroll
    for (int j = 0; j < 4; j++)
        t[ty + 8*j][tx] = inp[(size_t)(kb + ty + 8*j) * N + nb + tx];
    __syncthreads();
    #pragma unroll
    for (int j = 0; j < 4; j++){
        int n = nb + ty + 8*j, k = kb + tx;
        oh[lb + (size_t)n * K + k] = __float2half_rn(t[tx][ty + 8*j]);
    }
}

// fp16 hi/lo split for wte (already [N,K])
__global__ void split_f16_kernel(const float* __restrict__ in,
                                 __half* __restrict__ ohi, __half* __restrict__ olo, int n){
    int i = blockIdx.x * 256 + threadIdx.x;
    if (i < n){
        float v = in[i];
        __half h = __float2half_rn(v);
        ohi[i] = h;
        olo[i] = __float2half_rn(v - __half2float(h));
    }
}

// ---------------------------------------------------------------------------
// FIRE bias (pre-scaled by log2e)
// ---------------------------------------------------------------------------
__global__ void fire_bias_kernel(const float* __restrict__ log_c,
                                 const float* __restrict__ v1w, const float* __restrict__ v1b,
                                 const float* __restrict__ v2w, const float* __restrict__ v2b,
                                 const float* __restrict__ v3w, const float* __restrict__ v3b,
                                 float* __restrict__ bias) {
    __shared__ float s1w[32], s1b[32], s2w[1024], s2b[32], s3w[32];
    __shared__ float s3b, sc;
    int tid = threadIdx.x;
    if (tid < 32) { s1w[tid] = v1w[tid]; s1b[tid] = v1b[tid]; s2b[tid] = v2b[tid]; s3w[tid] = v3w[tid]; }
    for (int i = tid; i < 1024; i += blockDim.x) s2w[i] = v2w[i];
    if (tid == 0) { s3b = v3b[0]; sc = expf(log_c[0]); }
    __syncthreads();

    int idx = blockIdx.x * blockDim.x + tid;
    if (idx >= T_*T_) return;
    int i = idx / T_, j = idx % T_;
    if (j > i) { bias[idx] = -1e30f; return; }

    float c = sc;
    float fi = (float)(i + 1), fj = (float)(j + 1);
    float pv = logf(c * (fi - fj) + 1.0f) / logf(c * fi + 1.0f);

    float h1[32];
    #pragma unroll
    for (int k = 0; k < 32; k++) h1[k] = fmaxf(pv * s1w[k] + s1b[k], 0.f);
    float out = s3b;
    #pragma unroll
    for (int k2 = 0; k2 < 32; k2++) {
        float a = s2b[k2];
        #pragma unroll
        for (int k1 = 0; k1 < 32; k1++) a += h1[k1] * s2w[k1*32 + k2];
        out += fmaxf(a, 0.f) * s3w[k2];
    }
    bias[idx] = out * 1.4426950408889634f;
}

// ---------------------------------------------------------------------------
// Embedding gather
// ---------------------------------------------------------------------------
__global__ void embed_kernel(const int* __restrict__ idx, const float* __restrict__ wte,
                             float* __restrict__ x) {
    int row = blockIdx.x;
    const float* src = wte + (size_t)idx[row] * C_;
    float* dst = x + (size_t)row * C_;
    for (int c = threadIdx.x; c < C_; c += blockDim.x) dst[c] = src[c];
}

// ---------------------------------------------------------------------------
// LayerNorm: warp-per-row -> fp16 plane
// ---------------------------------------------------------------------------
__global__ void __launch_bounds__(256) ln_kernel(
    const float* __restrict__ x, const float* __restrict__ g,
    const float* __restrict__ b, __half* __restrict__ oh) {
    const int wid = threadIdx.x >> 5, lane = threadIdx.x & 31;
    const int row = blockIdx.x * 8 + wid;
    const float4* xr = reinterpret_cast<const float4*>(x + (size_t)row * C_);
    const float4* g4 = reinterpret_cast<const float4*>(g);
    const float4* b4 = reinterpret_cast<const float4*>(b);

    float4 v[6];
    float s = 0.f;
    #pragma unroll
    for (int c = 0; c < 6; c++){
        v[c] = xr[lane + c*32];
        s += v[c].x + v[c].y + v[c].z + v[c].w;
    }
    #pragma unroll
    for (int o = 16; o > 0; o >>= 1) s += __shfl_xor_sync(0xffffffffu, s, o);
    const float mean = s * (1.0f / C_);

    float q = 0.f;
    #pragma unroll
    for (int c = 0; c < 6; c++){
        v[c].x -= mean; v[c].y -= mean; v[c].z -= mean; v[c].w -= mean;
        q += v[c].x*v[c].x + v[c].y*v[c].y + v[c].z*v[c].z + v[c].w*v[c].w;
    }
    #pragma unroll
    for (int o = 16; o > 0; o >>= 1) q += __shfl_xor_sync(0xffffffffu, q, o);
    const float rs = rsqrtf(q * (1.0f / C_) + 1e-5f);

    const size_t base = (size_t)row * C_;
    #pragma unroll
    for (int c = 0; c < 6; c++){
        int c4 = lane + c*32;
        float4 gg = g4[c4], bb = b4[c4];
        uint2 hh;
        hh.x = packh2(v[c].x*rs*gg.x + bb.x, v[c].y*rs*gg.y + bb.y);
        hh.y = packh2(v[c].z*rs*gg.z + bb.z, v[c].w*rs*gg.w + bb.w);
        *reinterpret_cast<uint2*>(oh + base + c4*4) = hh;
    }
}

// ---------------------------------------------------------------------------
// Launch
// ---------------------------------------------------------------------------
extern "C" void kernel_launch(void* const* d_in, const int* in_sizes, int n_in,
                              void* d_out, int out_size) {
    int o = (n_in >= 2 && in_sizes[1] == 1) ? 1 : 0;

    const int*   idx   = (const int*)  d_in[0];
    const float* wte   = (const float*)d_in[1 + o];
    const float* log_c = (const float*)d_in[2 + o];
    const float* v1w   = (const float*)d_in[3 + o];
    const float* v1b   = (const float*)d_in[4 + o];
    const float* v2w   = (const float*)d_in[5 + o];
    const float* v2b   = (const float*)d_in[6 + o];
    const float* v3w   = (const float*)d_in[7 + o];
    const float* v3b   = (const float*)d_in[8 + o];
    const float* ln1g  = (const float*)d_in[9 + o];
    const float* ln1b  = (const float*)d_in[10 + o];
    const float* attnw = (const float*)d_in[11 + o];
    const float* attnb = (const float*)d_in[12 + o];
    const float* projw = (const float*)d_in[13 + o];
    const float* projb = (const float*)d_in[14 + o];
    const float* ln2g  = (const float*)d_in[15 + o];
    const float* ln2b  = (const float*)d_in[16 + o];
    const float* fcw   = (const float*)d_in[17 + o];
    const float* fcb   = (const float*)d_in[18 + o];
    const float* fc2w  = (const float*)d_in[19 + o];
    const float* fc2b  = (const float*)d_in[20 + o];
    const float* lnfg  = (const float*)d_in[21 + o];
    const float* lnfb  = (const float*)d_in[22 + o];

    float *bias, *x;
    __half *h16, *qkv16, *y16, *mlp16;
    __half *wa, *wp, *wf, *wf2, *wteh, *wtel;
    cudaGetSymbolAddress((void**)&bias,  g_bias);
    cudaGetSymbolAddress((void**)&x,     g_x);
    cudaGetSymbolAddress((void**)&h16,   g_h16);
    cudaGetSymbolAddress((void**)&qkv16, g_qkv16);
    cudaGetSymbolAddress((void**)&y16,   g_y16);
    cudaGetSymbolAddress((void**)&mlp16, g_mlp16);
    cudaGetSymbolAddress((void**)&wa,    g_wa);
    cudaGetSymbolAddress((void**)&wp,    g_wp);
    cudaGetSymbolAddress((void**)&wf,    g_wf);
    cudaGetSymbolAddress((void**)&wf2,   g_wf2);
    cudaGetSymbolAddress((void**)&wteh,  g_wteh);
    cudaGetSymbolAddress((void**)&wtel,  g_wtel);

    // smem sizes
    const int SMQ = 3*24576 + 1024;   // BN128, WPROD1, 3 stages -> 3 CTAs/SM
    const int SMP = 3*16384 + 1024;   // BN64,  WPROD1, 3 stages -> 4 CTAs/SM
    const int SML = 2*40960 + 1024;   // BN128, WPROD2, 2 stages -> 2 CTAs/SM

    cudaFuncSetAttribute(mma_gemm<0,true ,1,3,128>, cudaFuncAttributeMaxDynamicSharedMemorySize, SMQ);
    cudaFuncSetAttribute(mma_gemm<1,true ,1,3,128>, cudaFuncAttributeMaxDynamicSharedMemorySize, SMQ);
    cudaFuncSetAttribute(mma_gemm<0,false,1,3, 64>, cudaFuncAttributeMaxDynamicSharedMemorySize, SMP);
    cudaFuncSetAttribute(mma_gemm<0,false,2,2,128>, cudaFuncAttributeMaxDynamicSharedMemorySize, SML);
    cudaFuncSetAttribute(flash_kernel,              cudaFuncAttributeMaxDynamicSharedMemorySize, FLASH_SMEM);

    // 1. FIRE bias + embedding + weight prep
    fire_bias_kernel<<<(T_*T_ + 255) / 256, 256>>>(log_c, v1w, v1b, v2w, v2b, v3w, v3b, bias);
    embed_kernel<<<M_, 256>>>(idx, wte, x);
    {
        dim3 tb(32, 8);
        wtrans16_kernel<<<dim3(3*C_/32,  C_/32,  L_), tb>>>(attnw, wa,  C_,   3*C_);
        wtrans16_kernel<<<dim3(C_/32,    C_/32,  L_), tb>>>(projw, wp,  C_,   C_);
        wtrans16_kernel<<<dim3(4*C_/32,  C_/32,  L_), tb>>>(fcw,   wf,  C_,   4*C_);
        wtrans16_kernel<<<dim3(C_/32,  4*C_/32,  L_), tb>>>(fc2w,  wf2, 4*C_, C_);
        split_f16_kernel<<<(V_*C_ + 255)/256, 256>>>(wte, wteh, wtel, V_*C_);
    }

    // 2. Transformer layers
    const dim3 g_qkvd(M_/64, 3*C_/128);
    const dim3 g_cc  (M_/64, C_/64);
    const dim3 g_fc  (M_/64, 4*C_/128);
    const dim3 g_fl  (T_/128, B_*H_);

    for (int l = 0; l < L_; l++) {
        size_t wao = (size_t)l*3*C_*C_, wpo = (size_t)l*C_*C_, wfo = (size_t)l*4*C_*C_;
        ln_kernel<<<M_/8, 256>>>(x, ln1g + (size_t)l*C_, ln1b + (size_t)l*C_, h16);
        mma_gemm<0,true,1,3,128><<<g_qkvd, 128, SMQ>>>(h16, wa + wao, nullptr,
                                                       attnb + (size_t)l*3*C_, nullptr,
                                                       nullptr, qkv16, 3*C_, C_);
        flash_kernel<<<g_fl, 256, FLASH_SMEM>>>(qkv16, bias, y16);
        mma_gemm<0,false,1,3,64><<<g_cc, 128, SMP>>>(y16, wp + wpo, nullptr,
                                                     projb + (size_t)l*C_, x,
                                                     x, nullptr, C_, C_);
        ln_kernel<<<M_/8, 256>>>(x, ln2g + (size_t)l*C_, ln2b + (size_t)l*C_, h16);
        mma_gemm<1,true,1,3,128><<<g_fc, 128, SMQ>>>(h16, wf + wfo, nullptr,
                                                     fcb + (size_t)l*4*C_, nullptr,
                                                     nullptr, mlp16, 4*C_, C_);
        mma_gemm<0,false,1,3,64><<<g_cc, 128, SMP>>>(mlp16, wf2 + wfo, nullptr,
                                                     fc2b + (size_t)l*C_, x,
                                                     x, nullptr, C_, 4*C_);
    }

    // 3. Final LN + tied LM head (fp16 2-product)
    ln_kernel<<<M_/8, 256>>>(x, lnfg, lnfb, h16);
    const dim3 g_lm(M_/64, (V_ + 127)/128);
    mma_gemm<0,false,2,2,128><<<g_lm, 128, SML>>>(h16, wteh, wtel,
                                                  nullptr, nullptr,
                                                  (float*)d_out, nullptr, V_, C_);
}